// round 12
// baseline (speedup 1.0000x reference)
#include <cuda_runtime.h>
#include <cuda_fp16.h>
#include <math.h>
#include <stdint.h>

#define NB      2
#define LSEQ    1024
#define DMODEL  1024
#define NHEAD   16
#define DHEAD   64
#define NLAY    6
#define VOCAB   30000
#define VPAD    30080
#define HIDB    512
#define FFDIM   4096
#define NROWS   2048   /* NB*LSEQ */

/* ---- output layout (flattened tuple, in reference return order) ---- */
static const size_t OUT_LOGITS = 0;
static const size_t OUT_X   = (size_t)NROWS * VOCAB;
static const size_t OUT_GSM = OUT_X   + (size_t)NROWS * DMODEL;
static const size_t OUT_SSM = OUT_GSM + (size_t)NROWS * 4;
static const size_t OUT_GS  = OUT_SSM + (size_t)NROWS;
static const size_t OUT_SS  = OUT_GS  + (size_t)NLAY * NROWS * 4;

/* ---- transposed fp16 weight scratch layout (elements) ---- */
#define W_QKV 0UL
#define W_OUT (W_QKV + (size_t)NLAY * DMODEL * 3 * DMODEL)
#define W_FF1 (W_OUT + (size_t)NLAY * DMODEL * DMODEL)
#define W_FF2 (W_FF1 + (size_t)NLAY * DMODEL * FFDIM)
#define W_BND (W_FF2 + (size_t)NLAY * FFDIM * DMODEL)
#define W_TOT (W_BND + (size_t)DMODEL * HIDB)

/* ---- scratch ---- */
__device__ float g_x  [NROWS * DMODEL];
__device__ float g_xm [NROWS * DMODEL];
__device__ float g_pv [NROWS * NHEAD];
__device__ float g_bndh[NROWS * HIDB];
__device__ __align__(16) __half g_ainH[NROWS * DMODEL];
__device__ __align__(16) __half g_aoH [NROWS * DMODEL];
__device__ __align__(16) __half g_ffhH[NROWS * FFDIM];
__device__ __align__(16) __half g_qkvH[NROWS * 3 * DMODEL];
__device__ __align__(16) __half g_vT  [(size_t)NB * NHEAD * DHEAD * LSEQ];
__device__ __align__(16) __half g_wh  [W_TOT];
__device__ __align__(16) __half g_embH[(size_t)VPAD * DMODEL];

/* ================= low-level helpers (compute_103-safe) ================= */
__device__ __forceinline__ uint32_t smem_u32(const void* p) {
    uint32_t a;
    asm("{ .reg .u64 t; cvta.to.shared.u64 t, %1; cvt.u32.u64 %0, t; }" : "=r"(a) : "l"(p));
    return a;
}
__device__ __forceinline__ void cp16(void* s, const void* g) {
    asm volatile("cp.async.cg.shared.global [%0], [%1], 16;"
                 :: "r"(smem_u32(s)), "l"(g) : "memory");
}
#define CP_COMMIT() asm volatile("cp.async.commit_group;" ::: "memory")
#define CP_WAIT1()  asm volatile("cp.async.wait_group 1;" ::: "memory")
#define CP_WAIT0()  asm volatile("cp.async.wait_group 0;" ::: "memory")

#define LDSM4(r0, r1, r2, r3, addr) \
    asm volatile("ldmatrix.sync.aligned.m8n8.x4.shared.b16 {%0,%1,%2,%3}, [%4];" \
                 : "=r"(r0), "=r"(r1), "=r"(r2), "=r"(r3) : "r"(addr))

__device__ __forceinline__ void mma_h(float* c, const uint32_t* a, const uint32_t* b) {
    asm volatile(
        "mma.sync.aligned.m16n8k16.row.col.f32.f16.f16.f32 "
        "{%0,%1,%2,%3}, {%4,%5,%6,%7}, {%8,%9}, {%0,%1,%2,%3};"
        : "+f"(c[0]), "+f"(c[1]), "+f"(c[2]), "+f"(c[3])
        : "r"(a[0]), "r"(a[1]), "r"(a[2]), "r"(a[3]), "r"(b[0]), "r"(b[1]));
}

/* ================= fp16 mma GEMM — 3-stage pipeline, 1 barrier/chunk ======
   C[M,N](f32) / C2[M,N](fp16) = act(A[M,K] @ Bt[N,K]^T + bias) (+resid) */
#define GEMM_SMEM (3 * 8192 * 2 * 2)   /* 3 stages x (A+B) x 16KB = 96KB */

__global__ __launch_bounds__(256, 2)
void k_hgemm(const __half* __restrict__ A, const __half* __restrict__ Bm,
             const float* __restrict__ bias, const float* __restrict__ resid,
             float* __restrict__ C, __half* __restrict__ C2,
             int M, int N, int K, int act)
{
    extern __shared__ __half hs[];
    __half* As = hs;              /* 3 stages x 8192 halves */
    __half* Bs = hs + 3 * 8192;

    const int tid  = threadIdx.x;
    const int wid  = tid >> 5;
    const int lane = tid & 31;
    const int m0 = blockIdx.y * 128;
    const int n0 = blockIdx.x * 128;
    const int wm = (wid & 1) * 64;
    const int wn = (wid >> 1) * 32;
    const int nch = K >> 6;

    const int st_row = tid >> 3;
    const uint32_t st_sw = (uint32_t)(((tid & 7) ^ (st_row & 7)) * 8);
    const __half* aglob = A + (size_t)(m0 + st_row) * K + (tid & 7) * 8;
    const __half* bglob = Bm + (size_t)(n0 + st_row) * K + (tid & 7) * 8;

#define HSTAGE(ch, s) do {                                                      \
    __half* as_ = As + (s) * 8192;                                              \
    __half* bs_ = Bs + (s) * 8192;                                              \
    const __half* ap = aglob + (ch) * 64;                                       \
    const __half* bp = bglob + (ch) * 64;                                       \
    _Pragma("unroll")                                                           \
    for (int it = 0; it < 4; it++) {                                            \
        cp16(as_ + (st_row + it * 32) * 64 + st_sw, ap + (size_t)(it * 32) * K);\
        cp16(bs_ + (st_row + it * 32) * 64 + st_sw, bp + (size_t)(it * 32) * K);\
    }                                                                           \
} while (0)

    const int lsw = lane & 7;
    const int rA  = (lane & 7) + (lane & 8);
    const int rB  = (lane & 7) + ((lane & 16) >> 1);
    const int cA  = (lane >> 4) & 1;
    const int cB  = (lane >> 3) & 1;

    float cf[4][4][4];
    #pragma unroll
    for (int i = 0; i < 4; i++)
        #pragma unroll
        for (int j = 0; j < 4; j++)
            { cf[i][j][0] = 0.f; cf[i][j][1] = 0.f; cf[i][j][2] = 0.f; cf[i][j][3] = 0.f; }

    /* prologue: stages 0 and 1 in flight */
    HSTAGE(0, 0);
    CP_COMMIT();
    if (nch > 1) { HSTAGE(1, 1); CP_COMMIT(); }

    int sb = 0;                   /* stage index of chunk c (mod 3) */
    for (int c = 0; c < nch; c++) {
        if (c + 1 < nch) CP_WAIT1(); else CP_WAIT0();
        __syncthreads();          /* chunk c data ready; all warps done with buf (c+2)%3 */
        if (c + 2 < nch) {
            int s2 = sb + 2; if (s2 >= 3) s2 -= 3;
            HSTAGE(c + 2, s2);
            CP_COMMIT();
        }

        const uint32_t ab = smem_u32(As + sb * 8192);
        const uint32_t bb = smem_u32(Bs + sb * 8192);

        #pragma unroll
        for (int kk = 0; kk < 4; kk++) {
            const uint32_t sA = (uint32_t)(((kk * 2 + cA) ^ lsw) * 16);
            const uint32_t sB = (uint32_t)(((kk * 2 + cB) ^ lsw) * 16);
            uint32_t af[4][4], bf[2][4];
            #pragma unroll
            for (int mt = 0; mt < 4; mt++)
                LDSM4(af[mt][0], af[mt][1], af[mt][2], af[mt][3],
                      ab + (uint32_t)(wm + mt * 16 + rA) * 128u + sA);
            #pragma unroll
            for (int p = 0; p < 2; p++)
                LDSM4(bf[p][0], bf[p][1], bf[p][2], bf[p][3],
                      bb + (uint32_t)(wn + p * 16 + rB) * 128u + sB);
            #pragma unroll
            for (int mt = 0; mt < 4; mt++)
                #pragma unroll
                for (int nt = 0; nt < 4; nt++)
                    mma_h(cf[mt][nt], af[mt], &bf[nt >> 1][(nt & 1) * 2]);
        }
        if (++sb == 3) sb = 0;
    }
#undef HSTAGE

    #pragma unroll
    for (int mt = 0; mt < 4; mt++) {
        int row = m0 + wm + mt * 16 + (lane >> 2);
        #pragma unroll
        for (int nt = 0; nt < 4; nt++) {
            int col = n0 + wn + nt * 8 + (lane & 3) * 2;
            if (col < N) {
                #pragma unroll
                for (int hh = 0; hh < 2; hh++) {
                    int r = row + hh * 8;
                    float v0 = cf[mt][nt][hh * 2 + 0];
                    float v1 = cf[mt][nt][hh * 2 + 1];
                    if (bias) { v0 += bias[col]; v1 += bias[col + 1]; }
                    if (act == 1) {
                        v0 = 0.5f * v0 * (1.0f + erff(v0 * 0.70710678118654752f));
                        v1 = 0.5f * v1 * (1.0f + erff(v1 * 0.70710678118654752f));
                    } else if (act == 2) {
                        v0 = tanhf(v0); v1 = tanhf(v1);
                    }
                    if (resid) {
                        v0 += resid[(size_t)r * N + col];
                        v1 += resid[(size_t)r * N + col + 1];
                    }
                    if (C)  *(float2*)(C + (size_t)r * N + col) = make_float2(v0, v1);
                    if (C2) *(__half2*)(C2 + (size_t)r * N + col) = __floats2half2_rn(v0, v1);
                }
            }
        }
    }
}

/* ================= V transpose per head: g_vT[b,h][d][l] ================= */
__global__ void k_vT()
{
    __shared__ __half t[64][72];
    int b = blockIdx.z, h = blockIdx.y, l0 = blockIdx.x * 64;
    int tid = threadIdx.x;   /* 256 */
    #pragma unroll
    for (int it = 0; it < 8; it++) {
        int idx = tid + it * 256;
        int l = idx >> 5, c2 = idx & 31;
        const __half2* src = (const __half2*)(g_qkvH + (size_t)(b * LSEQ + l0 + l) * 3 * DMODEL
                                              + 2 * DMODEL + h * DHEAD);
        *(__half2*)&t[l][c2 * 2] = src[c2];
    }
    __syncthreads();
    #pragma unroll
    for (int it = 0; it < 8; it++) {
        int idx = tid + it * 256;
        int d = idx >> 5, lc = (idx & 31) * 2;
        __half2 v; v.x = t[lc][d]; v.y = t[lc + 1][d];
        *(__half2*)(g_vT + ((size_t)(b * NHEAD + h) * DHEAD + d) * LSEQ + l0 + lc) = v;
    }
}

/* ================= tensor-core fused attention (round-8 verified) ========== */
__global__ __launch_bounds__(128)
void k_attn(const float* __restrict__ res_scale, int layer)
{
    const int b = blockIdx.z, h = blockIdx.y, q0 = blockIdx.x * 64;
    const int tid = threadIdx.x, wid = tid >> 5, lane = tid & 31;
    const float rs = res_scale[layer];

    __shared__ __half Qs[64 * 64];          /* reused as P buffer after tile 0 */
    __shared__ __half Ks[2][64 * 64];
    __shared__ __half Vs[2][64 * 64];
    __shared__ float pvs[64];

    const int srow = tid >> 3;
    const int sc   = tid & 7;
    const uint32_t sdst = (uint32_t)((sc ^ (srow & 7)) * 8);

    /* stage Q (rows q0+) and KV tile 0 (rows 0+) */
    {
        const __half* qg = g_qkvH + (size_t)(b * LSEQ + q0 + srow) * 3 * DMODEL + h * DHEAD + sc * 8;
        const __half* kg = g_qkvH + (size_t)(b * LSEQ + srow) * 3 * DMODEL + DMODEL + h * DHEAD + sc * 8;
        const __half* vg = g_vT + ((size_t)(b * NHEAD + h) * DHEAD + srow) * LSEQ + sc * 8;
        #pragma unroll
        for (int it = 0; it < 4; it++) {
            size_t off = (size_t)(it * 16) * 3 * DMODEL;
            cp16(Qs + (srow + it * 16) * 64 + sdst, qg + off);
            cp16(Ks[0] + (srow + it * 16) * 64 + sdst, kg + off);
            cp16(Vs[0] + (srow + it * 16) * 64 + sdst, vg + (size_t)(it * 16) * LSEQ);
        }
    }
    CP_COMMIT();

    const int lsw = lane & 7;
    const int rA  = (lane & 7) + (lane & 8);
    const int rB  = (lane & 7) + ((lane & 16) >> 1);
    const int cA  = (lane >> 4) & 1;
    const int cB  = (lane >> 3) & 1;
    const int wm  = wid * 16;
    const int g   = lane >> 2;
    const int tq  = lane & 3;

    const int gr1 = q0 + wm + g;
    const float pq1 = g_pv[(size_t)(b * LSEQ + gr1) * NHEAD + h];
    const float pq2 = g_pv[(size_t)(b * LSEQ + gr1 + 8) * NHEAD + h];

    float o[8][4];
    #pragma unroll
    for (int i = 0; i < 8; i++)
        { o[i][0] = 0.f; o[i][1] = 0.f; o[i][2] = 0.f; o[i][3] = 0.f; }
    float m1 = -1e30f, m2 = -1e30f, d1 = 0.f, d2 = 0.f;
    uint32_t qa[4][4];

    __half* P1 = Qs + (wm + g) * 64 + tq * 2;
    __half* P2 = P1 + 8 * 64;
    const int psw = (g & 7) * 8;

    for (int j = 0; j < LSEQ / 64; j++) {
        const int buf = j & 1;
        if (j + 1 < LSEQ / 64) {
            const int nbuf = buf ^ 1;
            const int kv1 = (j + 1) * 64;
            const __half* kg = g_qkvH + (size_t)(b * LSEQ + kv1 + srow) * 3 * DMODEL
                               + DMODEL + h * DHEAD + sc * 8;
            const __half* vg = g_vT + ((size_t)(b * NHEAD + h) * DHEAD + srow) * LSEQ + kv1 + sc * 8;
            #pragma unroll
            for (int it = 0; it < 4; it++) {
                cp16(Ks[nbuf] + (srow + it * 16) * 64 + sdst, kg + (size_t)(it * 16) * 3 * DMODEL);
                cp16(Vs[nbuf] + (srow + it * 16) * 64 + sdst, vg + (size_t)(it * 16) * LSEQ);
            }
            CP_COMMIT();
            CP_WAIT1();
        } else {
            CP_WAIT0();
        }
        if (tid < 64)
            pvs[tid] = g_pv[(size_t)(b * LSEQ + j * 64 + tid) * NHEAD + h];
        __syncthreads();

        if (j == 0) {
            const uint32_t qb = smem_u32(Qs);
            #pragma unroll
            for (int ks = 0; ks < 4; ks++)
                LDSM4(qa[ks][0], qa[ks][1], qa[ks][2], qa[ks][3],
                      qb + (uint32_t)(wm + rA) * 128u + (uint32_t)(((ks * 2 + cA) ^ lsw) * 16));
        }

        /* S = Q K^T */
        float s[8][4];
        #pragma unroll
        for (int i = 0; i < 8; i++)
            { s[i][0] = 0.f; s[i][1] = 0.f; s[i][2] = 0.f; s[i][3] = 0.f; }
        {
            const uint32_t kb = smem_u32(Ks[buf]);
            #pragma unroll
            for (int ks = 0; ks < 4; ks++) {
                const uint32_t sB = (uint32_t)(((ks * 2 + cB) ^ lsw) * 16);
                uint32_t bfm[4][4];
                #pragma unroll
                for (int nb2 = 0; nb2 < 4; nb2++)
                    LDSM4(bfm[nb2][0], bfm[nb2][1], bfm[nb2][2], bfm[nb2][3],
                          kb + (uint32_t)(nb2 * 16 + rB) * 128u + sB);
                #pragma unroll
                for (int nt = 0; nt < 8; nt++)
                    mma_h(s[nt], qa[ks], &bfm[nt >> 1][(nt & 1) * 2]);
            }
        }

        /* exact phase penalty + online softmax */
        float tmax1 = -1e30f, tmax2 = -1e30f;
        #pragma unroll
        for (int nt = 0; nt < 8; nt++) {
            float k0 = pvs[nt * 8 + tq * 2];
            float k1 = pvs[nt * 8 + tq * 2 + 1];
            float u;
            u = pq1 - k0; s[nt][0] = s[nt][0] * 0.125f - rs * u * u;
            u = pq1 - k1; s[nt][1] = s[nt][1] * 0.125f - rs * u * u;
            u = pq2 - k0; s[nt][2] = s[nt][2] * 0.125f - rs * u * u;
            u = pq2 - k1; s[nt][3] = s[nt][3] * 0.125f - rs * u * u;
            tmax1 = fmaxf(tmax1, fmaxf(s[nt][0], s[nt][1]));
            tmax2 = fmaxf(tmax2, fmaxf(s[nt][2], s[nt][3]));
        }
        tmax1 = fmaxf(tmax1, __shfl_xor_sync(0xffffffffu, tmax1, 1));
        tmax1 = fmaxf(tmax1, __shfl_xor_sync(0xffffffffu, tmax1, 2));
        tmax2 = fmaxf(tmax2, __shfl_xor_sync(0xffffffffu, tmax2, 1));
        tmax2 = fmaxf(tmax2, __shfl_xor_sync(0xffffffffu, tmax2, 2));
        float mn1 = fmaxf(m1, tmax1), mn2 = fmaxf(m2, tmax2);
        float c1 = __expf(m1 - mn1), c2 = __expf(m2 - mn2);
        m1 = mn1; m2 = mn2;
        d1 *= c1; d2 *= c2;
        #pragma unroll
        for (int nt = 0; nt < 8; nt++) {
            o[nt][0] *= c1; o[nt][1] *= c1;
            o[nt][2] *= c2; o[nt][3] *= c2;
        }
        #pragma unroll
        for (int nt = 0; nt < 8; nt++) {
            float p0 = __expf(s[nt][0] - m1), p1 = __expf(s[nt][1] - m1);
            float p2 = __expf(s[nt][2] - m2), p3 = __expf(s[nt][3] - m2);
            d1 += p0 + p1; d2 += p2 + p3;
            int chunk = (nt ^ psw / 8) * 8;
            *(__half2*)(P1 + chunk) = __floats2half2_rn(p0, p1);
            *(__half2*)(P2 + chunk) = __floats2half2_rn(p2, p3);
        }
        __syncwarp();

        /* O += P @ Vt */
        {
            const uint32_t pb = smem_u32(Qs);
            const uint32_t vb = smem_u32(Vs[buf]);
            #pragma unroll
            for (int ks = 0; ks < 4; ks++) {
                uint32_t pa[4];
                LDSM4(pa[0], pa[1], pa[2], pa[3],
                      pb + (uint32_t)(wm + rA) * 128u + (uint32_t)(((ks * 2 + cA) ^ lsw) * 16));
                const uint32_t sB = (uint32_t)(((ks * 2 + cB) ^ lsw) * 16);
                uint32_t vf[4][4];
                #pragma unroll
                for (int nb2 = 0; nb2 < 4; nb2++)
                    LDSM4(vf[nb2][0], vf[nb2][1], vf[nb2][2], vf[nb2][3],
                          vb + (uint32_t)(nb2 * 16 + rB) * 128u + sB);
                #pragma unroll
                for (int nt = 0; nt < 8; nt++)
                    mma_h(o[nt], pa, &vf[nt >> 1][(nt & 1) * 2]);
            }
        }
        __syncthreads();
    }

    d1 += __shfl_xor_sync(0xffffffffu, d1, 1);
    d1 += __shfl_xor_sync(0xffffffffu, d1, 2);
    d2 += __shfl_xor_sync(0xffffffffu, d2, 1);
    d2 += __shfl_xor_sync(0xffffffffu, d2, 2);
    float i1 = 1.0f / d1, i2 = 1.0f / d2;
    __half* o1 = g_aoH + (size_t)(b * LSEQ + gr1) * DMODEL + h * DHEAD + tq * 2;
    __half* o2 = o1 + (size_t)8 * DMODEL;
    #pragma unroll
    for (int nt = 0; nt < 8; nt++) {
        *(__half2*)(o1 + nt * 8) = __floats2half2_rn(o[nt][0] * i1, o[nt][1] * i1);
        *(__half2*)(o2 + nt * 8) = __floats2half2_rn(o[nt][2] * i2, o[nt][3] * i2);
    }
}

/* ===== weight transpose + fp16 convert, 64x64 tiles, layer-batched (z) ===== */
__global__ void k_cvtT(const float* __restrict__ src, __half* __restrict__ dst,
                       int K, int N)
{
    __shared__ float t[64][65];
    size_t seg = (size_t)blockIdx.z * K * N;
    const float* s0 = src + seg;
    __half* d0 = dst + seg;
    int n0 = blockIdx.x * 64, k0 = blockIdx.y * 64;
    int tid = threadIdx.x;               /* 256 */
    {
        int kr = tid >> 2, c4 = tid & 3;
        const float* sp = s0 + (size_t)(k0 + kr) * N + n0;
        #pragma unroll
        for (int j = 0; j < 4; j++) {
            int col = (c4 + j * 4) * 4;
            float4 v = *(const float4*)(sp + col);
            t[kr][col + 0] = v.x; t[kr][col + 1] = v.y;
            t[kr][col + 2] = v.z; t[kr][col + 3] = v.w;
        }
    }
    __syncthreads();
    {
        int n = tid >> 2, kc = (tid & 3) * 16;
        __half2 h[8];
        #pragma unroll
        for (int j = 0; j < 8; j++)
            h[j] = __floats2half2_rn(t[kc + 2 * j][n], t[kc + 2 * j + 1][n]);
        __half* dp = d0 + (size_t)(n0 + n) * K + k0 + kc;
        *(uint4*)(dp + 0) = *(uint4*)&h[0];
        *(uint4*)(dp + 8) = *(uint4*)&h[4];
    }
}

/* ================= embed -> fp16 [VPAD][D] with zero pad ================= */
__global__ void k_cvtE(const float* __restrict__ src)
{
    size_t stride = (size_t)gridDim.x * blockDim.x;
    size_t tot8 = (size_t)VPAD * DMODEL / 8;
    for (size_t i = (size_t)blockIdx.x * blockDim.x + threadIdx.x; i < tot8; i += stride) {
        size_t e = i * 8;
        size_t row = e >> 10;    /* / DMODEL */
        __half2 h[4];
        if (row < VOCAB) {
            float4 v0 = *(const float4*)(src + e);
            float4 v1 = *(const float4*)(src + e + 4);
            h[0] = __floats2half2_rn(v0.x, v0.y);
            h[1] = __floats2half2_rn(v0.z, v0.w);
            h[2] = __floats2half2_rn(v1.x, v1.y);
            h[3] = __floats2half2_rn(v1.z, v1.w);
        } else {
            h[0] = h[1] = h[2] = h[3] = __float2half2_rn(0.f);
        }
        *(uint4*)(g_embH + e) = *(uint4*)h;
    }
}

/* ================= embedding + positional ================= */
__global__ void k_embed(const int* __restrict__ ids,
                        const float* __restrict__ emb,
                        const float* __restrict__ pos)
{
    int r = blockIdx.x;
    int l = r % LSEQ;
    int id = ids[r];
    const float4* e4 = (const float4*)(emb + (size_t)id * DMODEL);
    const float4* p4 = (const float4*)(pos + (size_t)l * DMODEL);
    float4* x4 = (float4*)(g_x + (size_t)r * DMODEL);
    for (int k = threadIdx.x; k < DMODEL / 4; k += blockDim.x) {
        float4 e = e4[k], p = p4[k];
        float4 o;
        o.x = e.x * 32.0f + p.x;
        o.y = e.y * 32.0f + p.y;
        o.z = e.z * 32.0f + p.z;
        o.w = e.w * 32.0f + p.w;
        x4[k] = o;
    }
}

/* ========== fused: R-grammar gate + xm + pre-norm1 + phase vector ========== */
__global__ void k_gate_ln_ph(const float* __restrict__ rg_w, const float* __restrict__ rg_b,
                             const float* __restrict__ n1g, const float* __restrict__ n1b,
                             const float* __restrict__ ph_w, const float* __restrict__ ph_b,
                             const float* __restrict__ ph_scale, int layer,
                             float* __restrict__ gs_out)
{
    int r = blockIdx.x, t = threadIdx.x;   /* 256 threads, 4 elems each */
    int w = t >> 5, lane = t & 31;
    __shared__ float gred[8][4];
    __shared__ float sred[8], qred[8];
    __shared__ float pred_[8][16];
    __shared__ float s_ms, s_mean, s_inv;

    float4 xv = ((const float4*)(g_x + (size_t)r * DMODEL))[t];

    /* gate: 4 dot products over the row */
    const float4* w4 = (const float4*)(rg_w + (size_t)layer * DMODEL * 4);
    float4 wa = w4[t * 4 + 0], wb = w4[t * 4 + 1], wc = w4[t * 4 + 2], wd = w4[t * 4 + 3];
    float s0 = xv.x * wa.x + xv.y * wb.x + xv.z * wc.x + xv.w * wd.x;
    float s1 = xv.x * wa.y + xv.y * wb.y + xv.z * wc.y + xv.w * wd.y;
    float s2 = xv.x * wa.z + xv.y * wb.z + xv.z * wc.z + xv.w * wd.z;
    float s3 = xv.x * wa.w + xv.y * wb.w + xv.z * wc.w + xv.w * wd.w;
    #pragma unroll
    for (int o = 16; o > 0; o >>= 1) {
        s0 += __shfl_xor_sync(0xffffffffu, s0, o);
        s1 += __shfl_xor_sync(0xffffffffu, s1, o);
        s2 += __shfl_xor_sync(0xffffffffu, s2, o);
        s3 += __shfl_xor_sync(0xffffffffu, s3, o);
    }
    if (lane == 0) { gred[w][0] = s0; gred[w][1] = s1; gred[w][2] = s2; gred[w][3] = s3; }
    __syncthreads();
    if (t == 0) {
        float sum4 = 0.f;
        float* gsp = gs_out + ((size_t)layer * NROWS + r) * 4;
        #pragma unroll
        for (int n = 0; n < 4; n++) {
            float a = rg_b[layer * 4 + n];
            #pragma unroll
            for (int ww = 0; ww < 8; ww++) a += gred[ww][n];
            float sg = 1.0f / (1.0f + expf(-a));
            gsp[n] = sg;
            sum4 += sg;
        }
        s_ms = 1.0f + 0.1f * (sum4 * 0.25f);
    }
    __syncthreads();
    float ms = s_ms;
    float4 xm;
    xm.x = xv.x * ms; xm.y = xv.y * ms; xm.z = xv.z * ms; xm.w = xv.w * ms;
    ((float4*)(g_xm + (size_t)r * DMODEL))[t] = xm;

    /* LayerNorm stats on xm */
    float s = xm.x + xm.y + xm.z + xm.w;
    float q = xm.x * xm.x + xm.y * xm.y + xm.z * xm.z + xm.w * xm.w;
    #pragma unroll
    for (int o = 16; o > 0; o >>= 1) {
        s += __shfl_xor_sync(0xffffffffu, s, o);
        q += __shfl_xor_sync(0xffffffffu, q, o);
    }
    if (lane == 0) { sred[w] = s; qred[w] = q; }
    __syncthreads();
    if (t == 0) {
        float S = 0.f, Q = 0.f;
        #pragma unroll
        for (int i = 0; i < 8; i++) { S += sred[i]; Q += qred[i]; }
        float mean = S * (1.0f / DMODEL);
        float var = Q * (1.0f / DMODEL) - mean * mean;
        s_mean = mean;
        s_inv = rsqrtf(var + 1e-5f);
    }
    __syncthreads();
    float mean = s_mean, inv = s_inv;
    float4 gg = ((const float4*)n1g)[t];
    float4 bb = ((const float4*)n1b)[t];
    float a0 = (xm.x - mean) * inv * gg.x + bb.x;
    float a1 = (xm.y - mean) * inv * gg.y + bb.y;
    float a2 = (xm.z - mean) * inv * gg.z + bb.z;
    float a3 = (xm.w - mean) * inv * gg.w + bb.w;
    __half2* hp = (__half2*)(g_ainH + (size_t)r * DMODEL + t * 4);
    hp[0] = __floats2half2_rn(a0, a1);
    hp[1] = __floats2half2_rn(a2, a3);

    /* phase vector: 16 dots over the row using a_in */
    const float4* p4 = (const float4*)(ph_w + (size_t)layer * DMODEL * NHEAD);
    float acc[16];
    #pragma unroll
    for (int n = 0; n < 16; n++) acc[n] = 0.f;
    float av[4] = {a0, a1, a2, a3};
    #pragma unroll
    for (int e = 0; e < 4; e++) {
        float a = av[e];
        const float4* pr = p4 + (size_t)(t * 4 + e) * 4;
        float4 p0 = pr[0], p1 = pr[1], p2 = pr[2], p3 = pr[3];
        acc[0]  += a * p0.x; acc[1]  += a * p0.y; acc[2]  += a * p0.z; acc[3]  += a * p0.w;
        acc[4]  += a * p1.x; acc[5]  += a * p1.y; acc[6]  += a * p1.z; acc[7]  += a * p1.w;
        acc[8]  += a * p2.x; acc[9]  += a * p2.y; acc[10] += a * p2.z; acc[11] += a * p2.w;
        acc[12] += a * p3.x; acc[13] += a * p3.y; acc[14] += a * p3.z; acc[15] += a * p3.w;
    }
    #pragma unroll
    for (int n = 0; n < 16; n++) {
        #pragma unroll
        for (int o = 16; o > 0; o >>= 1)
            acc[n] += __shfl_xor_sync(0xffffffffu, acc[n], o);
    }
    if (lane == 0) {
        #pragma unroll
        for (int n = 0; n < 16; n++) pred_[w][n] = acc[n];
    }
    __syncthreads();
    if (t < 16) {
        float v = ph_b[layer * NHEAD + t];
        #pragma unroll
        for (int ww = 0; ww < 8; ww++) v += pred_[ww][t];
        g_pv[(size_t)r * NHEAD + t] = tanhf(ph_scale[layer] * v);
    }
}

/* ================= LayerNorm: fp16 main output + optional fp32 copy ======= */
__global__ void k_ln(const float* __restrict__ in,
                     const float* __restrict__ g,
                     const float* __restrict__ b,
                     __half* __restrict__ outh,
                     float* __restrict__ outf)
{
    int r = blockIdx.x, t = threadIdx.x;
    const float4* i4 = (const float4*)(in + (size_t)r * DMODEL);
    float4 v = i4[t];
    float s = v.x + v.y + v.z + v.w;
    float q = v.x * v.x + v.y * v.y + v.z * v.z + v.w * v.w;
    for (int o = 16; o > 0; o >>= 1) {
        s += __shfl_down_sync(0xffffffffu, s, o);
        q += __shfl_down_sync(0xffffffffu, q, o);
    }
    __shared__ float sr[8], qr[8];
    __shared__ float smean, sinv;
    if ((t & 31) == 0) { sr[t >> 5] = s; qr[t >> 5] = q; }
    __syncthreads();
    if (t == 0) {
        float S = 0.f, Q = 0.f;
        #pragma unroll
        for (int i = 0; i < 8; i++) { S += sr[i]; Q += qr[i]; }
        float mean = S * (1.0f / DMODEL);
        float var = Q * (1.0f / DMODEL) - mean * mean;
        smean = mean;
        sinv = rsqrtf(var + 1e-5f);
    }
    __syncthreads();
    float mean = smean, inv = sinv;
    float4 gg = ((const float4*)g)[t];
    float4 bb = ((const float4*)b)[t];
    float4 o;
    o.x = (v.x - mean) * inv * gg.x + bb.x;
    o.y = (v.y - mean) * inv * gg.y + bb.y;
    o.z = (v.z - mean) * inv * gg.z + bb.z;
    o.w = (v.w - mean) * inv * gg.w + bb.w;
    __half2* hp = (__half2*)(outh + (size_t)r * DMODEL + t * 4);
    hp[0] = __floats2half2_rn(o.x, o.y);
    hp[1] = __floats2half2_rn(o.z, o.w);
    if (outf)
        ((float4*)(outf + (size_t)r * DMODEL))[t] = o;
}

/* ================= boundary scalar ================= */
__global__ void k_bnd2(const float* __restrict__ w2,
                       const float* __restrict__ b2,
                       float* __restrict__ ss_out, int layer)
{
    int r = blockIdx.x, t = threadIdx.x;
    const float* hr = g_bndh + (size_t)r * HIDB;
    float s = 0.f;
    for (int k = t; k < HIDB; k += 128) s += hr[k] * w2[k];
    for (int o = 16; o > 0; o >>= 1) s += __shfl_down_sync(0xffffffffu, s, o);
    __shared__ float red[4];
    if ((t & 31) == 0) red[t >> 5] = s;
    __syncthreads();
    if (t == 0) {
        float v = red[0] + red[1] + red[2] + red[3] + b2[0];
        ss_out[(size_t)layer * NROWS + r] = 1.0f / (1.0f + expf(-v));
    }
}

/* ================= means over layers ================= */
__global__ void k_means(float* out)
{
    int idx = blockIdx.x * 256 + threadIdx.x;
    if (idx < NROWS * 4) {
        float s = 0.f;
        #pragma unroll
        for (int l = 0; l < NLAY; l++) s += out[OUT_GS + (size_t)l * NROWS * 4 + idx];
        out[OUT_GSM + idx] = s * (1.0f / NLAY);
    }
    int idx2 = idx - NROWS * 4;
    if (idx2 >= 0 && idx2 < NROWS) {
        float s = 0.f;
        #pragma unroll
        for (int l = 0; l < NLAY; l++) s += out[OUT_SS + (size_t)l * NROWS + idx2];
        out[OUT_SSM + idx2] = s * (1.0f / NLAY);
    }
}

/* ================= host ================= */
extern "C" void kernel_launch(void* const* d_in, const int* in_sizes, int n_in,
                              void* d_out, int out_size)
{
    const int*   ids      = (const int*)  d_in[0];
    const float* embed    = (const float*)d_in[1];
    const float* pos_enc  = (const float*)d_in[2];
    const float* rg_w     = (const float*)d_in[3];
    const float* rg_b     = (const float*)d_in[4];
    const float* qkv_w    = (const float*)d_in[5];
    const float* qkv_b    = (const float*)d_in[6];
    const float* out_w    = (const float*)d_in[7];
    const float* out_b    = (const float*)d_in[8];
    const float* ph_w     = (const float*)d_in[9];
    const float* ph_b     = (const float*)d_in[10];
    const float* resscale = (const float*)d_in[11];
    const float* ph_scale = (const float*)d_in[12];
    const float* ff1_w    = (const float*)d_in[13];
    const float* ff1_b    = (const float*)d_in[14];
    const float* ff2_w    = (const float*)d_in[15];
    const float* ff2_b    = (const float*)d_in[16];
    const float* n1_g     = (const float*)d_in[17];
    const float* n1_b     = (const float*)d_in[18];
    const float* n2_g     = (const float*)d_in[19];
    const float* n2_b     = (const float*)d_in[20];
    const float* bnd_w1   = (const float*)d_in[21];
    const float* bnd_b1   = (const float*)d_in[22];
    const float* bnd_w2   = (const float*)d_in[23];
    const float* bnd_b2   = (const float*)d_in[24];
    const float* fn_g     = (const float*)d_in[25];
    const float* fn_b     = (const float*)d_in[26];
    float* out = (float*)d_out;

    float *px, *pxm, *pbndh;
    __half *painH, *paoH, *pffhH, *pqkvH, *pwh, *pembH;
    cudaGetSymbolAddress((void**)&px,    g_x);
    cudaGetSymbolAddress((void**)&pxm,   g_xm);
    cudaGetSymbolAddress((void**)&pbndh, g_bndh);
    cudaGetSymbolAddress((void**)&painH, g_ainH);
    cudaGetSymbolAddress((void**)&paoH,  g_aoH);
    cudaGetSymbolAddress((void**)&pffhH, g_ffhH);
    cudaGetSymbolAddress((void**)&pqkvH, g_qkvH);
    cudaGetSymbolAddress((void**)&pwh,   g_wh);
    cudaGetSymbolAddress((void**)&pembH, g_embH);

    cudaFuncSetAttribute(k_hgemm, cudaFuncAttributeMaxDynamicSharedMemorySize, GEMM_SMEM);

    /* weight conversions, layer-batched over grid.z */
    dim3 tb(256);
    k_cvtT<<<dim3(3 * DMODEL / 64, DMODEL / 64, NLAY), tb>>>(qkv_w, pwh + W_QKV, DMODEL, 3 * DMODEL);
    k_cvtT<<<dim3(DMODEL / 64, DMODEL / 64, NLAY), tb>>>(out_w, pwh + W_OUT, DMODEL, DMODEL);
    k_cvtT<<<dim3(FFDIM / 64, DMODEL / 64, NLAY), tb>>>(ff1_w, pwh + W_FF1, DMODEL, FFDIM);
    k_cvtT<<<dim3(DMODEL / 64, FFDIM / 64, NLAY), tb>>>(ff2_w, pwh + W_FF2, FFDIM, DMODEL);
    k_cvtT<<<dim3(HIDB / 64, DMODEL / 64, 1), tb>>>(bnd_w1, pwh + W_BND, DMODEL, HIDB);
    k_cvtE<<<2048, 256>>>(embed);
    k_embed<<<NROWS, 256>>>(ids, embed, pos_enc);

    for (int i = 0; i < NLAY; i++) {
        /* gate + xm + pre-norm1 + phase, fused */
        k_gate_ln_ph<<<NROWS, 256>>>(rg_w, rg_b,
                                     n1_g + (size_t)i * DMODEL, n1_b + (size_t)i * DMODEL,
                                     ph_w, ph_b, ph_scale, i, out + OUT_GS);
        /* QKV projection -> fp16 qkv */
        {
            dim3 grid((3 * DMODEL) / 128, NROWS / 128);
            k_hgemm<<<grid, 256, GEMM_SMEM>>>(painH, pwh + W_QKV + (size_t)i * 3 * DMODEL * DMODEL,
                                              qkv_b + (size_t)i * 3 * DMODEL, (const float*)0,
                                              (float*)0, pqkvH, NROWS, 3 * DMODEL, DMODEL, 0);
        }
        k_vT<<<dim3(LSEQ / 64, NHEAD, NB), 256>>>();
        {
            dim3 grid(LSEQ / 64, NHEAD, NB);
            k_attn<<<grid, 128>>>(resscale, i);
        }
        /* out projection + residual (xm) -> px fp32 */
        {
            dim3 grid(DMODEL / 128, NROWS / 128);
            k_hgemm<<<grid, 256, GEMM_SMEM>>>(paoH, pwh + W_OUT + (size_t)i * DMODEL * DMODEL,
                                              out_b + (size_t)i * DMODEL, pxm,
                                              px, (__half*)0, NROWS, DMODEL, DMODEL, 0);
        }
        k_ln<<<NROWS, 256>>>(px, n2_g + (size_t)i * DMODEL, n2_b + (size_t)i * DMODEL,
                             painH, (float*)0);
        /* FF1 + GELU -> fp16 hidden */
        {
            dim3 grid(FFDIM / 128, NROWS / 128);
            k_hgemm<<<grid, 256, GEMM_SMEM>>>(painH, pwh + W_FF1 + (size_t)i * DMODEL * FFDIM,
                                              ff1_b + (size_t)i * FFDIM, (const float*)0,
                                              (float*)0, pffhH, NROWS, FFDIM, DMODEL, 1);
        }
        /* FF2 + residual -> px fp32 AND fp16 copy for boundary */
        {
            dim3 grid(DMODEL / 128, NROWS / 128);
            k_hgemm<<<grid, 256, GEMM_SMEM>>>(pffhH, pwh + W_FF2 + (size_t)i * FFDIM * DMODEL,
                                              ff2_b + (size_t)i * DMODEL, px,
                                              px, painH, NROWS, DMODEL, FFDIM, 0);
        }
        /* boundary MLP layer 1 (tanh) -> fp32 hidden */
        {
            dim3 grid(HIDB / 128, NROWS / 128);
            k_hgemm<<<grid, 256, GEMM_SMEM>>>(painH, pwh + W_BND, bnd_b1, (const float*)0,
                                              pbndh, (__half*)0, NROWS, HIDB, DMODEL, 2);
        }
        k_bnd2<<<NROWS, 128>>>(bnd_w2, bnd_b2, out + OUT_SS, i);
    }

    /* final LN -> fp32 x output + fp16 copy for logits A */
    k_ln<<<NROWS, 256>>>(px, fn_g, fn_b, painH, out + OUT_X);

    {
        dim3 grid(VPAD / 128, NROWS / 128);
        k_hgemm<<<grid, 256, GEMM_SMEM>>>(painH, pembH, (const float*)0, (const float*)0,
                                          out + OUT_LOGITS, (__half*)0, NROWS, VOCAB, DMODEL, 0);
    }

    k_means<<<(NROWS * 4 + NROWS + 255) / 256, 256>>>(out);
}

// round 13
// speedup vs baseline: 1.0116x; 1.0116x over previous
#include <cuda_runtime.h>
#include <cuda_fp16.h>
#include <math.h>
#include <stdint.h>

#define NB      2
#define LSEQ    1024
#define DMODEL  1024
#define NHEAD   16
#define DHEAD   64
#define NLAY    6
#define VOCAB   30000
#define VPAD    30080
#define HIDB    512
#define FFDIM   4096
#define NROWS   2048   /* NB*LSEQ */

/* ---- output layout (flattened tuple, in reference return order) ---- */
static const size_t OUT_LOGITS = 0;
static const size_t OUT_X   = (size_t)NROWS * VOCAB;
static const size_t OUT_GSM = OUT_X   + (size_t)NROWS * DMODEL;
static const size_t OUT_SSM = OUT_GSM + (size_t)NROWS * 4;
static const size_t OUT_GS  = OUT_SSM + (size_t)NROWS;
static const size_t OUT_SS  = OUT_GS  + (size_t)NLAY * NROWS * 4;

/* ---- transposed fp16 weight scratch layout (elements) ---- */
#define W_QKV 0UL
#define W_OUT (W_QKV + (size_t)NLAY * DMODEL * 3 * DMODEL)
#define W_FF1 (W_OUT + (size_t)NLAY * DMODEL * DMODEL)
#define W_FF2 (W_FF1 + (size_t)NLAY * DMODEL * FFDIM)
#define W_BND (W_FF2 + (size_t)NLAY * FFDIM * DMODEL)
#define W_TOT (W_BND + (size_t)DMODEL * HIDB)

/* ---- scratch ---- */
__device__ float g_x  [NROWS * DMODEL];
__device__ float g_xm [NROWS * DMODEL];
__device__ float g_pv [NROWS * NHEAD];
__device__ float g_bndh[NROWS * HIDB];
__device__ __align__(16) __half g_ainH[NROWS * DMODEL];
__device__ __align__(16) __half g_aoH [NROWS * DMODEL];
__device__ __align__(16) __half g_ffhH[NROWS * FFDIM];
__device__ __align__(16) __half g_qkvH[NROWS * 3 * DMODEL];
__device__ __align__(16) __half g_wh  [W_TOT];
__device__ __align__(16) __half g_embH[(size_t)VPAD * DMODEL];

/* ================= low-level helpers (compute_103-safe) ================= */
__device__ __forceinline__ uint32_t smem_u32(const void* p) {
    uint32_t a;
    asm("{ .reg .u64 t; cvta.to.shared.u64 t, %1; cvt.u32.u64 %0, t; }" : "=r"(a) : "l"(p));
    return a;
}
__device__ __forceinline__ void cp16(void* s, const void* g) {
    asm volatile("cp.async.cg.shared.global [%0], [%1], 16;"
                 :: "r"(smem_u32(s)), "l"(g) : "memory");
}
#define CP_COMMIT() asm volatile("cp.async.commit_group;" ::: "memory")
#define CP_WAIT1()  asm volatile("cp.async.wait_group 1;" ::: "memory")
#define CP_WAIT0()  asm volatile("cp.async.wait_group 0;" ::: "memory")

#define LDSM4(r0, r1, r2, r3, addr) \
    asm volatile("ldmatrix.sync.aligned.m8n8.x4.shared.b16 {%0,%1,%2,%3}, [%4];" \
                 : "=r"(r0), "=r"(r1), "=r"(r2), "=r"(r3) : "r"(addr))

#define LDSM4T(r0, r1, r2, r3, addr) \
    asm volatile("ldmatrix.sync.aligned.m8n8.x4.trans.shared.b16 {%0,%1,%2,%3}, [%4];" \
                 : "=r"(r0), "=r"(r1), "=r"(r2), "=r"(r3) : "r"(addr))

__device__ __forceinline__ void mma_h(float* c, const uint32_t* a, const uint32_t* b) {
    asm volatile(
        "mma.sync.aligned.m16n8k16.row.col.f32.f16.f16.f32 "
        "{%0,%1,%2,%3}, {%4,%5,%6,%7}, {%8,%9}, {%0,%1,%2,%3};"
        : "+f"(c[0]), "+f"(c[1]), "+f"(c[2]), "+f"(c[3])
        : "r"(a[0]), "r"(a[1]), "r"(a[2]), "r"(a[3]), "r"(b[0]), "r"(b[1]));
}

/* ================= fp16 mma GEMM (round-11 verified, 2-stage) =============
   C[M,N](f32) / C2[M,N](fp16) = act(A[M,K] @ Bt[N,K]^T + bias) (+resid) */
#define GEMM_SMEM 65536

__global__ __launch_bounds__(256, 2)
void k_hgemm(const __half* __restrict__ A, const __half* __restrict__ Bm,
             const float* __restrict__ bias, const float* __restrict__ resid,
             float* __restrict__ C, __half* __restrict__ C2,
             int M, int N, int K, int act)
{
    extern __shared__ __half hs[];
    __half* As = hs;              /* 2 stages x 8192 halves */
    __half* Bs = hs + 16384;

    const int tid  = threadIdx.x;
    const int wid  = tid >> 5;
    const int lane = tid & 31;
    const int m0 = blockIdx.y * 128;
    const int n0 = blockIdx.x * 128;
    const int wm = (wid & 1) * 64;
    const int wn = (wid >> 1) * 32;
    const int nch = K >> 6;

    const int st_row = tid >> 3;
    const uint32_t st_sw = (uint32_t)(((tid & 7) ^ (st_row & 7)) * 8);
    const __half* aglob = A + (size_t)(m0 + st_row) * K + (tid & 7) * 8;
    const __half* bglob = Bm + (size_t)(n0 + st_row) * K + (tid & 7) * 8;

#define HSTAGE(ch, s) do {                                                      \
    __half* as_ = As + (s) * 8192;                                              \
    __half* bs_ = Bs + (s) * 8192;                                              \
    const __half* ap = aglob + (ch) * 64;                                       \
    const __half* bp = bglob + (ch) * 64;                                       \
    _Pragma("unroll")                                                           \
    for (int it = 0; it < 4; it++) {                                            \
        cp16(as_ + (st_row + it * 32) * 64 + st_sw, ap + (size_t)(it * 32) * K);\
        cp16(bs_ + (st_row + it * 32) * 64 + st_sw, bp + (size_t)(it * 32) * K);\
    }                                                                           \
} while (0)

    const int lsw = lane & 7;
    const int rA  = (lane & 7) + (lane & 8);
    const int rB  = (lane & 7) + ((lane & 16) >> 1);
    const int cA  = (lane >> 4) & 1;
    const int cB  = (lane >> 3) & 1;

    float cf[4][4][4];
    #pragma unroll
    for (int i = 0; i < 4; i++)
        #pragma unroll
        for (int j = 0; j < 4; j++)
            { cf[i][j][0] = 0.f; cf[i][j][1] = 0.f; cf[i][j][2] = 0.f; cf[i][j][3] = 0.f; }

    HSTAGE(0, 0);
    CP_COMMIT();

    for (int c = 0; c < nch; c++) {
        if (c + 1 < nch) { HSTAGE(c + 1, (c + 1) & 1); CP_COMMIT(); CP_WAIT1(); }
        else             { CP_WAIT0(); }
        __syncthreads();

        const uint32_t ab = smem_u32(As + (c & 1) * 8192);
        const uint32_t bb = smem_u32(Bs + (c & 1) * 8192);

        #pragma unroll
        for (int kk = 0; kk < 4; kk++) {
            const uint32_t sA = (uint32_t)(((kk * 2 + cA) ^ lsw) * 16);
            const uint32_t sB = (uint32_t)(((kk * 2 + cB) ^ lsw) * 16);
            uint32_t af[4][4], bf[2][4];
            #pragma unroll
            for (int mt = 0; mt < 4; mt++)
                LDSM4(af[mt][0], af[mt][1], af[mt][2], af[mt][3],
                      ab + (uint32_t)(wm + mt * 16 + rA) * 128u + sA);
            #pragma unroll
            for (int p = 0; p < 2; p++)
                LDSM4(bf[p][0], bf[p][1], bf[p][2], bf[p][3],
                      bb + (uint32_t)(wn + p * 16 + rB) * 128u + sB);
            #pragma unroll
            for (int mt = 0; mt < 4; mt++)
                #pragma unroll
                for (int nt = 0; nt < 4; nt++)
                    mma_h(cf[mt][nt], af[mt], &bf[nt >> 1][(nt & 1) * 2]);
        }
        __syncthreads();
    }
#undef HSTAGE

    #pragma unroll
    for (int mt = 0; mt < 4; mt++) {
        int row = m0 + wm + mt * 16 + (lane >> 2);
        #pragma unroll
        for (int nt = 0; nt < 4; nt++) {
            int col = n0 + wn + nt * 8 + (lane & 3) * 2;
            if (col < N) {
                #pragma unroll
                for (int hh = 0; hh < 2; hh++) {
                    int r = row + hh * 8;
                    float v0 = cf[mt][nt][hh * 2 + 0];
                    float v1 = cf[mt][nt][hh * 2 + 1];
                    if (bias) { v0 += bias[col]; v1 += bias[col + 1]; }
                    if (act == 1) {
                        v0 = 0.5f * v0 * (1.0f + erff(v0 * 0.70710678118654752f));
                        v1 = 0.5f * v1 * (1.0f + erff(v1 * 0.70710678118654752f));
                    } else if (act == 2) {
                        v0 = tanhf(v0); v1 = tanhf(v1);
                    }
                    if (resid) {
                        v0 += resid[(size_t)r * N + col];
                        v1 += resid[(size_t)r * N + col + 1];
                    }
                    if (C)  *(float2*)(C + (size_t)r * N + col) = make_float2(v0, v1);
                    if (C2) *(__half2*)(C2 + (size_t)r * N + col) = __floats2half2_rn(v0, v1);
                }
            }
        }
    }
}

/* ====== tensor-core fused attention; V via ldmatrix.trans (no k_vT) ====== */
__global__ __launch_bounds__(128)
void k_attn(const float* __restrict__ res_scale, int layer)
{
    const int b = blockIdx.z, h = blockIdx.y, q0 = blockIdx.x * 64;
    const int tid = threadIdx.x, wid = tid >> 5, lane = tid & 31;
    const float rs = res_scale[layer];

    __shared__ __half Qs[64 * 64];          /* reused as P buffer after tile 0 */
    __shared__ __half Ks[2][64 * 64];
    __shared__ __half Vs[2][64 * 64];       /* [kv][d], same layout as Ks */
    __shared__ float pvs[64];

    const int srow = tid >> 3;
    const int sc   = tid & 7;
    const uint32_t sdst = (uint32_t)((sc ^ (srow & 7)) * 8);

    /* stage Q (rows q0+) and KV tile 0 (rows 0+); V rows direct from qkv */
    {
        const __half* qg = g_qkvH + (size_t)(b * LSEQ + q0 + srow) * 3 * DMODEL + h * DHEAD + sc * 8;
        const __half* kg = g_qkvH + (size_t)(b * LSEQ + srow) * 3 * DMODEL + DMODEL + h * DHEAD + sc * 8;
        #pragma unroll
        for (int it = 0; it < 4; it++) {
            size_t off = (size_t)(it * 16) * 3 * DMODEL;
            cp16(Qs + (srow + it * 16) * 64 + sdst, qg + off);
            cp16(Ks[0] + (srow + it * 16) * 64 + sdst, kg + off);
            cp16(Vs[0] + (srow + it * 16) * 64 + sdst, kg + DMODEL + off);
        }
    }
    CP_COMMIT();

    const int lsw = lane & 7;
    const int rA  = (lane & 7) + (lane & 8);
    const int rB  = (lane & 7) + ((lane & 16) >> 1);
    const int cA  = (lane >> 4) & 1;
    const int cB  = (lane >> 3) & 1;
    const int wm  = wid * 16;
    const int g   = lane >> 2;
    const int tq  = lane & 3;

    const int gr1 = q0 + wm + g;
    const float pq1 = g_pv[(size_t)(b * LSEQ + gr1) * NHEAD + h];
    const float pq2 = g_pv[(size_t)(b * LSEQ + gr1 + 8) * NHEAD + h];

    float o[8][4];
    #pragma unroll
    for (int i = 0; i < 8; i++)
        { o[i][0] = 0.f; o[i][1] = 0.f; o[i][2] = 0.f; o[i][3] = 0.f; }
    float m1 = -1e30f, m2 = -1e30f, d1 = 0.f, d2 = 0.f;
    uint32_t qa[4][4];

    __half* P1 = Qs + (wm + g) * 64 + tq * 2;
    __half* P2 = P1 + 8 * 64;
    const int psw = (g & 7) * 8;

    for (int j = 0; j < LSEQ / 64; j++) {
        const int buf = j & 1;
        if (j + 1 < LSEQ / 64) {
            const int nbuf = buf ^ 1;
            const int kv1 = (j + 1) * 64;
            const __half* kg = g_qkvH + (size_t)(b * LSEQ + kv1 + srow) * 3 * DMODEL
                               + DMODEL + h * DHEAD + sc * 8;
            #pragma unroll
            for (int it = 0; it < 4; it++) {
                size_t off = (size_t)(it * 16) * 3 * DMODEL;
                cp16(Ks[nbuf] + (srow + it * 16) * 64 + sdst, kg + off);
                cp16(Vs[nbuf] + (srow + it * 16) * 64 + sdst, kg + DMODEL + off);
            }
            CP_COMMIT();
            CP_WAIT1();
        } else {
            CP_WAIT0();
        }
        if (tid < 64)
            pvs[tid] = g_pv[(size_t)(b * LSEQ + j * 64 + tid) * NHEAD + h];
        __syncthreads();

        if (j == 0) {
            const uint32_t qb = smem_u32(Qs);
            #pragma unroll
            for (int ks = 0; ks < 4; ks++)
                LDSM4(qa[ks][0], qa[ks][1], qa[ks][2], qa[ks][3],
                      qb + (uint32_t)(wm + rA) * 128u + (uint32_t)(((ks * 2 + cA) ^ lsw) * 16));
        }

        /* S = Q K^T */
        float s[8][4];
        #pragma unroll
        for (int i = 0; i < 8; i++)
            { s[i][0] = 0.f; s[i][1] = 0.f; s[i][2] = 0.f; s[i][3] = 0.f; }
        {
            const uint32_t kb = smem_u32(Ks[buf]);
            #pragma unroll
            for (int ks = 0; ks < 4; ks++) {
                const uint32_t sB = (uint32_t)(((ks * 2 + cB) ^ lsw) * 16);
                uint32_t bfm[4][4];
                #pragma unroll
                for (int nb2 = 0; nb2 < 4; nb2++)
                    LDSM4(bfm[nb2][0], bfm[nb2][1], bfm[nb2][2], bfm[nb2][3],
                          kb + (uint32_t)(nb2 * 16 + rB) * 128u + sB);
                #pragma unroll
                for (int nt = 0; nt < 8; nt++)
                    mma_h(s[nt], qa[ks], &bfm[nt >> 1][(nt & 1) * 2]);
            }
        }

        /* exact phase penalty + online softmax */
        float tmax1 = -1e30f, tmax2 = -1e30f;
        #pragma unroll
        for (int nt = 0; nt < 8; nt++) {
            float k0 = pvs[nt * 8 + tq * 2];
            float k1 = pvs[nt * 8 + tq * 2 + 1];
            float u;
            u = pq1 - k0; s[nt][0] = s[nt][0] * 0.125f - rs * u * u;
            u = pq1 - k1; s[nt][1] = s[nt][1] * 0.125f - rs * u * u;
            u = pq2 - k0; s[nt][2] = s[nt][2] * 0.125f - rs * u * u;
            u = pq2 - k1; s[nt][3] = s[nt][3] * 0.125f - rs * u * u;
            tmax1 = fmaxf(tmax1, fmaxf(s[nt][0], s[nt][1]));
            tmax2 = fmaxf(tmax2, fmaxf(s[nt][2], s[nt][3]));
        }
        tmax1 = fmaxf(tmax1, __shfl_xor_sync(0xffffffffu, tmax1, 1));
        tmax1 = fmaxf(tmax1, __shfl_xor_sync(0xffffffffu, tmax1, 2));
        tmax2 = fmaxf(tmax2, __shfl_xor_sync(0xffffffffu, tmax2, 1));
        tmax2 = fmaxf(tmax2, __shfl_xor_sync(0xffffffffu, tmax2, 2));
        float mn1 = fmaxf(m1, tmax1), mn2 = fmaxf(m2, tmax2);
        float c1 = __expf(m1 - mn1), c2 = __expf(m2 - mn2);
        m1 = mn1; m2 = mn2;
        d1 *= c1; d2 *= c2;
        #pragma unroll
        for (int nt = 0; nt < 8; nt++) {
            o[nt][0] *= c1; o[nt][1] *= c1;
            o[nt][2] *= c2; o[nt][3] *= c2;
        }
        #pragma unroll
        for (int nt = 0; nt < 8; nt++) {
            float p0 = __expf(s[nt][0] - m1), p1 = __expf(s[nt][1] - m1);
            float p2 = __expf(s[nt][2] - m2), p3 = __expf(s[nt][3] - m2);
            d1 += p0 + p1; d2 += p2 + p3;
            int chunk = (nt ^ psw / 8) * 8;
            *(__half2*)(P1 + chunk) = __floats2half2_rn(p0, p1);
            *(__half2*)(P2 + chunk) = __floats2half2_rn(p2, p3);
        }
        __syncwarp();

        /* O += P @ V  (V [kv][d]; B fragment via trans-ldmatrix) */
        {
            const uint32_t pb = smem_u32(Qs);
            const uint32_t vb = smem_u32(Vs[buf]);
            #pragma unroll
            for (int ks = 0; ks < 4; ks++) {
                uint32_t pa[4];
                LDSM4(pa[0], pa[1], pa[2], pa[3],
                      pb + (uint32_t)(wm + rA) * 128u + (uint32_t)(((ks * 2 + cA) ^ lsw) * 16));
                uint32_t vf[4][4];
                #pragma unroll
                for (int nb2 = 0; nb2 < 4; nb2++)
                    LDSM4T(vf[nb2][0], vf[nb2][1], vf[nb2][2], vf[nb2][3],
                           vb + (uint32_t)(ks * 16 + rA) * 128u
                              + (uint32_t)(((nb2 * 2 + cA) ^ lsw) * 16));
                #pragma unroll
                for (int nt = 0; nt < 8; nt++)
                    mma_h(o[nt], pa, &vf[nt >> 1][(nt & 1) * 2]);
            }
        }
        __syncthreads();
    }

    d1 += __shfl_xor_sync(0xffffffffu, d1, 1);
    d1 += __shfl_xor_sync(0xffffffffu, d1, 2);
    d2 += __shfl_xor_sync(0xffffffffu, d2, 1);
    d2 += __shfl_xor_sync(0xffffffffu, d2, 2);
    float i1 = 1.0f / d1, i2 = 1.0f / d2;
    __half* o1 = g_aoH + (size_t)(b * LSEQ + gr1) * DMODEL + h * DHEAD + tq * 2;
    __half* o2 = o1 + (size_t)8 * DMODEL;
    #pragma unroll
    for (int nt = 0; nt < 8; nt++) {
        *(__half2*)(o1 + nt * 8) = __floats2half2_rn(o[nt][0] * i1, o[nt][1] * i1);
        *(__half2*)(o2 + nt * 8) = __floats2half2_rn(o[nt][2] * i2, o[nt][3] * i2);
    }
}

/* ===== weight transpose + fp16 convert, 64x64 tiles, layer-batched (z) ===== */
__global__ void k_cvtT(const float* __restrict__ src, __half* __restrict__ dst,
                       int K, int N)
{
    __shared__ float t[64][65];
    size_t seg = (size_t)blockIdx.z * K * N;
    const float* s0 = src + seg;
    __half* d0 = dst + seg;
    int n0 = blockIdx.x * 64, k0 = blockIdx.y * 64;
    int tid = threadIdx.x;               /* 256 */
    {
        int kr = tid >> 2, c4 = tid & 3;
        const float* sp = s0 + (size_t)(k0 + kr) * N + n0;
        #pragma unroll
        for (int j = 0; j < 4; j++) {
            int col = (c4 + j * 4) * 4;
            float4 v = *(const float4*)(sp + col);
            t[kr][col + 0] = v.x; t[kr][col + 1] = v.y;
            t[kr][col + 2] = v.z; t[kr][col + 3] = v.w;
        }
    }
    __syncthreads();
    {
        int n = tid >> 2, kc = (tid & 3) * 16;
        __half2 h[8];
        #pragma unroll
        for (int j = 0; j < 8; j++)
            h[j] = __floats2half2_rn(t[kc + 2 * j][n], t[kc + 2 * j + 1][n]);
        __half* dp = d0 + (size_t)(n0 + n) * K + k0 + kc;
        *(uint4*)(dp + 0) = *(uint4*)&h[0];
        *(uint4*)(dp + 8) = *(uint4*)&h[4];
    }
}

/* ================= embed -> fp16 [VPAD][D] with zero pad ================= */
__global__ void k_cvtE(const float* __restrict__ src)
{
    size_t stride = (size_t)gridDim.x * blockDim.x;
    size_t tot8 = (size_t)VPAD * DMODEL / 8;
    for (size_t i = (size_t)blockIdx.x * blockDim.x + threadIdx.x; i < tot8; i += stride) {
        size_t e = i * 8;
        size_t row = e >> 10;
        __half2 h[4];
        if (row < VOCAB) {
            float4 v0 = *(const float4*)(src + e);
            float4 v1 = *(const float4*)(src + e + 4);
            h[0] = __floats2half2_rn(v0.x, v0.y);
            h[1] = __floats2half2_rn(v0.z, v0.w);
            h[2] = __floats2half2_rn(v1.x, v1.y);
            h[3] = __floats2half2_rn(v1.z, v1.w);
        } else {
            h[0] = h[1] = h[2] = h[3] = __float2half2_rn(0.f);
        }
        *(uint4*)(g_embH + e) = *(uint4*)h;
    }
}

/* ================= embedding + positional ================= */
__global__ void k_embed(const int* __restrict__ ids,
                        const float* __restrict__ emb,
                        const float* __restrict__ pos)
{
    int r = blockIdx.x;
    int l = r % LSEQ;
    int id = ids[r];
    const float4* e4 = (const float4*)(emb + (size_t)id * DMODEL);
    const float4* p4 = (const float4*)(pos + (size_t)l * DMODEL);
    float4* x4 = (float4*)(g_x + (size_t)r * DMODEL);
    for (int k = threadIdx.x; k < DMODEL / 4; k += blockDim.x) {
        float4 e = e4[k], p = p4[k];
        float4 o;
        o.x = e.x * 32.0f + p.x;
        o.y = e.y * 32.0f + p.y;
        o.z = e.z * 32.0f + p.z;
        o.w = e.w * 32.0f + p.w;
        x4[k] = o;
    }
}

/* ========== fused: R-grammar gate + xm + pre-norm1 + phase vector ========== */
__global__ void k_gate_ln_ph(const float* __restrict__ rg_w, const float* __restrict__ rg_b,
                             const float* __restrict__ n1g, const float* __restrict__ n1b,
                             const float* __restrict__ ph_w, const float* __restrict__ ph_b,
                             const float* __restrict__ ph_scale, int layer,
                             float* __restrict__ gs_out)
{
    int r = blockIdx.x, t = threadIdx.x;   /* 256 threads, 4 elems each */
    int w = t >> 5, lane = t & 31;
    __shared__ float gred[8][4];
    __shared__ float sred[8], qred[8];
    __shared__ float pred_[8][16];
    __shared__ float s_ms, s_mean, s_inv;

    float4 xv = ((const float4*)(g_x + (size_t)r * DMODEL))[t];

    const float4* w4 = (const float4*)(rg_w + (size_t)layer * DMODEL * 4);
    float4 wa = w4[t * 4 + 0], wb = w4[t * 4 + 1], wc = w4[t * 4 + 2], wd = w4[t * 4 + 3];
    float s0 = xv.x * wa.x + xv.y * wb.x + xv.z * wc.x + xv.w * wd.x;
    float s1 = xv.x * wa.y + xv.y * wb.y + xv.z * wc.y + xv.w * wd.y;
    float s2 = xv.x * wa.z + xv.y * wb.z + xv.z * wc.z + xv.w * wd.z;
    float s3 = xv.x * wa.w + xv.y * wb.w + xv.z * wc.w + xv.w * wd.w;
    #pragma unroll
    for (int o = 16; o > 0; o >>= 1) {
        s0 += __shfl_xor_sync(0xffffffffu, s0, o);
        s1 += __shfl_xor_sync(0xffffffffu, s1, o);
        s2 += __shfl_xor_sync(0xffffffffu, s2, o);
        s3 += __shfl_xor_sync(0xffffffffu, s3, o);
    }
    if (lane == 0) { gred[w][0] = s0; gred[w][1] = s1; gred[w][2] = s2; gred[w][3] = s3; }
    __syncthreads();
    if (t == 0) {
        float sum4 = 0.f;
        float* gsp = gs_out + ((size_t)layer * NROWS + r) * 4;
        #pragma unroll
        for (int n = 0; n < 4; n++) {
            float a = rg_b[layer * 4 + n];
            #pragma unroll
            for (int ww = 0; ww < 8; ww++) a += gred[ww][n];
            float sg = 1.0f / (1.0f + expf(-a));
            gsp[n] = sg;
            sum4 += sg;
        }
        s_ms = 1.0f + 0.1f * (sum4 * 0.25f);
    }
    __syncthreads();
    float ms = s_ms;
    float4 xm;
    xm.x = xv.x * ms; xm.y = xv.y * ms; xm.z = xv.z * ms; xm.w = xv.w * ms;
    ((float4*)(g_xm + (size_t)r * DMODEL))[t] = xm;

    float s = xm.x + xm.y + xm.z + xm.w;
    float q = xm.x * xm.x + xm.y * xm.y + xm.z * xm.z + xm.w * xm.w;
    #pragma unroll
    for (int o = 16; o > 0; o >>= 1) {
        s += __shfl_xor_sync(0xffffffffu, s, o);
        q += __shfl_xor_sync(0xffffffffu, q, o);
    }
    if (lane == 0) { sred[w] = s; qred[w] = q; }
    __syncthreads();
    if (t == 0) {
        float S = 0.f, Q = 0.f;
        #pragma unroll
        for (int i = 0; i < 8; i++) { S += sred[i]; Q += qred[i]; }
        float mean = S * (1.0f / DMODEL);
        float var = Q * (1.0f / DMODEL) - mean * mean;
        s_mean = mean;
        s_inv = rsqrtf(var + 1e-5f);
    }
    __syncthreads();
    float mean = s_mean, inv = s_inv;
    float4 gg = ((const float4*)n1g)[t];
    float4 bb = ((const float4*)n1b)[t];
    float a0 = (xm.x - mean) * inv * gg.x + bb.x;
    float a1 = (xm.y - mean) * inv * gg.y + bb.y;
    float a2 = (xm.z - mean) * inv * gg.z + bb.z;
    float a3 = (xm.w - mean) * inv * gg.w + bb.w;
    __half2* hp = (__half2*)(g_ainH + (size_t)r * DMODEL + t * 4);
    hp[0] = __floats2half2_rn(a0, a1);
    hp[1] = __floats2half2_rn(a2, a3);

    const float4* p4 = (const float4*)(ph_w + (size_t)layer * DMODEL * NHEAD);
    float acc[16];
    #pragma unroll
    for (int n = 0; n < 16; n++) acc[n] = 0.f;
    float av[4] = {a0, a1, a2, a3};
    #pragma unroll
    for (int e = 0; e < 4; e++) {
        float a = av[e];
        const float4* pr = p4 + (size_t)(t * 4 + e) * 4;
        float4 p0 = pr[0], p1 = pr[1], p2 = pr[2], p3 = pr[3];
        acc[0]  += a * p0.x; acc[1]  += a * p0.y; acc[2]  += a * p0.z; acc[3]  += a * p0.w;
        acc[4]  += a * p1.x; acc[5]  += a * p1.y; acc[6]  += a * p1.z; acc[7]  += a * p1.w;
        acc[8]  += a * p2.x; acc[9]  += a * p2.y; acc[10] += a * p2.z; acc[11] += a * p2.w;
        acc[12] += a * p3.x; acc[13] += a * p3.y; acc[14] += a * p3.z; acc[15] += a * p3.w;
    }
    #pragma unroll
    for (int n = 0; n < 16; n++) {
        #pragma unroll
        for (int o = 16; o > 0; o >>= 1)
            acc[n] += __shfl_xor_sync(0xffffffffu, acc[n], o);
    }
    if (lane == 0) {
        #pragma unroll
        for (int n = 0; n < 16; n++) pred_[w][n] = acc[n];
    }
    __syncthreads();
    if (t < 16) {
        float v = ph_b[layer * NHEAD + t];
        #pragma unroll
        for (int ww = 0; ww < 8; ww++) v += pred_[ww][t];
        g_pv[(size_t)r * NHEAD + t] = tanhf(ph_scale[layer] * v);
    }
}

/* ================= LayerNorm: fp16 main output + optional fp32 copy ======= */
__global__ void k_ln(const float* __restrict__ in,
                     const float* __restrict__ g,
                     const float* __restrict__ b,
                     __half* __restrict__ outh,
                     float* __restrict__ outf)
{
    int r = blockIdx.x, t = threadIdx.x;
    const float4* i4 = (const float4*)(in + (size_t)r * DMODEL);
    float4 v = i4[t];
    float s = v.x + v.y + v.z + v.w;
    float q = v.x * v.x + v.y * v.y + v.z * v.z + v.w * v.w;
    for (int o = 16; o > 0; o >>= 1) {
        s += __shfl_down_sync(0xffffffffu, s, o);
        q += __shfl_down_sync(0xffffffffu, q, o);
    }
    __shared__ float sr[8], qr[8];
    __shared__ float smean, sinv;
    if ((t & 31) == 0) { sr[t >> 5] = s; qr[t >> 5] = q; }
    __syncthreads();
    if (t == 0) {
        float S = 0.f, Q = 0.f;
        #pragma unroll
        for (int i = 0; i < 8; i++) { S += sr[i]; Q += qr[i]; }
        float mean = S * (1.0f / DMODEL);
        float var = Q * (1.0f / DMODEL) - mean * mean;
        smean = mean;
        sinv = rsqrtf(var + 1e-5f);
    }
    __syncthreads();
    float mean = smean, inv = sinv;
    float4 gg = ((const float4*)g)[t];
    float4 bb = ((const float4*)b)[t];
    float4 o;
    o.x = (v.x - mean) * inv * gg.x + bb.x;
    o.y = (v.y - mean) * inv * gg.y + bb.y;
    o.z = (v.z - mean) * inv * gg.z + bb.z;
    o.w = (v.w - mean) * inv * gg.w + bb.w;
    __half2* hp = (__half2*)(outh + (size_t)r * DMODEL + t * 4);
    hp[0] = __floats2half2_rn(o.x, o.y);
    hp[1] = __floats2half2_rn(o.z, o.w);
    if (outf)
        ((float4*)(outf + (size_t)r * DMODEL))[t] = o;
}

/* ================= boundary scalar ================= */
__global__ void k_bnd2(const float* __restrict__ w2,
                       const float* __restrict__ b2,
                       float* __restrict__ ss_out, int layer)
{
    int r = blockIdx.x, t = threadIdx.x;
    const float* hr = g_bndh + (size_t)r * HIDB;
    float s = 0.f;
    for (int k = t; k < HIDB; k += 128) s += hr[k] * w2[k];
    for (int o = 16; o > 0; o >>= 1) s += __shfl_down_sync(0xffffffffu, s, o);
    __shared__ float red[4];
    if ((t & 31) == 0) red[t >> 5] = s;
    __syncthreads();
    if (t == 0) {
        float v = red[0] + red[1] + red[2] + red[3] + b2[0];
        ss_out[(size_t)layer * NROWS + r] = 1.0f / (1.0f + expf(-v));
    }
}

/* ================= means over layers ================= */
__global__ void k_means(float* out)
{
    int idx = blockIdx.x * 256 + threadIdx.x;
    if (idx < NROWS * 4) {
        float s = 0.f;
        #pragma unroll
        for (int l = 0; l < NLAY; l++) s += out[OUT_GS + (size_t)l * NROWS * 4 + idx];
        out[OUT_GSM + idx] = s * (1.0f / NLAY);
    }
    int idx2 = idx - NROWS * 4;
    if (idx2 >= 0 && idx2 < NROWS) {
        float s = 0.f;
        #pragma unroll
        for (int l = 0; l < NLAY; l++) s += out[OUT_SS + (size_t)l * NROWS + idx2];
        out[OUT_SSM + idx2] = s * (1.0f / NLAY);
    }
}

/* ================= host ================= */
extern "C" void kernel_launch(void* const* d_in, const int* in_sizes, int n_in,
                              void* d_out, int out_size)
{
    const int*   ids      = (const int*)  d_in[0];
    const float* embed    = (const float*)d_in[1];
    const float* pos_enc  = (const float*)d_in[2];
    const float* rg_w     = (const float*)d_in[3];
    const float* rg_b     = (const float*)d_in[4];
    const float* qkv_w    = (const float*)d_in[5];
    const float* qkv_b    = (const float*)d_in[6];
    const float* out_w    = (const float*)d_in[7];
    const float* out_b    = (const float*)d_in[8];
    const float* ph_w     = (const float*)d_in[9];
    const float* ph_b     = (const float*)d_in[10];
    const float* resscale = (const float*)d_in[11];
    const float* ph_scale = (const float*)d_in[12];
    const float* ff1_w    = (const float*)d_in[13];
    const float* ff1_b    = (const float*)d_in[14];
    const float* ff2_w    = (const float*)d_in[15];
    const float* ff2_b    = (const float*)d_in[16];
    const float* n1_g     = (const float*)d_in[17];
    const float* n1_b     = (const float*)d_in[18];
    const float* n2_g     = (const float*)d_in[19];
    const float* n2_b     = (const float*)d_in[20];
    const float* bnd_w1   = (const float*)d_in[21];
    const float* bnd_b1   = (const float*)d_in[22];
    const float* bnd_w2   = (const float*)d_in[23];
    const float* bnd_b2   = (const float*)d_in[24];
    const float* fn_g     = (const float*)d_in[25];
    const float* fn_b     = (const float*)d_in[26];
    float* out = (float*)d_out;

    float *px, *pxm, *pbndh;
    __half *painH, *paoH, *pffhH, *pqkvH, *pwh, *pembH;
    cudaGetSymbolAddress((void**)&px,    g_x);
    cudaGetSymbolAddress((void**)&pxm,   g_xm);
    cudaGetSymbolAddress((void**)&pbndh, g_bndh);
    cudaGetSymbolAddress((void**)&painH, g_ainH);
    cudaGetSymbolAddress((void**)&paoH,  g_aoH);
    cudaGetSymbolAddress((void**)&pffhH, g_ffhH);
    cudaGetSymbolAddress((void**)&pqkvH, g_qkvH);
    cudaGetSymbolAddress((void**)&pwh,   g_wh);
    cudaGetSymbolAddress((void**)&pembH, g_embH);

    cudaFuncSetAttribute(k_hgemm, cudaFuncAttributeMaxDynamicSharedMemorySize, GEMM_SMEM);

    /* weight conversions, layer-batched over grid.z */
    dim3 tb(256);
    k_cvtT<<<dim3(3 * DMODEL / 64, DMODEL / 64, NLAY), tb>>>(qkv_w, pwh + W_QKV, DMODEL, 3 * DMODEL);
    k_cvtT<<<dim3(DMODEL / 64, DMODEL / 64, NLAY), tb>>>(out_w, pwh + W_OUT, DMODEL, DMODEL);
    k_cvtT<<<dim3(FFDIM / 64, DMODEL / 64, NLAY), tb>>>(ff1_w, pwh + W_FF1, DMODEL, FFDIM);
    k_cvtT<<<dim3(DMODEL / 64, FFDIM / 64, NLAY), tb>>>(ff2_w, pwh + W_FF2, FFDIM, DMODEL);
    k_cvtT<<<dim3(HIDB / 64, DMODEL / 64, 1), tb>>>(bnd_w1, pwh + W_BND, DMODEL, HIDB);
    k_cvtE<<<2048, 256>>>(embed);
    k_embed<<<NROWS, 256>>>(ids, embed, pos_enc);

    for (int i = 0; i < NLAY; i++) {
        k_gate_ln_ph<<<NROWS, 256>>>(rg_w, rg_b,
                                     n1_g + (size_t)i * DMODEL, n1_b + (size_t)i * DMODEL,
                                     ph_w, ph_b, ph_scale, i, out + OUT_GS);
        /* QKV projection -> fp16 qkv */
        {
            dim3 grid((3 * DMODEL) / 128, NROWS / 128);
            k_hgemm<<<grid, 256, GEMM_SMEM>>>(painH, pwh + W_QKV + (size_t)i * 3 * DMODEL * DMODEL,
                                              qkv_b + (size_t)i * 3 * DMODEL, (const float*)0,
                                              (float*)0, pqkvH, NROWS, 3 * DMODEL, DMODEL, 0);
        }
        {
            dim3 grid(LSEQ / 64, NHEAD, NB);
            k_attn<<<grid, 128>>>(resscale, i);
        }
        /* out projection + residual (xm) -> px fp32 */
        {
            dim3 grid(DMODEL / 128, NROWS / 128);
            k_hgemm<<<grid, 256, GEMM_SMEM>>>(paoH, pwh + W_OUT + (size_t)i * DMODEL * DMODEL,
                                              out_b + (size_t)i * DMODEL, pxm,
                                              px, (__half*)0, NROWS, DMODEL, DMODEL, 0);
        }
        k_ln<<<NROWS, 256>>>(px, n2_g + (size_t)i * DMODEL, n2_b + (size_t)i * DMODEL,
                             painH, (float*)0);
        /* FF1 + GELU -> fp16 hidden */
        {
            dim3 grid(FFDIM / 128, NROWS / 128);
            k_hgemm<<<grid, 256, GEMM_SMEM>>>(painH, pwh + W_FF1 + (size_t)i * DMODEL * FFDIM,
                                              ff1_b + (size_t)i * FFDIM, (const float*)0,
                                              (float*)0, pffhH, NROWS, FFDIM, DMODEL, 1);
        }
        /* FF2 + residual -> px fp32 AND fp16 copy for boundary */
        {
            dim3 grid(DMODEL / 128, NROWS / 128);
            k_hgemm<<<grid, 256, GEMM_SMEM>>>(pffhH, pwh + W_FF2 + (size_t)i * FFDIM * DMODEL,
                                              ff2_b + (size_t)i * DMODEL, px,
                                              px, painH, NROWS, DMODEL, FFDIM, 0);
        }
        /* boundary MLP layer 1 (tanh) -> fp32 hidden */
        {
            dim3 grid(HIDB / 128, NROWS / 128);
            k_hgemm<<<grid, 256, GEMM_SMEM>>>(painH, pwh + W_BND, bnd_b1, (const float*)0,
                                              pbndh, (__half*)0, NROWS, HIDB, DMODEL, 2);
        }
        k_bnd2<<<NROWS, 128>>>(bnd_w2, bnd_b2, out + OUT_SS, i);
    }

    /* final LN -> fp32 x output + fp16 copy for logits A */
    k_ln<<<NROWS, 256>>>(px, fn_g, fn_b, painH, out + OUT_X);

    {
        dim3 grid(VPAD / 128, NROWS / 128);
        k_hgemm<<<grid, 256, GEMM_SMEM>>>(painH, pembH, (const float*)0, (const float*)0,
                                          out + OUT_LOGITS, (__half*)0, NROWS, VOCAB, DMODEL, 0);
    }

    k_means<<<(NROWS * 4 + NROWS + 255) / 256, 256>>>(out);
}

// round 14
// speedup vs baseline: 1.0429x; 1.0309x over previous
#include <cuda_runtime.h>
#include <cuda_fp16.h>
#include <math.h>
#include <stdint.h>

#define NB      2
#define LSEQ    1024
#define DMODEL  1024
#define NHEAD   16
#define DHEAD   64
#define NLAY    6
#define VOCAB   30000
#define VPAD    30080
#define HIDB    512
#define FFDIM   4096
#define NROWS   2048   /* NB*LSEQ */

/* ---- output layout (flattened tuple, in reference return order) ---- */
static const size_t OUT_LOGITS = 0;
static const size_t OUT_X   = (size_t)NROWS * VOCAB;
static const size_t OUT_GSM = OUT_X   + (size_t)NROWS * DMODEL;
static const size_t OUT_SSM = OUT_GSM + (size_t)NROWS * 4;
static const size_t OUT_GS  = OUT_SSM + (size_t)NROWS;
static const size_t OUT_SS  = OUT_GS  + (size_t)NLAY * NROWS * 4;

/* ---- transposed fp16 weight scratch layout (elements) ---- */
#define W_QKV 0UL
#define W_OUT (W_QKV + (size_t)NLAY * DMODEL * 3 * DMODEL)
#define W_FF1 (W_OUT + (size_t)NLAY * DMODEL * DMODEL)
#define W_FF2 (W_FF1 + (size_t)NLAY * DMODEL * FFDIM)
#define W_BND (W_FF2 + (size_t)NLAY * FFDIM * DMODEL)
#define W_TOT (W_BND + (size_t)DMODEL * HIDB)

/* ---- scratch ---- */
__device__ float g_x  [NROWS * DMODEL];
__device__ float g_xm [NROWS * DMODEL];
__device__ float g_pv [NROWS * NHEAD];
__device__ float g_bndh[NROWS * HIDB];
__device__ __align__(16) __half g_ainH[NROWS * DMODEL];
__device__ __align__(16) __half g_aoH [NROWS * DMODEL];
__device__ __align__(16) __half g_ffhH[NROWS * FFDIM];
__device__ __align__(16) __half g_qkvH[NROWS * 3 * DMODEL];
__device__ __align__(16) __half g_wh  [W_TOT];
__device__ __align__(16) __half g_embH[(size_t)VPAD * DMODEL];

/* ================= low-level helpers (compute_103-safe) ================= */
__device__ __forceinline__ uint32_t smem_u32(const void* p) {
    uint32_t a;
    asm("{ .reg .u64 t; cvta.to.shared.u64 t, %1; cvt.u32.u64 %0, t; }" : "=r"(a) : "l"(p));
    return a;
}
__device__ __forceinline__ void cp16(void* s, const void* g) {
    asm volatile("cp.async.cg.shared.global [%0], [%1], 16;"
                 :: "r"(smem_u32(s)), "l"(g) : "memory");
}
#define CP_COMMIT() asm volatile("cp.async.commit_group;" ::: "memory")
#define CP_WAIT1()  asm volatile("cp.async.wait_group 1;" ::: "memory")
#define CP_WAIT0()  asm volatile("cp.async.wait_group 0;" ::: "memory")

#define LDSM4(r0, r1, r2, r3, addr) \
    asm volatile("ldmatrix.sync.aligned.m8n8.x4.shared.b16 {%0,%1,%2,%3}, [%4];" \
                 : "=r"(r0), "=r"(r1), "=r"(r2), "=r"(r3) : "r"(addr))

#define LDSM4T(r0, r1, r2, r3, addr) \
    asm volatile("ldmatrix.sync.aligned.m8n8.x4.trans.shared.b16 {%0,%1,%2,%3}, [%4];" \
                 : "=r"(r0), "=r"(r1), "=r"(r2), "=r"(r3) : "r"(addr))

__device__ __forceinline__ void mma_h(float* c, const uint32_t* a, const uint32_t* b) {
    asm volatile(
        "mma.sync.aligned.m16n8k16.row.col.f32.f16.f16.f32 "
        "{%0,%1,%2,%3}, {%4,%5,%6,%7}, {%8,%9}, {%0,%1,%2,%3};"
        : "+f"(c[0]), "+f"(c[1]), "+f"(c[2]), "+f"(c[3])
        : "r"(a[0]), "r"(a[1]), "r"(a[2]), "r"(a[3]), "r"(b[0]), "r"(b[1]));
}
/* fp16-accumulate variant (double rate); C = 2 regs of half2 */
__device__ __forceinline__ void mma_hh(uint32_t* c, const uint32_t* a, const uint32_t* b) {
    asm volatile(
        "mma.sync.aligned.m16n8k16.row.col.f16.f16.f16.f16 "
        "{%0,%1}, {%2,%3,%4,%5}, {%6,%7}, {%0,%1};"
        : "+r"(c[0]), "+r"(c[1])
        : "r"(a[0]), "r"(a[1]), "r"(a[2]), "r"(a[3]), "r"(b[0]), "r"(b[1]));
}

/* ================= fp16 mma GEMM (round-11 verified, 2-stage) =============
   C[M,N](f32) / C2[M,N](fp16) = act(A[M,K] @ Bt[N,K]^T + bias) (+resid) */
#define GEMM_SMEM 65536

__global__ __launch_bounds__(256, 2)
void k_hgemm(const __half* __restrict__ A, const __half* __restrict__ Bm,
             const float* __restrict__ bias, const float* __restrict__ resid,
             float* __restrict__ C, __half* __restrict__ C2,
             int M, int N, int K, int act)
{
    extern __shared__ __half hs[];
    __half* As = hs;              /* 2 stages x 8192 halves */
    __half* Bs = hs + 16384;

    const int tid  = threadIdx.x;
    const int wid  = tid >> 5;
    const int lane = tid & 31;
    const int m0 = blockIdx.y * 128;
    const int n0 = blockIdx.x * 128;
    const int wm = (wid & 1) * 64;
    const int wn = (wid >> 1) * 32;
    const int nch = K >> 6;

    const int st_row = tid >> 3;
    const uint32_t st_sw = (uint32_t)(((tid & 7) ^ (st_row & 7)) * 8);
    const __half* aglob = A + (size_t)(m0 + st_row) * K + (tid & 7) * 8;
    const __half* bglob = Bm + (size_t)(n0 + st_row) * K + (tid & 7) * 8;

#define HSTAGE(ch, s) do {                                                      \
    __half* as_ = As + (s) * 8192;                                              \
    __half* bs_ = Bs + (s) * 8192;                                              \
    const __half* ap = aglob + (ch) * 64;                                       \
    const __half* bp = bglob + (ch) * 64;                                       \
    _Pragma("unroll")                                                           \
    for (int it = 0; it < 4; it++) {                                            \
        cp16(as_ + (st_row + it * 32) * 64 + st_sw, ap + (size_t)(it * 32) * K);\
        cp16(bs_ + (st_row + it * 32) * 64 + st_sw, bp + (size_t)(it * 32) * K);\
    }                                                                           \
} while (0)

    const int lsw = lane & 7;
    const int rA  = (lane & 7) + (lane & 8);
    const int rB  = (lane & 7) + ((lane & 16) >> 1);
    const int cA  = (lane >> 4) & 1;
    const int cB  = (lane >> 3) & 1;

    float cf[4][4][4];
    #pragma unroll
    for (int i = 0; i < 4; i++)
        #pragma unroll
        for (int j = 0; j < 4; j++)
            { cf[i][j][0] = 0.f; cf[i][j][1] = 0.f; cf[i][j][2] = 0.f; cf[i][j][3] = 0.f; }

    HSTAGE(0, 0);
    CP_COMMIT();

    for (int c = 0; c < nch; c++) {
        if (c + 1 < nch) { HSTAGE(c + 1, (c + 1) & 1); CP_COMMIT(); CP_WAIT1(); }
        else             { CP_WAIT0(); }
        __syncthreads();

        const uint32_t ab = smem_u32(As + (c & 1) * 8192);
        const uint32_t bb = smem_u32(Bs + (c & 1) * 8192);

        #pragma unroll
        for (int kk = 0; kk < 4; kk++) {
            const uint32_t sA = (uint32_t)(((kk * 2 + cA) ^ lsw) * 16);
            const uint32_t sB = (uint32_t)(((kk * 2 + cB) ^ lsw) * 16);
            uint32_t af[4][4], bf[2][4];
            #pragma unroll
            for (int mt = 0; mt < 4; mt++)
                LDSM4(af[mt][0], af[mt][1], af[mt][2], af[mt][3],
                      ab + (uint32_t)(wm + mt * 16 + rA) * 128u + sA);
            #pragma unroll
            for (int p = 0; p < 2; p++)
                LDSM4(bf[p][0], bf[p][1], bf[p][2], bf[p][3],
                      bb + (uint32_t)(wn + p * 16 + rB) * 128u + sB);
            #pragma unroll
            for (int mt = 0; mt < 4; mt++)
                #pragma unroll
                for (int nt = 0; nt < 4; nt++)
                    mma_h(cf[mt][nt], af[mt], &bf[nt >> 1][(nt & 1) * 2]);
        }
        __syncthreads();
    }
#undef HSTAGE

    #pragma unroll
    for (int mt = 0; mt < 4; mt++) {
        int row = m0 + wm + mt * 16 + (lane >> 2);
        #pragma unroll
        for (int nt = 0; nt < 4; nt++) {
            int col = n0 + wn + nt * 8 + (lane & 3) * 2;
            if (col < N) {
                #pragma unroll
                for (int hh = 0; hh < 2; hh++) {
                    int r = row + hh * 8;
                    float v0 = cf[mt][nt][hh * 2 + 0];
                    float v1 = cf[mt][nt][hh * 2 + 1];
                    if (bias) { v0 += bias[col]; v1 += bias[col + 1]; }
                    if (act == 1) {
                        v0 = 0.5f * v0 * (1.0f + erff(v0 * 0.70710678118654752f));
                        v1 = 0.5f * v1 * (1.0f + erff(v1 * 0.70710678118654752f));
                    } else if (act == 2) {
                        v0 = tanhf(v0); v1 = tanhf(v1);
                    }
                    if (resid) {
                        v0 += resid[(size_t)r * N + col];
                        v1 += resid[(size_t)r * N + col + 1];
                    }
                    if (C)  *(float2*)(C + (size_t)r * N + col) = make_float2(v0, v1);
                    if (C2) *(__half2*)(C2 + (size_t)r * N + col) = __floats2half2_rn(v0, v1);
                }
            }
        }
    }
}

/* ====== tensor-core fused attention; V via ldmatrix.trans; S fp16-accum === */
__global__ __launch_bounds__(128)
void k_attn(const float* __restrict__ res_scale, int layer)
{
    const int b = blockIdx.z, h = blockIdx.y, q0 = blockIdx.x * 64;
    const int tid = threadIdx.x, wid = tid >> 5, lane = tid & 31;
    const float rs = res_scale[layer];

    __shared__ __half Qs[64 * 64];          /* reused as P buffer after tile 0 */
    __shared__ __half Ks[2][64 * 64];
    __shared__ __half Vs[2][64 * 64];       /* [kv][d], same layout as Ks */
    __shared__ float pvs[64];

    const int srow = tid >> 3;
    const int sc   = tid & 7;
    const uint32_t sdst = (uint32_t)((sc ^ (srow & 7)) * 8);

    /* stage Q (rows q0+) and KV tile 0 (rows 0+); V rows direct from qkv */
    {
        const __half* qg = g_qkvH + (size_t)(b * LSEQ + q0 + srow) * 3 * DMODEL + h * DHEAD + sc * 8;
        const __half* kg = g_qkvH + (size_t)(b * LSEQ + srow) * 3 * DMODEL + DMODEL + h * DHEAD + sc * 8;
        #pragma unroll
        for (int it = 0; it < 4; it++) {
            size_t off = (size_t)(it * 16) * 3 * DMODEL;
            cp16(Qs + (srow + it * 16) * 64 + sdst, qg + off);
            cp16(Ks[0] + (srow + it * 16) * 64 + sdst, kg + off);
            cp16(Vs[0] + (srow + it * 16) * 64 + sdst, kg + DMODEL + off);
        }
    }
    CP_COMMIT();

    const int lsw = lane & 7;
    const int rA  = (lane & 7) + (lane & 8);
    const int rB  = (lane & 7) + ((lane & 16) >> 1);
    const int cA  = (lane >> 4) & 1;
    const int cB  = (lane >> 3) & 1;
    const int wm  = wid * 16;
    const int g   = lane >> 2;
    const int tq  = lane & 3;

    const int gr1 = q0 + wm + g;
    const float pq1 = g_pv[(size_t)(b * LSEQ + gr1) * NHEAD + h];
    const float pq2 = g_pv[(size_t)(b * LSEQ + gr1 + 8) * NHEAD + h];

    float o[8][4];
    #pragma unroll
    for (int i = 0; i < 8; i++)
        { o[i][0] = 0.f; o[i][1] = 0.f; o[i][2] = 0.f; o[i][3] = 0.f; }
    float m1 = -1e30f, m2 = -1e30f, d1 = 0.f, d2 = 0.f;
    uint32_t qa[4][4];

    __half* P1 = Qs + (wm + g) * 64 + tq * 2;
    __half* P2 = P1 + 8 * 64;
    const int psw = (g & 7) * 8;

    for (int j = 0; j < LSEQ / 64; j++) {
        const int buf = j & 1;
        if (j + 1 < LSEQ / 64) {
            const int nbuf = buf ^ 1;
            const int kv1 = (j + 1) * 64;
            const __half* kg = g_qkvH + (size_t)(b * LSEQ + kv1 + srow) * 3 * DMODEL
                               + DMODEL + h * DHEAD + sc * 8;
            #pragma unroll
            for (int it = 0; it < 4; it++) {
                size_t off = (size_t)(it * 16) * 3 * DMODEL;
                cp16(Ks[nbuf] + (srow + it * 16) * 64 + sdst, kg + off);
                cp16(Vs[nbuf] + (srow + it * 16) * 64 + sdst, kg + DMODEL + off);
            }
            CP_COMMIT();
            CP_WAIT1();
        } else {
            CP_WAIT0();
        }
        if (tid < 64)
            pvs[tid] = g_pv[(size_t)(b * LSEQ + j * 64 + tid) * NHEAD + h];
        __syncthreads();

        if (j == 0) {
            const uint32_t qb = smem_u32(Qs);
            #pragma unroll
            for (int ks = 0; ks < 4; ks++)
                LDSM4(qa[ks][0], qa[ks][1], qa[ks][2], qa[ks][3],
                      qb + (uint32_t)(wm + rA) * 128u + (uint32_t)(((ks * 2 + cA) ^ lsw) * 16));
        }

        /* S = Q K^T  (fp16 accumulate, double rate; fresh per tile) */
        uint32_t sh[8][2];
        #pragma unroll
        for (int i = 0; i < 8; i++) { sh[i][0] = 0u; sh[i][1] = 0u; }
        {
            const uint32_t kb = smem_u32(Ks[buf]);
            #pragma unroll
            for (int ks = 0; ks < 4; ks++) {
                const uint32_t sB = (uint32_t)(((ks * 2 + cB) ^ lsw) * 16);
                uint32_t bfm[4][4];
                #pragma unroll
                for (int nb2 = 0; nb2 < 4; nb2++)
                    LDSM4(bfm[nb2][0], bfm[nb2][1], bfm[nb2][2], bfm[nb2][3],
                          kb + (uint32_t)(nb2 * 16 + rB) * 128u + sB);
                #pragma unroll
                for (int nt = 0; nt < 8; nt++)
                    mma_hh(sh[nt], qa[ks], &bfm[nt >> 1][(nt & 1) * 2]);
            }
        }
        float s[8][4];
        #pragma unroll
        for (int nt = 0; nt < 8; nt++) {
            float2 v01 = __half22float2(*(__half2*)&sh[nt][0]);
            float2 v23 = __half22float2(*(__half2*)&sh[nt][1]);
            s[nt][0] = v01.x; s[nt][1] = v01.y;
            s[nt][2] = v23.x; s[nt][3] = v23.y;
        }

        /* exact phase penalty + online softmax */
        float tmax1 = -1e30f, tmax2 = -1e30f;
        #pragma unroll
        for (int nt = 0; nt < 8; nt++) {
            float k0 = pvs[nt * 8 + tq * 2];
            float k1 = pvs[nt * 8 + tq * 2 + 1];
            float u;
            u = pq1 - k0; s[nt][0] = s[nt][0] * 0.125f - rs * u * u;
            u = pq1 - k1; s[nt][1] = s[nt][1] * 0.125f - rs * u * u;
            u = pq2 - k0; s[nt][2] = s[nt][2] * 0.125f - rs * u * u;
            u = pq2 - k1; s[nt][3] = s[nt][3] * 0.125f - rs * u * u;
            tmax1 = fmaxf(tmax1, fmaxf(s[nt][0], s[nt][1]));
            tmax2 = fmaxf(tmax2, fmaxf(s[nt][2], s[nt][3]));
        }
        tmax1 = fmaxf(tmax1, __shfl_xor_sync(0xffffffffu, tmax1, 1));
        tmax1 = fmaxf(tmax1, __shfl_xor_sync(0xffffffffu, tmax1, 2));
        tmax2 = fmaxf(tmax2, __shfl_xor_sync(0xffffffffu, tmax2, 1));
        tmax2 = fmaxf(tmax2, __shfl_xor_sync(0xffffffffu, tmax2, 2));
        float mn1 = fmaxf(m1, tmax1), mn2 = fmaxf(m2, tmax2);
        float c1 = __expf(m1 - mn1), c2 = __expf(m2 - mn2);
        m1 = mn1; m2 = mn2;
        d1 *= c1; d2 *= c2;
        #pragma unroll
        for (int nt = 0; nt < 8; nt++) {
            o[nt][0] *= c1; o[nt][1] *= c1;
            o[nt][2] *= c2; o[nt][3] *= c2;
        }
        #pragma unroll
        for (int nt = 0; nt < 8; nt++) {
            float p0 = __expf(s[nt][0] - m1), p1 = __expf(s[nt][1] - m1);
            float p2 = __expf(s[nt][2] - m2), p3 = __expf(s[nt][3] - m2);
            d1 += p0 + p1; d2 += p2 + p3;
            int chunk = (nt ^ psw / 8) * 8;
            *(__half2*)(P1 + chunk) = __floats2half2_rn(p0, p1);
            *(__half2*)(P2 + chunk) = __floats2half2_rn(p2, p3);
        }
        __syncwarp();

        /* O += P @ V  (V [kv][d]; B fragment via trans-ldmatrix; fp32 accum) */
        {
            const uint32_t pb = smem_u32(Qs);
            const uint32_t vb = smem_u32(Vs[buf]);
            #pragma unroll
            for (int ks = 0; ks < 4; ks++) {
                uint32_t pa[4];
                LDSM4(pa[0], pa[1], pa[2], pa[3],
                      pb + (uint32_t)(wm + rA) * 128u + (uint32_t)(((ks * 2 + cA) ^ lsw) * 16));
                uint32_t vf[4][4];
                #pragma unroll
                for (int nb2 = 0; nb2 < 4; nb2++)
                    LDSM4T(vf[nb2][0], vf[nb2][1], vf[nb2][2], vf[nb2][3],
                           vb + (uint32_t)(ks * 16 + rA) * 128u
                              + (uint32_t)(((nb2 * 2 + cA) ^ lsw) * 16));
                #pragma unroll
                for (int nt = 0; nt < 8; nt++)
                    mma_h(o[nt], pa, &vf[nt >> 1][(nt & 1) * 2]);
            }
        }
        __syncthreads();
    }

    d1 += __shfl_xor_sync(0xffffffffu, d1, 1);
    d1 += __shfl_xor_sync(0xffffffffu, d1, 2);
    d2 += __shfl_xor_sync(0xffffffffu, d2, 1);
    d2 += __shfl_xor_sync(0xffffffffu, d2, 2);
    float i1 = 1.0f / d1, i2 = 1.0f / d2;
    __half* o1 = g_aoH + (size_t)(b * LSEQ + gr1) * DMODEL + h * DHEAD + tq * 2;
    __half* o2 = o1 + (size_t)8 * DMODEL;
    #pragma unroll
    for (int nt = 0; nt < 8; nt++) {
        *(__half2*)(o1 + nt * 8) = __floats2half2_rn(o[nt][0] * i1, o[nt][1] * i1);
        *(__half2*)(o2 + nt * 8) = __floats2half2_rn(o[nt][2] * i2, o[nt][3] * i2);
    }
}

/* ===== weight transpose + fp16 convert, 64x64 tiles, layer-batched (z) ===== */
__global__ void k_cvtT(const float* __restrict__ src, __half* __restrict__ dst,
                       int K, int N)
{
    __shared__ float t[64][65];
    size_t seg = (size_t)blockIdx.z * K * N;
    const float* s0 = src + seg;
    __half* d0 = dst + seg;
    int n0 = blockIdx.x * 64, k0 = blockIdx.y * 64;
    int tid = threadIdx.x;               /* 256 */
    {
        int kr = tid >> 2, c4 = tid & 3;
        const float* sp = s0 + (size_t)(k0 + kr) * N + n0;
        #pragma unroll
        for (int j = 0; j < 4; j++) {
            int col = (c4 + j * 4) * 4;
            float4 v = *(const float4*)(sp + col);
            t[kr][col + 0] = v.x; t[kr][col + 1] = v.y;
            t[kr][col + 2] = v.z; t[kr][col + 3] = v.w;
        }
    }
    __syncthreads();
    {
        int n = tid >> 2, kc = (tid & 3) * 16;
        __half2 h[8];
        #pragma unroll
        for (int j = 0; j < 8; j++)
            h[j] = __floats2half2_rn(t[kc + 2 * j][n], t[kc + 2 * j + 1][n]);
        __half* dp = d0 + (size_t)(n0 + n) * K + k0 + kc;
        *(uint4*)(dp + 0) = *(uint4*)&h[0];
        *(uint4*)(dp + 8) = *(uint4*)&h[4];
    }
}

/* ================= embed -> fp16 [VPAD][D] with zero pad ================= */
__global__ void k_cvtE(const float* __restrict__ src)
{
    size_t stride = (size_t)gridDim.x * blockDim.x;
    size_t tot8 = (size_t)VPAD * DMODEL / 8;
    for (size_t i = (size_t)blockIdx.x * blockDim.x + threadIdx.x; i < tot8; i += stride) {
        size_t e = i * 8;
        size_t row = e >> 10;
        __half2 h[4];
        if (row < VOCAB) {
            float4 v0 = *(const float4*)(src + e);
            float4 v1 = *(const float4*)(src + e + 4);
            h[0] = __floats2half2_rn(v0.x, v0.y);
            h[1] = __floats2half2_rn(v0.z, v0.w);
            h[2] = __floats2half2_rn(v1.x, v1.y);
            h[3] = __floats2half2_rn(v1.z, v1.w);
        } else {
            h[0] = h[1] = h[2] = h[3] = __float2half2_rn(0.f);
        }
        *(uint4*)(g_embH + e) = *(uint4*)h;
    }
}

/* ================= embedding + positional ================= */
__global__ void k_embed(const int* __restrict__ ids,
                        const float* __restrict__ emb,
                        const float* __restrict__ pos)
{
    int r = blockIdx.x;
    int l = r % LSEQ;
    int id = ids[r];
    const float4* e4 = (const float4*)(emb + (size_t)id * DMODEL);
    const float4* p4 = (const float4*)(pos + (size_t)l * DMODEL);
    float4* x4 = (float4*)(g_x + (size_t)r * DMODEL);
    for (int k = threadIdx.x; k < DMODEL / 4; k += blockDim.x) {
        float4 e = e4[k], p = p4[k];
        float4 o;
        o.x = e.x * 32.0f + p.x;
        o.y = e.y * 32.0f + p.y;
        o.z = e.z * 32.0f + p.z;
        o.w = e.w * 32.0f + p.w;
        x4[k] = o;
    }
}

/* ========== fused: R-grammar gate + xm + pre-norm1 + phase vector ========== */
__global__ void k_gate_ln_ph(const float* __restrict__ rg_w, const float* __restrict__ rg_b,
                             const float* __restrict__ n1g, const float* __restrict__ n1b,
                             const float* __restrict__ ph_w, const float* __restrict__ ph_b,
                             const float* __restrict__ ph_scale, int layer,
                             float* __restrict__ gs_out)
{
    int r = blockIdx.x, t = threadIdx.x;   /* 256 threads, 4 elems each */
    int w = t >> 5, lane = t & 31;
    __shared__ float gred[8][4];
    __shared__ float sred[8], qred[8];
    __shared__ float pred_[8][16];
    __shared__ float s_ms, s_mean, s_inv;

    float4 xv = ((const float4*)(g_x + (size_t)r * DMODEL))[t];

    const float4* w4 = (const float4*)(rg_w + (size_t)layer * DMODEL * 4);
    float4 wa = w4[t * 4 + 0], wb = w4[t * 4 + 1], wc = w4[t * 4 + 2], wd = w4[t * 4 + 3];
    float s0 = xv.x * wa.x + xv.y * wb.x + xv.z * wc.x + xv.w * wd.x;
    float s1 = xv.x * wa.y + xv.y * wb.y + xv.z * wc.y + xv.w * wd.y;
    float s2 = xv.x * wa.z + xv.y * wb.z + xv.z * wc.z + xv.w * wd.z;
    float s3 = xv.x * wa.w + xv.y * wb.w + xv.z * wc.w + xv.w * wd.w;
    #pragma unroll
    for (int o = 16; o > 0; o >>= 1) {
        s0 += __shfl_xor_sync(0xffffffffu, s0, o);
        s1 += __shfl_xor_sync(0xffffffffu, s1, o);
        s2 += __shfl_xor_sync(0xffffffffu, s2, o);
        s3 += __shfl_xor_sync(0xffffffffu, s3, o);
    }
    if (lane == 0) { gred[w][0] = s0; gred[w][1] = s1; gred[w][2] = s2; gred[w][3] = s3; }
    __syncthreads();
    if (t == 0) {
        float sum4 = 0.f;
        float* gsp = gs_out + ((size_t)layer * NROWS + r) * 4;
        #pragma unroll
        for (int n = 0; n < 4; n++) {
            float a = rg_b[layer * 4 + n];
            #pragma unroll
            for (int ww = 0; ww < 8; ww++) a += gred[ww][n];
            float sg = 1.0f / (1.0f + expf(-a));
            gsp[n] = sg;
            sum4 += sg;
        }
        s_ms = 1.0f + 0.1f * (sum4 * 0.25f);
    }
    __syncthreads();
    float ms = s_ms;
    float4 xm;
    xm.x = xv.x * ms; xm.y = xv.y * ms; xm.z = xv.z * ms; xm.w = xv.w * ms;
    ((float4*)(g_xm + (size_t)r * DMODEL))[t] = xm;

    float s = xm.x + xm.y + xm.z + xm.w;
    float q = xm.x * xm.x + xm.y * xm.y + xm.z * xm.z + xm.w * xm.w;
    #pragma unroll
    for (int o = 16; o > 0; o >>= 1) {
        s += __shfl_xor_sync(0xffffffffu, s, o);
        q += __shfl_xor_sync(0xffffffffu, q, o);
    }
    if (lane == 0) { sred[w] = s; qred[w] = q; }
    __syncthreads();
    if (t == 0) {
        float S = 0.f, Q = 0.f;
        #pragma unroll
        for (int i = 0; i < 8; i++) { S += sred[i]; Q += qred[i]; }
        float mean = S * (1.0f / DMODEL);
        float var = Q * (1.0f / DMODEL) - mean * mean;
        s_mean = mean;
        s_inv = rsqrtf(var + 1e-5f);
    }
    __syncthreads();
    float mean = s_mean, inv = s_inv;
    float4 gg = ((const float4*)n1g)[t];
    float4 bb = ((const float4*)n1b)[t];
    float a0 = (xm.x - mean) * inv * gg.x + bb.x;
    float a1 = (xm.y - mean) * inv * gg.y + bb.y;
    float a2 = (xm.z - mean) * inv * gg.z + bb.z;
    float a3 = (xm.w - mean) * inv * gg.w + bb.w;
    __half2* hp = (__half2*)(g_ainH + (size_t)r * DMODEL + t * 4);
    hp[0] = __floats2half2_rn(a0, a1);
    hp[1] = __floats2half2_rn(a2, a3);

    const float4* p4 = (const float4*)(ph_w + (size_t)layer * DMODEL * NHEAD);
    float acc[16];
    #pragma unroll
    for (int n = 0; n < 16; n++) acc[n] = 0.f;
    float av[4] = {a0, a1, a2, a3};
    #pragma unroll
    for (int e = 0; e < 4; e++) {
        float a = av[e];
        const float4* pr = p4 + (size_t)(t * 4 + e) * 4;
        float4 p0 = pr[0], p1 = pr[1], p2 = pr[2], p3 = pr[3];
        acc[0]  += a * p0.x; acc[1]  += a * p0.y; acc[2]  += a * p0.z; acc[3]  += a * p0.w;
        acc[4]  += a * p1.x; acc[5]  += a * p1.y; acc[6]  += a * p1.z; acc[7]  += a * p1.w;
        acc[8]  += a * p2.x; acc[9]  += a * p2.y; acc[10] += a * p2.z; acc[11] += a * p2.w;
        acc[12] += a * p3.x; acc[13] += a * p3.y; acc[14] += a * p3.z; acc[15] += a * p3.w;
    }
    #pragma unroll
    for (int n = 0; n < 16; n++) {
        #pragma unroll
        for (int o = 16; o > 0; o >>= 1)
            acc[n] += __shfl_xor_sync(0xffffffffu, acc[n], o);
    }
    if (lane == 0) {
        #pragma unroll
        for (int n = 0; n < 16; n++) pred_[w][n] = acc[n];
    }
    __syncthreads();
    if (t < 16) {
        float v = ph_b[layer * NHEAD + t];
        #pragma unroll
        for (int ww = 0; ww < 8; ww++) v += pred_[ww][t];
        g_pv[(size_t)r * NHEAD + t] = tanhf(ph_scale[layer] * v);
    }
}

/* ================= LayerNorm: fp16 main output + optional fp32 copy ======= */
__global__ void k_ln(const float* __restrict__ in,
                     const float* __restrict__ g,
                     const float* __restrict__ b,
                     __half* __restrict__ outh,
                     float* __restrict__ outf)
{
    int r = blockIdx.x, t = threadIdx.x;
    const float4* i4 = (const float4*)(in + (size_t)r * DMODEL);
    float4 v = i4[t];
    float s = v.x + v.y + v.z + v.w;
    float q = v.x * v.x + v.y * v.y + v.z * v.z + v.w * v.w;
    for (int o = 16; o > 0; o >>= 1) {
        s += __shfl_down_sync(0xffffffffu, s, o);
        q += __shfl_down_sync(0xffffffffu, q, o);
    }
    __shared__ float sr[8], qr[8];
    __shared__ float smean, sinv;
    if ((t & 31) == 0) { sr[t >> 5] = s; qr[t >> 5] = q; }
    __syncthreads();
    if (t == 0) {
        float S = 0.f, Q = 0.f;
        #pragma unroll
        for (int i = 0; i < 8; i++) { S += sr[i]; Q += qr[i]; }
        float mean = S * (1.0f / DMODEL);
        float var = Q * (1.0f / DMODEL) - mean * mean;
        smean = mean;
        sinv = rsqrtf(var + 1e-5f);
    }
    __syncthreads();
    float mean = smean, inv = sinv;
    float4 gg = ((const float4*)g)[t];
    float4 bb = ((const float4*)b)[t];
    float4 o;
    o.x = (v.x - mean) * inv * gg.x + bb.x;
    o.y = (v.y - mean) * inv * gg.y + bb.y;
    o.z = (v.z - mean) * inv * gg.z + bb.z;
    o.w = (v.w - mean) * inv * gg.w + bb.w;
    __half2* hp = (__half2*)(outh + (size_t)r * DMODEL + t * 4);
    hp[0] = __floats2half2_rn(o.x, o.y);
    hp[1] = __floats2half2_rn(o.z, o.w);
    if (outf)
        ((float4*)(outf + (size_t)r * DMODEL))[t] = o;
}

/* ================= boundary scalar ================= */
__global__ void k_bnd2(const float* __restrict__ w2,
                       const float* __restrict__ b2,
                       float* __restrict__ ss_out, int layer)
{
    int r = blockIdx.x, t = threadIdx.x;
    const float* hr = g_bndh + (size_t)r * HIDB;
    float s = 0.f;
    for (int k = t; k < HIDB; k += 128) s += hr[k] * w2[k];
    for (int o = 16; o > 0; o >>= 1) s += __shfl_down_sync(0xffffffffu, s, o);
    __shared__ float red[4];
    if ((t & 31) == 0) red[t >> 5] = s;
    __syncthreads();
    if (t == 0) {
        float v = red[0] + red[1] + red[2] + red[3] + b2[0];
        ss_out[(size_t)layer * NROWS + r] = 1.0f / (1.0f + expf(-v));
    }
}

/* ================= means over layers ================= */
__global__ void k_means(float* out)
{
    int idx = blockIdx.x * 256 + threadIdx.x;
    if (idx < NROWS * 4) {
        float s = 0.f;
        #pragma unroll
        for (int l = 0; l < NLAY; l++) s += out[OUT_GS + (size_t)l * NROWS * 4 + idx];
        out[OUT_GSM + idx] = s * (1.0f / NLAY);
    }
    int idx2 = idx - NROWS * 4;
    if (idx2 >= 0 && idx2 < NROWS) {
        float s = 0.f;
        #pragma unroll
        for (int l = 0; l < NLAY; l++) s += out[OUT_SS + (size_t)l * NROWS + idx2];
        out[OUT_SSM + idx2] = s * (1.0f / NLAY);
    }
}

/* ================= host ================= */
extern "C" void kernel_launch(void* const* d_in, const int* in_sizes, int n_in,
                              void* d_out, int out_size)
{
    const int*   ids      = (const int*)  d_in[0];
    const float* embed    = (const float*)d_in[1];
    const float* pos_enc  = (const float*)d_in[2];
    const float* rg_w     = (const float*)d_in[3];
    const float* rg_b     = (const float*)d_in[4];
    const float* qkv_w    = (const float*)d_in[5];
    const float* qkv_b    = (const float*)d_in[6];
    const float* out_w    = (const float*)d_in[7];
    const float* out_b    = (const float*)d_in[8];
    const float* ph_w     = (const float*)d_in[9];
    const float* ph_b     = (const float*)d_in[10];
    const float* resscale = (const float*)d_in[11];
    const float* ph_scale = (const float*)d_in[12];
    const float* ff1_w    = (const float*)d_in[13];
    const float* ff1_b    = (const float*)d_in[14];
    const float* ff2_w    = (const float*)d_in[15];
    const float* ff2_b    = (const float*)d_in[16];
    const float* n1_g     = (const float*)d_in[17];
    const float* n1_b     = (const float*)d_in[18];
    const float* n2_g     = (const float*)d_in[19];
    const float* n2_b     = (const float*)d_in[20];
    const float* bnd_w1   = (const float*)d_in[21];
    const float* bnd_b1   = (const float*)d_in[22];
    const float* bnd_w2   = (const float*)d_in[23];
    const float* bnd_b2   = (const float*)d_in[24];
    const float* fn_g     = (const float*)d_in[25];
    const float* fn_b     = (const float*)d_in[26];
    float* out = (float*)d_out;

    float *px, *pxm, *pbndh;
    __half *painH, *paoH, *pffhH, *pqkvH, *pwh, *pembH;
    cudaGetSymbolAddress((void**)&px,    g_x);
    cudaGetSymbolAddress((void**)&pxm,   g_xm);
    cudaGetSymbolAddress((void**)&pbndh, g_bndh);
    cudaGetSymbolAddress((void**)&painH, g_ainH);
    cudaGetSymbolAddress((void**)&paoH,  g_aoH);
    cudaGetSymbolAddress((void**)&pffhH, g_ffhH);
    cudaGetSymbolAddress((void**)&pqkvH, g_qkvH);
    cudaGetSymbolAddress((void**)&pwh,   g_wh);
    cudaGetSymbolAddress((void**)&pembH, g_embH);

    cudaFuncSetAttribute(k_hgemm, cudaFuncAttributeMaxDynamicSharedMemorySize, GEMM_SMEM);

    /* weight conversions, layer-batched over grid.z */
    dim3 tb(256);
    k_cvtT<<<dim3(3 * DMODEL / 64, DMODEL / 64, NLAY), tb>>>(qkv_w, pwh + W_QKV, DMODEL, 3 * DMODEL);
    k_cvtT<<<dim3(DMODEL / 64, DMODEL / 64, NLAY), tb>>>(out_w, pwh + W_OUT, DMODEL, DMODEL);
    k_cvtT<<<dim3(FFDIM / 64, DMODEL / 64, NLAY), tb>>>(ff1_w, pwh + W_FF1, DMODEL, FFDIM);
    k_cvtT<<<dim3(DMODEL / 64, FFDIM / 64, NLAY), tb>>>(ff2_w, pwh + W_FF2, FFDIM, DMODEL);
    k_cvtT<<<dim3(HIDB / 64, DMODEL / 64, 1), tb>>>(bnd_w1, pwh + W_BND, DMODEL, HIDB);
    k_cvtE<<<2048, 256>>>(embed);
    k_embed<<<NROWS, 256>>>(ids, embed, pos_enc);

    for (int i = 0; i < NLAY; i++) {
        k_gate_ln_ph<<<NROWS, 256>>>(rg_w, rg_b,
                                     n1_g + (size_t)i * DMODEL, n1_b + (size_t)i * DMODEL,
                                     ph_w, ph_b, ph_scale, i, out + OUT_GS);
        /* QKV projection -> fp16 qkv */
        {
            dim3 grid((3 * DMODEL) / 128, NROWS / 128);
            k_hgemm<<<grid, 256, GEMM_SMEM>>>(painH, pwh + W_QKV + (size_t)i * 3 * DMODEL * DMODEL,
                                              qkv_b + (size_t)i * 3 * DMODEL, (const float*)0,
                                              (float*)0, pqkvH, NROWS, 3 * DMODEL, DMODEL, 0);
        }
        {
            dim3 grid(LSEQ / 64, NHEAD, NB);
            k_attn<<<grid, 128>>>(resscale, i);
        }
        /* out projection + residual (xm) -> px fp32 */
        {
            dim3 grid(DMODEL / 128, NROWS / 128);
            k_hgemm<<<grid, 256, GEMM_SMEM>>>(paoH, pwh + W_OUT + (size_t)i * DMODEL * DMODEL,
                                              out_b + (size_t)i * DMODEL, pxm,
                                              px, (__half*)0, NROWS, DMODEL, DMODEL, 0);
        }
        k_ln<<<NROWS, 256>>>(px, n2_g + (size_t)i * DMODEL, n2_b + (size_t)i * DMODEL,
                             painH, (float*)0);
        /* FF1 + GELU -> fp16 hidden */
        {
            dim3 grid(FFDIM / 128, NROWS / 128);
            k_hgemm<<<grid, 256, GEMM_SMEM>>>(painH, pwh + W_FF1 + (size_t)i * DMODEL * FFDIM,
                                              ff1_b + (size_t)i * FFDIM, (const float*)0,
                                              (float*)0, pffhH, NROWS, FFDIM, DMODEL, 1);
        }
        /* FF2 + residual -> px fp32 AND fp16 copy for boundary */
        {
            dim3 grid(DMODEL / 128, NROWS / 128);
            k_hgemm<<<grid, 256, GEMM_SMEM>>>(pffhH, pwh + W_FF2 + (size_t)i * FFDIM * DMODEL,
                                              ff2_b + (size_t)i * DMODEL, px,
                                              px, painH, NROWS, DMODEL, FFDIM, 0);
        }
        /* boundary MLP layer 1 (tanh) -> fp32 hidden */
        {
            dim3 grid(HIDB / 128, NROWS / 128);
            k_hgemm<<<grid, 256, GEMM_SMEM>>>(painH, pwh + W_BND, bnd_b1, (const float*)0,
                                              pbndh, (__half*)0, NROWS, HIDB, DMODEL, 2);
        }
        k_bnd2<<<NROWS, 128>>>(bnd_w2, bnd_b2, out + OUT_SS, i);
    }

    /* final LN -> fp32 x output + fp16 copy for logits A */
    k_ln<<<NROWS, 256>>>(px, fn_g, fn_b, painH, out + OUT_X);

    {
        dim3 grid(VPAD / 128, NROWS / 128);
        k_hgemm<<<grid, 256, GEMM_SMEM>>>(painH, pembH, (const float*)0, (const float*)0,
                                          out + OUT_LOGITS, (__half*)0, NROWS, VOCAB, DMODEL, 0);
    }

    k_means<<<(NROWS * 4 + NROWS + 255) / 256, 256>>>(out);
}

// round 15
// speedup vs baseline: 1.0445x; 1.0015x over previous
#include <cuda_runtime.h>
#include <cuda_fp16.h>
#include <math.h>
#include <stdint.h>

#define NB      2
#define LSEQ    1024
#define DMODEL  1024
#define NHEAD   16
#define DHEAD   64
#define NLAY    6
#define VOCAB   30000
#define VPAD    30080
#define HIDB    512
#define FFDIM   4096
#define NROWS   2048   /* NB*LSEQ */

/* ---- output layout (flattened tuple, in reference return order) ---- */
static const size_t OUT_LOGITS = 0;
static const size_t OUT_X   = (size_t)NROWS * VOCAB;
static const size_t OUT_GSM = OUT_X   + (size_t)NROWS * DMODEL;
static const size_t OUT_SSM = OUT_GSM + (size_t)NROWS * 4;
static const size_t OUT_GS  = OUT_SSM + (size_t)NROWS;
static const size_t OUT_SS  = OUT_GS  + (size_t)NLAY * NROWS * 4;

/* ---- transposed fp16 weight scratch layout (elements) ---- */
#define W_QKV 0UL
#define W_OUT (W_QKV + (size_t)NLAY * DMODEL * 3 * DMODEL)
#define W_FF1 (W_OUT + (size_t)NLAY * DMODEL * DMODEL)
#define W_FF2 (W_FF1 + (size_t)NLAY * DMODEL * FFDIM)
#define W_BND (W_FF2 + (size_t)NLAY * FFDIM * DMODEL)
#define W_TOT (W_BND + (size_t)DMODEL * HIDB)

/* ---- scratch ---- */
__device__ float g_x  [NROWS * DMODEL];
__device__ float g_xm [NROWS * DMODEL];
__device__ float g_pv [NROWS * NHEAD];
__device__ float g_bndh[NROWS * HIDB];
__device__ __align__(16) __half g_ainH[NROWS * DMODEL];
__device__ __align__(16) __half g_aoH [NROWS * DMODEL];
__device__ __align__(16) __half g_ffhH[NROWS * FFDIM];
__device__ __align__(16) __half g_qkvH[NROWS * 3 * DMODEL];
__device__ __align__(16) __half g_wh  [W_TOT];
__device__ __align__(16) __half g_embH[(size_t)VPAD * DMODEL];

/* ================= low-level helpers (compute_103-safe) ================= */
__device__ __forceinline__ uint32_t smem_u32(const void* p) {
    uint32_t a;
    asm("{ .reg .u64 t; cvta.to.shared.u64 t, %1; cvt.u32.u64 %0, t; }" : "=r"(a) : "l"(p));
    return a;
}
__device__ __forceinline__ void cp16(void* s, const void* g) {
    asm volatile("cp.async.cg.shared.global [%0], [%1], 16;"
                 :: "r"(smem_u32(s)), "l"(g) : "memory");
}
#define CP_COMMIT() asm volatile("cp.async.commit_group;" ::: "memory")
#define CP_WAIT1()  asm volatile("cp.async.wait_group 1;" ::: "memory")
#define CP_WAIT0()  asm volatile("cp.async.wait_group 0;" ::: "memory")

#define LDSM4(r0, r1, r2, r3, addr) \
    asm volatile("ldmatrix.sync.aligned.m8n8.x4.shared.b16 {%0,%1,%2,%3}, [%4];" \
                 : "=r"(r0), "=r"(r1), "=r"(r2), "=r"(r3) : "r"(addr))

#define LDSM4T(r0, r1, r2, r3, addr) \
    asm volatile("ldmatrix.sync.aligned.m8n8.x4.trans.shared.b16 {%0,%1,%2,%3}, [%4];" \
                 : "=r"(r0), "=r"(r1), "=r"(r2), "=r"(r3) : "r"(addr))

__device__ __forceinline__ void mma_h(float* c, const uint32_t* a, const uint32_t* b) {
    asm volatile(
        "mma.sync.aligned.m16n8k16.row.col.f32.f16.f16.f32 "
        "{%0,%1,%2,%3}, {%4,%5,%6,%7}, {%8,%9}, {%0,%1,%2,%3};"
        : "+f"(c[0]), "+f"(c[1]), "+f"(c[2]), "+f"(c[3])
        : "r"(a[0]), "r"(a[1]), "r"(a[2]), "r"(a[3]), "r"(b[0]), "r"(b[1]));
}
/* fp16-accumulate variant (double rate); C = 2 regs of half2 */
__device__ __forceinline__ void mma_hh(uint32_t* c, const uint32_t* a, const uint32_t* b) {
    asm volatile(
        "mma.sync.aligned.m16n8k16.row.col.f16.f16.f16.f16 "
        "{%0,%1}, {%2,%3,%4,%5}, {%6,%7}, {%0,%1};"
        : "+r"(c[0]), "+r"(c[1])
        : "r"(a[0]), "r"(a[1]), "r"(a[2]), "r"(a[3]), "r"(b[0]), "r"(b[1]));
}
__device__ __forceinline__ uint32_t packh2(float a, float b) {
    __half2 h = __floats2half2_rn(a, b);
    return *(uint32_t*)&h;
}

/* ================= fp16 mma GEMM (round-11 verified, 2-stage) =============
   C[M,N](f32) / C2[M,N](fp16) = act(A[M,K] @ Bt[N,K]^T + bias) (+resid) */
#define GEMM_SMEM 65536

__global__ __launch_bounds__(256, 2)
void k_hgemm(const __half* __restrict__ A, const __half* __restrict__ Bm,
             const float* __restrict__ bias, const float* __restrict__ resid,
             float* __restrict__ C, __half* __restrict__ C2,
             int M, int N, int K, int act)
{
    extern __shared__ __half hs[];
    __half* As = hs;              /* 2 stages x 8192 halves */
    __half* Bs = hs + 16384;

    const int tid  = threadIdx.x;
    const int wid  = tid >> 5;
    const int lane = tid & 31;
    const int m0 = blockIdx.y * 128;
    const int n0 = blockIdx.x * 128;
    const int wm = (wid & 1) * 64;
    const int wn = (wid >> 1) * 32;
    const int nch = K >> 6;

    const int st_row = tid >> 3;
    const uint32_t st_sw = (uint32_t)(((tid & 7) ^ (st_row & 7)) * 8);
    const __half* aglob = A + (size_t)(m0 + st_row) * K + (tid & 7) * 8;
    const __half* bglob = Bm + (size_t)(n0 + st_row) * K + (tid & 7) * 8;

#define HSTAGE(ch, s) do {                                                      \
    __half* as_ = As + (s) * 8192;                                              \
    __half* bs_ = Bs + (s) * 8192;                                              \
    const __half* ap = aglob + (ch) * 64;                                       \
    const __half* bp = bglob + (ch) * 64;                                       \
    _Pragma("unroll")                                                           \
    for (int it = 0; it < 4; it++) {                                            \
        cp16(as_ + (st_row + it * 32) * 64 + st_sw, ap + (size_t)(it * 32) * K);\
        cp16(bs_ + (st_row + it * 32) * 64 + st_sw, bp + (size_t)(it * 32) * K);\
    }                                                                           \
} while (0)

    const int lsw = lane & 7;
    const int rA  = (lane & 7) + (lane & 8);
    const int rB  = (lane & 7) + ((lane & 16) >> 1);
    const int cA  = (lane >> 4) & 1;
    const int cB  = (lane >> 3) & 1;

    float cf[4][4][4];
    #pragma unroll
    for (int i = 0; i < 4; i++)
        #pragma unroll
        for (int j = 0; j < 4; j++)
            { cf[i][j][0] = 0.f; cf[i][j][1] = 0.f; cf[i][j][2] = 0.f; cf[i][j][3] = 0.f; }

    HSTAGE(0, 0);
    CP_COMMIT();

    for (int c = 0; c < nch; c++) {
        if (c + 1 < nch) { HSTAGE(c + 1, (c + 1) & 1); CP_COMMIT(); CP_WAIT1(); }
        else             { CP_WAIT0(); }
        __syncthreads();

        const uint32_t ab = smem_u32(As + (c & 1) * 8192);
        const uint32_t bb = smem_u32(Bs + (c & 1) * 8192);

        #pragma unroll
        for (int kk = 0; kk < 4; kk++) {
            const uint32_t sA = (uint32_t)(((kk * 2 + cA) ^ lsw) * 16);
            const uint32_t sB = (uint32_t)(((kk * 2 + cB) ^ lsw) * 16);
            uint32_t af[4][4], bf[2][4];
            #pragma unroll
            for (int mt = 0; mt < 4; mt++)
                LDSM4(af[mt][0], af[mt][1], af[mt][2], af[mt][3],
                      ab + (uint32_t)(wm + mt * 16 + rA) * 128u + sA);
            #pragma unroll
            for (int p = 0; p < 2; p++)
                LDSM4(bf[p][0], bf[p][1], bf[p][2], bf[p][3],
                      bb + (uint32_t)(wn + p * 16 + rB) * 128u + sB);
            #pragma unroll
            for (int mt = 0; mt < 4; mt++)
                #pragma unroll
                for (int nt = 0; nt < 4; nt++)
                    mma_h(cf[mt][nt], af[mt], &bf[nt >> 1][(nt & 1) * 2]);
        }
        __syncthreads();
    }
#undef HSTAGE

    #pragma unroll
    for (int mt = 0; mt < 4; mt++) {
        int row = m0 + wm + mt * 16 + (lane >> 2);
        #pragma unroll
        for (int nt = 0; nt < 4; nt++) {
            int col = n0 + wn + nt * 8 + (lane & 3) * 2;
            if (col < N) {
                #pragma unroll
                for (int hh = 0; hh < 2; hh++) {
                    int r = row + hh * 8;
                    float v0 = cf[mt][nt][hh * 2 + 0];
                    float v1 = cf[mt][nt][hh * 2 + 1];
                    if (bias) { v0 += bias[col]; v1 += bias[col + 1]; }
                    if (act == 1) {
                        v0 = 0.5f * v0 * (1.0f + erff(v0 * 0.70710678118654752f));
                        v1 = 0.5f * v1 * (1.0f + erff(v1 * 0.70710678118654752f));
                    } else if (act == 2) {
                        v0 = tanhf(v0); v1 = tanhf(v1);
                    }
                    if (resid) {
                        v0 += resid[(size_t)r * N + col];
                        v1 += resid[(size_t)r * N + col + 1];
                    }
                    if (C)  *(float2*)(C + (size_t)r * N + col) = make_float2(v0, v1);
                    if (C2) *(__half2*)(C2 + (size_t)r * N + col) = __floats2half2_rn(v0, v1);
                }
            }
        }
    }
}

/* == tensor-core fused attention; S fp16-acc; P register repack; O per-tile fp16-acc == */
__global__ __launch_bounds__(128)
void k_attn(const float* __restrict__ res_scale, int layer)
{
    const int b = blockIdx.z, h = blockIdx.y, q0 = blockIdx.x * 64;
    const int tid = threadIdx.x, wid = tid >> 5, lane = tid & 31;
    const float rs = res_scale[layer];

    __shared__ __half Qs[64 * 64];
    __shared__ __half Ks[2][64 * 64];
    __shared__ __half Vs[2][64 * 64];       /* [kv][d], same layout as Ks */
    __shared__ float pvs[64];

    const int srow = tid >> 3;
    const int sc   = tid & 7;
    const uint32_t sdst = (uint32_t)((sc ^ (srow & 7)) * 8);

    /* stage Q (rows q0+) and KV tile 0 (rows 0+) */
    {
        const __half* qg = g_qkvH + (size_t)(b * LSEQ + q0 + srow) * 3 * DMODEL + h * DHEAD + sc * 8;
        const __half* kg = g_qkvH + (size_t)(b * LSEQ + srow) * 3 * DMODEL + DMODEL + h * DHEAD + sc * 8;
        #pragma unroll
        for (int it = 0; it < 4; it++) {
            size_t off = (size_t)(it * 16) * 3 * DMODEL;
            cp16(Qs + (srow + it * 16) * 64 + sdst, qg + off);
            cp16(Ks[0] + (srow + it * 16) * 64 + sdst, kg + off);
            cp16(Vs[0] + (srow + it * 16) * 64 + sdst, kg + DMODEL + off);
        }
    }
    CP_COMMIT();

    const int lsw = lane & 7;
    const int rA  = (lane & 7) + (lane & 8);
    const int rB  = (lane & 7) + ((lane & 16) >> 1);
    const int cA  = (lane >> 4) & 1;
    const int cB  = (lane >> 3) & 1;
    const int wm  = wid * 16;
    const int g   = lane >> 2;
    const int tq  = lane & 3;

    const int gr1 = q0 + wm + g;
    const float pq1 = g_pv[(size_t)(b * LSEQ + gr1) * NHEAD + h];
    const float pq2 = g_pv[(size_t)(b * LSEQ + gr1 + 8) * NHEAD + h];

    float o[8][4];
    #pragma unroll
    for (int i = 0; i < 8; i++)
        { o[i][0] = 0.f; o[i][1] = 0.f; o[i][2] = 0.f; o[i][3] = 0.f; }
    float m1 = -1e30f, m2 = -1e30f, d1 = 0.f, d2 = 0.f;
    uint32_t qa[4][4];

    for (int j = 0; j < LSEQ / 64; j++) {
        const int buf = j & 1;
        if (j + 1 < LSEQ / 64) {
            const int nbuf = buf ^ 1;
            const int kv1 = (j + 1) * 64;
            const __half* kg = g_qkvH + (size_t)(b * LSEQ + kv1 + srow) * 3 * DMODEL
                               + DMODEL + h * DHEAD + sc * 8;
            #pragma unroll
            for (int it = 0; it < 4; it++) {
                size_t off = (size_t)(it * 16) * 3 * DMODEL;
                cp16(Ks[nbuf] + (srow + it * 16) * 64 + sdst, kg + off);
                cp16(Vs[nbuf] + (srow + it * 16) * 64 + sdst, kg + DMODEL + off);
            }
            CP_COMMIT();
            CP_WAIT1();
        } else {
            CP_WAIT0();
        }
        if (tid < 64)
            pvs[tid] = g_pv[(size_t)(b * LSEQ + j * 64 + tid) * NHEAD + h];
        __syncthreads();

        if (j == 0) {
            const uint32_t qb = smem_u32(Qs);
            #pragma unroll
            for (int ks = 0; ks < 4; ks++)
                LDSM4(qa[ks][0], qa[ks][1], qa[ks][2], qa[ks][3],
                      qb + (uint32_t)(wm + rA) * 128u + (uint32_t)(((ks * 2 + cA) ^ lsw) * 16));
        }

        /* S = Q K^T  (fp16 accumulate; fresh per tile) */
        uint32_t sh[8][2];
        #pragma unroll
        for (int i = 0; i < 8; i++) { sh[i][0] = 0u; sh[i][1] = 0u; }
        {
            const uint32_t kb = smem_u32(Ks[buf]);
            #pragma unroll
            for (int ks = 0; ks < 4; ks++) {
                const uint32_t sB = (uint32_t)(((ks * 2 + cB) ^ lsw) * 16);
                uint32_t bfm[4][4];
                #pragma unroll
                for (int nb2 = 0; nb2 < 4; nb2++)
                    LDSM4(bfm[nb2][0], bfm[nb2][1], bfm[nb2][2], bfm[nb2][3],
                          kb + (uint32_t)(nb2 * 16 + rB) * 128u + sB);
                #pragma unroll
                for (int nt = 0; nt < 8; nt++)
                    mma_hh(sh[nt], qa[ks], &bfm[nt >> 1][(nt & 1) * 2]);
            }
        }
        float s[8][4];
        #pragma unroll
        for (int nt = 0; nt < 8; nt++) {
            float2 v01 = __half22float2(*(__half2*)&sh[nt][0]);
            float2 v23 = __half22float2(*(__half2*)&sh[nt][1]);
            s[nt][0] = v01.x; s[nt][1] = v01.y;
            s[nt][2] = v23.x; s[nt][3] = v23.y;
        }

        /* exact phase penalty + online softmax */
        float tmax1 = -1e30f, tmax2 = -1e30f;
        #pragma unroll
        for (int nt = 0; nt < 8; nt++) {
            float k0 = pvs[nt * 8 + tq * 2];
            float k1 = pvs[nt * 8 + tq * 2 + 1];
            float u;
            u = pq1 - k0; s[nt][0] = s[nt][0] * 0.125f - rs * u * u;
            u = pq1 - k1; s[nt][1] = s[nt][1] * 0.125f - rs * u * u;
            u = pq2 - k0; s[nt][2] = s[nt][2] * 0.125f - rs * u * u;
            u = pq2 - k1; s[nt][3] = s[nt][3] * 0.125f - rs * u * u;
            tmax1 = fmaxf(tmax1, fmaxf(s[nt][0], s[nt][1]));
            tmax2 = fmaxf(tmax2, fmaxf(s[nt][2], s[nt][3]));
        }
        tmax1 = fmaxf(tmax1, __shfl_xor_sync(0xffffffffu, tmax1, 1));
        tmax1 = fmaxf(tmax1, __shfl_xor_sync(0xffffffffu, tmax1, 2));
        tmax2 = fmaxf(tmax2, __shfl_xor_sync(0xffffffffu, tmax2, 1));
        tmax2 = fmaxf(tmax2, __shfl_xor_sync(0xffffffffu, tmax2, 2));
        float mn1 = fmaxf(m1, tmax1), mn2 = fmaxf(m2, tmax2);
        float c1 = __expf(m1 - mn1), c2 = __expf(m2 - mn2);
        m1 = mn1; m2 = mn2;
        d1 *= c1; d2 *= c2;
        #pragma unroll
        for (int nt = 0; nt < 8; nt++) {
            o[nt][0] *= c1; o[nt][1] *= c1;
            o[nt][2] *= c2; o[nt][3] *= c2;
        }
        /* P -> fp16 A-fragments by direct register repack:
           pa[ks][0]= rows g   cols 16ks+2tq.. ; [1]= rows g+8 ; [2],[3]= +8 cols */
        uint32_t pa[4][4];
        #pragma unroll
        for (int nt = 0; nt < 8; nt++) {
            float p0 = __expf(s[nt][0] - m1), p1 = __expf(s[nt][1] - m1);
            float p2 = __expf(s[nt][2] - m2), p3 = __expf(s[nt][3] - m2);
            d1 += p0 + p1; d2 += p2 + p3;
            pa[nt >> 1][(nt & 1) * 2 + 0] = packh2(p0, p1);
            pa[nt >> 1][(nt & 1) * 2 + 1] = packh2(p2, p3);
        }

        /* O-tile = P @ V in fp16 accum, promoted once per tile into fp32 o */
        uint32_t oh[8][2];
        #pragma unroll
        for (int i = 0; i < 8; i++) { oh[i][0] = 0u; oh[i][1] = 0u; }
        {
            const uint32_t vb = smem_u32(Vs[buf]);
            #pragma unroll
            for (int ks = 0; ks < 4; ks++) {
                uint32_t vf[4][4];
                #pragma unroll
                for (int nb2 = 0; nb2 < 4; nb2++)
                    LDSM4T(vf[nb2][0], vf[nb2][1], vf[nb2][2], vf[nb2][3],
                           vb + (uint32_t)(ks * 16 + rA) * 128u
                              + (uint32_t)(((nb2 * 2 + cA) ^ lsw) * 16));
                #pragma unroll
                for (int nt = 0; nt < 8; nt++)
                    mma_hh(oh[nt], pa[ks], &vf[nt >> 1][(nt & 1) * 2]);
            }
        }
        #pragma unroll
        for (int nt = 0; nt < 8; nt++) {
            float2 v01 = __half22float2(*(__half2*)&oh[nt][0]);
            float2 v23 = __half22float2(*(__half2*)&oh[nt][1]);
            o[nt][0] += v01.x; o[nt][1] += v01.y;
            o[nt][2] += v23.x; o[nt][3] += v23.y;
        }
        __syncthreads();
    }

    d1 += __shfl_xor_sync(0xffffffffu, d1, 1);
    d1 += __shfl_xor_sync(0xffffffffu, d1, 2);
    d2 += __shfl_xor_sync(0xffffffffu, d2, 1);
    d2 += __shfl_xor_sync(0xffffffffu, d2, 2);
    float i1 = 1.0f / d1, i2 = 1.0f / d2;
    __half* o1 = g_aoH + (size_t)(b * LSEQ + gr1) * DMODEL + h * DHEAD + tq * 2;
    __half* o2 = o1 + (size_t)8 * DMODEL;
    #pragma unroll
    for (int nt = 0; nt < 8; nt++) {
        *(__half2*)(o1 + nt * 8) = __floats2half2_rn(o[nt][0] * i1, o[nt][1] * i1);
        *(__half2*)(o2 + nt * 8) = __floats2half2_rn(o[nt][2] * i2, o[nt][3] * i2);
    }
}

/* ===== weight transpose + fp16 convert, 64x64 tiles, layer-batched (z) ===== */
__global__ void k_cvtT(const float* __restrict__ src, __half* __restrict__ dst,
                       int K, int N)
{
    __shared__ float t[64][65];
    size_t seg = (size_t)blockIdx.z * K * N;
    const float* s0 = src + seg;
    __half* d0 = dst + seg;
    int n0 = blockIdx.x * 64, k0 = blockIdx.y * 64;
    int tid = threadIdx.x;               /* 256 */
    {
        int kr = tid >> 2, c4 = tid & 3;
        const float* sp = s0 + (size_t)(k0 + kr) * N + n0;
        #pragma unroll
        for (int j = 0; j < 4; j++) {
            int col = (c4 + j * 4) * 4;
            float4 v = *(const float4*)(sp + col);
            t[kr][col + 0] = v.x; t[kr][col + 1] = v.y;
            t[kr][col + 2] = v.z; t[kr][col + 3] = v.w;
        }
    }
    __syncthreads();
    {
        int n = tid >> 2, kc = (tid & 3) * 16;
        __half2 h[8];
        #pragma unroll
        for (int j = 0; j < 8; j++)
            h[j] = __floats2half2_rn(t[kc + 2 * j][n], t[kc + 2 * j + 1][n]);
        __half* dp = d0 + (size_t)(n0 + n) * K + k0 + kc;
        *(uint4*)(dp + 0) = *(uint4*)&h[0];
        *(uint4*)(dp + 8) = *(uint4*)&h[4];
    }
}

/* ================= embed -> fp16 [VPAD][D] with zero pad ================= */
__global__ void k_cvtE(const float* __restrict__ src)
{
    size_t stride = (size_t)gridDim.x * blockDim.x;
    size_t tot8 = (size_t)VPAD * DMODEL / 8;
    for (size_t i = (size_t)blockIdx.x * blockDim.x + threadIdx.x; i < tot8; i += stride) {
        size_t e = i * 8;
        size_t row = e >> 10;
        __half2 h[4];
        if (row < VOCAB) {
            float4 v0 = *(const float4*)(src + e);
            float4 v1 = *(const float4*)(src + e + 4);
            h[0] = __floats2half2_rn(v0.x, v0.y);
            h[1] = __floats2half2_rn(v0.z, v0.w);
            h[2] = __floats2half2_rn(v1.x, v1.y);
            h[3] = __floats2half2_rn(v1.z, v1.w);
        } else {
            h[0] = h[1] = h[2] = h[3] = __float2half2_rn(0.f);
        }
        *(uint4*)(g_embH + e) = *(uint4*)h;
    }
}

/* ================= embedding + positional ================= */
__global__ void k_embed(const int* __restrict__ ids,
                        const float* __restrict__ emb,
                        const float* __restrict__ pos)
{
    int r = blockIdx.x;
    int l = r % LSEQ;
    int id = ids[r];
    const float4* e4 = (const float4*)(emb + (size_t)id * DMODEL);
    const float4* p4 = (const float4*)(pos + (size_t)l * DMODEL);
    float4* x4 = (float4*)(g_x + (size_t)r * DMODEL);
    for (int k = threadIdx.x; k < DMODEL / 4; k += blockDim.x) {
        float4 e = e4[k], p = p4[k];
        float4 o;
        o.x = e.x * 32.0f + p.x;
        o.y = e.y * 32.0f + p.y;
        o.z = e.z * 32.0f + p.z;
        o.w = e.w * 32.0f + p.w;
        x4[k] = o;
    }
}

/* ========== fused: R-grammar gate + xm + pre-norm1 + phase vector ========== */
__global__ void k_gate_ln_ph(const float* __restrict__ rg_w, const float* __restrict__ rg_b,
                             const float* __restrict__ n1g, const float* __restrict__ n1b,
                             const float* __restrict__ ph_w, const float* __restrict__ ph_b,
                             const float* __restrict__ ph_scale, int layer,
                             float* __restrict__ gs_out)
{
    int r = blockIdx.x, t = threadIdx.x;   /* 256 threads, 4 elems each */
    int w = t >> 5, lane = t & 31;
    __shared__ float gred[8][4];
    __shared__ float sred[8], qred[8];
    __shared__ float pred_[8][16];
    __shared__ float s_ms, s_mean, s_inv;

    float4 xv = ((const float4*)(g_x + (size_t)r * DMODEL))[t];

    const float4* w4 = (const float4*)(rg_w + (size_t)layer * DMODEL * 4);
    float4 wa = w4[t * 4 + 0], wb = w4[t * 4 + 1], wc = w4[t * 4 + 2], wd = w4[t * 4 + 3];
    float s0 = xv.x * wa.x + xv.y * wb.x + xv.z * wc.x + xv.w * wd.x;
    float s1 = xv.x * wa.y + xv.y * wb.y + xv.z * wc.y + xv.w * wd.y;
    float s2 = xv.x * wa.z + xv.y * wb.z + xv.z * wc.z + xv.w * wd.z;
    float s3 = xv.x * wa.w + xv.y * wb.w + xv.z * wc.w + xv.w * wd.w;
    #pragma unroll
    for (int o = 16; o > 0; o >>= 1) {
        s0 += __shfl_xor_sync(0xffffffffu, s0, o);
        s1 += __shfl_xor_sync(0xffffffffu, s1, o);
        s2 += __shfl_xor_sync(0xffffffffu, s2, o);
        s3 += __shfl_xor_sync(0xffffffffu, s3, o);
    }
    if (lane == 0) { gred[w][0] = s0; gred[w][1] = s1; gred[w][2] = s2; gred[w][3] = s3; }
    __syncthreads();
    if (t == 0) {
        float sum4 = 0.f;
        float* gsp = gs_out + ((size_t)layer * NROWS + r) * 4;
        #pragma unroll
        for (int n = 0; n < 4; n++) {
            float a = rg_b[layer * 4 + n];
            #pragma unroll
            for (int ww = 0; ww < 8; ww++) a += gred[ww][n];
            float sg = 1.0f / (1.0f + expf(-a));
            gsp[n] = sg;
            sum4 += sg;
        }
        s_ms = 1.0f + 0.1f * (sum4 * 0.25f);
    }
    __syncthreads();
    float ms = s_ms;
    float4 xm;
    xm.x = xv.x * ms; xm.y = xv.y * ms; xm.z = xv.z * ms; xm.w = xv.w * ms;
    ((float4*)(g_xm + (size_t)r * DMODEL))[t] = xm;

    float s = xm.x + xm.y + xm.z + xm.w;
    float q = xm.x * xm.x + xm.y * xm.y + xm.z * xm.z + xm.w * xm.w;
    #pragma unroll
    for (int o = 16; o > 0; o >>= 1) {
        s += __shfl_xor_sync(0xffffffffu, s, o);
        q += __shfl_xor_sync(0xffffffffu, q, o);
    }
    if (lane == 0) { sred[w] = s; qred[w] = q; }
    __syncthreads();
    if (t == 0) {
        float S = 0.f, Q = 0.f;
        #pragma unroll
        for (int i = 0; i < 8; i++) { S += sred[i]; Q += qred[i]; }
        float mean = S * (1.0f / DMODEL);
        float var = Q * (1.0f / DMODEL) - mean * mean;
        s_mean = mean;
        s_inv = rsqrtf(var + 1e-5f);
    }
    __syncthreads();
    float mean = s_mean, inv = s_inv;
    float4 gg = ((const float4*)n1g)[t];
    float4 bb = ((const float4*)n1b)[t];
    float a0 = (xm.x - mean) * inv * gg.x + bb.x;
    float a1 = (xm.y - mean) * inv * gg.y + bb.y;
    float a2 = (xm.z - mean) * inv * gg.z + bb.z;
    float a3 = (xm.w - mean) * inv * gg.w + bb.w;
    __half2* hp = (__half2*)(g_ainH + (size_t)r * DMODEL + t * 4);
    hp[0] = __floats2half2_rn(a0, a1);
    hp[1] = __floats2half2_rn(a2, a3);

    const float4* p4 = (const float4*)(ph_w + (size_t)layer * DMODEL * NHEAD);
    float acc[16];
    #pragma unroll
    for (int n = 0; n < 16; n++) acc[n] = 0.f;
    float av[4] = {a0, a1, a2, a3};
    #pragma unroll
    for (int e = 0; e < 4; e++) {
        float a = av[e];
        const float4* pr = p4 + (size_t)(t * 4 + e) * 4;
        float4 p0 = pr[0], p1 = pr[1], p2 = pr[2], p3 = pr[3];
        acc[0]  += a * p0.x; acc[1]  += a * p0.y; acc[2]  += a * p0.z; acc[3]  += a * p0.w;
        acc[4]  += a * p1.x; acc[5]  += a * p1.y; acc[6]  += a * p1.z; acc[7]  += a * p1.w;
        acc[8]  += a * p2.x; acc[9]  += a * p2.y; acc[10] += a * p2.z; acc[11] += a * p2.w;
        acc[12] += a * p3.x; acc[13] += a * p3.y; acc[14] += a * p3.z; acc[15] += a * p3.w;
    }
    #pragma unroll
    for (int n = 0; n < 16; n++) {
        #pragma unroll
        for (int o = 16; o > 0; o >>= 1)
            acc[n] += __shfl_xor_sync(0xffffffffu, acc[n], o);
    }
    if (lane == 0) {
        #pragma unroll
        for (int n = 0; n < 16; n++) pred_[w][n] = acc[n];
    }
    __syncthreads();
    if (t < 16) {
        float v = ph_b[layer * NHEAD + t];
        #pragma unroll
        for (int ww = 0; ww < 8; ww++) v += pred_[ww][t];
        g_pv[(size_t)r * NHEAD + t] = tanhf(ph_scale[layer] * v);
    }
}

/* ================= LayerNorm: fp16 main output + optional fp32 copy ======= */
__global__ void k_ln(const float* __restrict__ in,
                     const float* __restrict__ g,
                     const float* __restrict__ b,
                     __half* __restrict__ outh,
                     float* __restrict__ outf)
{
    int r = blockIdx.x, t = threadIdx.x;
    const float4* i4 = (const float4*)(in + (size_t)r * DMODEL);
    float4 v = i4[t];
    float s = v.x + v.y + v.z + v.w;
    float q = v.x * v.x + v.y * v.y + v.z * v.z + v.w * v.w;
    for (int o = 16; o > 0; o >>= 1) {
        s += __shfl_down_sync(0xffffffffu, s, o);
        q += __shfl_down_sync(0xffffffffu, q, o);
    }
    __shared__ float sr[8], qr[8];
    __shared__ float smean, sinv;
    if ((t & 31) == 0) { sr[t >> 5] = s; qr[t >> 5] = q; }
    __syncthreads();
    if (t == 0) {
        float S = 0.f, Q = 0.f;
        #pragma unroll
        for (int i = 0; i < 8; i++) { S += sr[i]; Q += qr[i]; }
        float mean = S * (1.0f / DMODEL);
        float var = Q * (1.0f / DMODEL) - mean * mean;
        smean = mean;
        sinv = rsqrtf(var + 1e-5f);
    }
    __syncthreads();
    float mean = smean, inv = sinv;
    float4 gg = ((const float4*)g)[t];
    float4 bb = ((const float4*)b)[t];
    float4 o;
    o.x = (v.x - mean) * inv * gg.x + bb.x;
    o.y = (v.y - mean) * inv * gg.y + bb.y;
    o.z = (v.z - mean) * inv * gg.z + bb.z;
    o.w = (v.w - mean) * inv * gg.w + bb.w;
    __half2* hp = (__half2*)(outh + (size_t)r * DMODEL + t * 4);
    hp[0] = __floats2half2_rn(o.x, o.y);
    hp[1] = __floats2half2_rn(o.z, o.w);
    if (outf)
        ((float4*)(outf + (size_t)r * DMODEL))[t] = o;
}

/* ================= boundary scalar ================= */
__global__ void k_bnd2(const float* __restrict__ w2,
                       const float* __restrict__ b2,
                       float* __restrict__ ss_out, int layer)
{
    int r = blockIdx.x, t = threadIdx.x;
    const float* hr = g_bndh + (size_t)r * HIDB;
    float s = 0.f;
    for (int k = t; k < HIDB; k += 128) s += hr[k] * w2[k];
    for (int o = 16; o > 0; o >>= 1) s += __shfl_down_sync(0xffffffffu, s, o);
    __shared__ float red[4];
    if ((t & 31) == 0) red[t >> 5] = s;
    __syncthreads();
    if (t == 0) {
        float v = red[0] + red[1] + red[2] + red[3] + b2[0];
        ss_out[(size_t)layer * NROWS + r] = 1.0f / (1.0f + expf(-v));
    }
}

/* ================= means over layers ================= */
__global__ void k_means(float* out)
{
    int idx = blockIdx.x * 256 + threadIdx.x;
    if (idx < NROWS * 4) {
        float s = 0.f;
        #pragma unroll
        for (int l = 0; l < NLAY; l++) s += out[OUT_GS + (size_t)l * NROWS * 4 + idx];
        out[OUT_GSM + idx] = s * (1.0f / NLAY);
    }
    int idx2 = idx - NROWS * 4;
    if (idx2 >= 0 && idx2 < NROWS) {
        float s = 0.f;
        #pragma unroll
        for (int l = 0; l < NLAY; l++) s += out[OUT_SS + (size_t)l * NROWS + idx2];
        out[OUT_SSM + idx2] = s * (1.0f / NLAY);
    }
}

/* ================= host ================= */
extern "C" void kernel_launch(void* const* d_in, const int* in_sizes, int n_in,
                              void* d_out, int out_size)
{
    const int*   ids      = (const int*)  d_in[0];
    const float* embed    = (const float*)d_in[1];
    const float* pos_enc  = (const float*)d_in[2];
    const float* rg_w     = (const float*)d_in[3];
    const float* rg_b     = (const float*)d_in[4];
    const float* qkv_w    = (const float*)d_in[5];
    const float* qkv_b    = (const float*)d_in[6];
    const float* out_w    = (const float*)d_in[7];
    const float* out_b    = (const float*)d_in[8];
    const float* ph_w     = (const float*)d_in[9];
    const float* ph_b     = (const float*)d_in[10];
    const float* resscale = (const float*)d_in[11];
    const float* ph_scale = (const float*)d_in[12];
    const float* ff1_w    = (const float*)d_in[13];
    const float* ff1_b    = (const float*)d_in[14];
    const float* ff2_w    = (const float*)d_in[15];
    const float* ff2_b    = (const float*)d_in[16];
    const float* n1_g     = (const float*)d_in[17];
    const float* n1_b     = (const float*)d_in[18];
    const float* n2_g     = (const float*)d_in[19];
    const float* n2_b     = (const float*)d_in[20];
    const float* bnd_w1   = (const float*)d_in[21];
    const float* bnd_b1   = (const float*)d_in[22];
    const float* bnd_w2   = (const float*)d_in[23];
    const float* bnd_b2   = (const float*)d_in[24];
    const float* fn_g     = (const float*)d_in[25];
    const float* fn_b     = (const float*)d_in[26];
    float* out = (float*)d_out;

    float *px, *pxm, *pbndh;
    __half *painH, *paoH, *pffhH, *pqkvH, *pwh, *pembH;
    cudaGetSymbolAddress((void**)&px,    g_x);
    cudaGetSymbolAddress((void**)&pxm,   g_xm);
    cudaGetSymbolAddress((void**)&pbndh, g_bndh);
    cudaGetSymbolAddress((void**)&painH, g_ainH);
    cudaGetSymbolAddress((void**)&paoH,  g_aoH);
    cudaGetSymbolAddress((void**)&pffhH, g_ffhH);
    cudaGetSymbolAddress((void**)&pqkvH, g_qkvH);
    cudaGetSymbolAddress((void**)&pwh,   g_wh);
    cudaGetSymbolAddress((void**)&pembH, g_embH);

    cudaFuncSetAttribute(k_hgemm, cudaFuncAttributeMaxDynamicSharedMemorySize, GEMM_SMEM);

    /* weight conversions, layer-batched over grid.z */
    dim3 tb(256);
    k_cvtT<<<dim3(3 * DMODEL / 64, DMODEL / 64, NLAY), tb>>>(qkv_w, pwh + W_QKV, DMODEL, 3 * DMODEL);
    k_cvtT<<<dim3(DMODEL / 64, DMODEL / 64, NLAY), tb>>>(out_w, pwh + W_OUT, DMODEL, DMODEL);
    k_cvtT<<<dim3(FFDIM / 64, DMODEL / 64, NLAY), tb>>>(ff1_w, pwh + W_FF1, DMODEL, FFDIM);
    k_cvtT<<<dim3(DMODEL / 64, FFDIM / 64, NLAY), tb>>>(ff2_w, pwh + W_FF2, FFDIM, DMODEL);
    k_cvtT<<<dim3(HIDB / 64, DMODEL / 64, 1), tb>>>(bnd_w1, pwh + W_BND, DMODEL, HIDB);
    k_cvtE<<<2048, 256>>>(embed);
    k_embed<<<NROWS, 256>>>(ids, embed, pos_enc);

    for (int i = 0; i < NLAY; i++) {
        k_gate_ln_ph<<<NROWS, 256>>>(rg_w, rg_b,
                                     n1_g + (size_t)i * DMODEL, n1_b + (size_t)i * DMODEL,
                                     ph_w, ph_b, ph_scale, i, out + OUT_GS);
        /* QKV projection -> fp16 qkv */
        {
            dim3 grid((3 * DMODEL) / 128, NROWS / 128);
            k_hgemm<<<grid, 256, GEMM_SMEM>>>(painH, pwh + W_QKV + (size_t)i * 3 * DMODEL * DMODEL,
                                              qkv_b + (size_t)i * 3 * DMODEL, (const float*)0,
                                              (float*)0, pqkvH, NROWS, 3 * DMODEL, DMODEL, 0);
        }
        {
            dim3 grid(LSEQ / 64, NHEAD, NB);
            k_attn<<<grid, 128>>>(resscale, i);
        }
        /* out projection + residual (xm) -> px fp32 */
        {
            dim3 grid(DMODEL / 128, NROWS / 128);
            k_hgemm<<<grid, 256, GEMM_SMEM>>>(paoH, pwh + W_OUT + (size_t)i * DMODEL * DMODEL,
                                              out_b + (size_t)i * DMODEL, pxm,
                                              px, (__half*)0, NROWS, DMODEL, DMODEL, 0);
        }
        k_ln<<<NROWS, 256>>>(px, n2_g + (size_t)i * DMODEL, n2_b + (size_t)i * DMODEL,
                             painH, (float*)0);
        /* FF1 + GELU -> fp16 hidden */
        {
            dim3 grid(FFDIM / 128, NROWS / 128);
            k_hgemm<<<grid, 256, GEMM_SMEM>>>(painH, pwh + W_FF1 + (size_t)i * DMODEL * FFDIM,
                                              ff1_b + (size_t)i * FFDIM, (const float*)0,
                                              (float*)0, pffhH, NROWS, FFDIM, DMODEL, 1);
        }
        /* FF2 + residual -> px fp32 AND fp16 copy for boundary */
        {
            dim3 grid(DMODEL / 128, NROWS / 128);
            k_hgemm<<<grid, 256, GEMM_SMEM>>>(pffhH, pwh + W_FF2 + (size_t)i * FFDIM * DMODEL,
                                              ff2_b + (size_t)i * DMODEL, px,
                                              px, painH, NROWS, DMODEL, FFDIM, 0);
        }
        /* boundary MLP layer 1 (tanh) -> fp32 hidden */
        {
            dim3 grid(HIDB / 128, NROWS / 128);
            k_hgemm<<<grid, 256, GEMM_SMEM>>>(painH, pwh + W_BND, bnd_b1, (const float*)0,
                                              pbndh, (__half*)0, NROWS, HIDB, DMODEL, 2);
        }
        k_bnd2<<<NROWS, 128>>>(bnd_w2, bnd_b2, out + OUT_SS, i);
    }

    /* final LN -> fp32 x output + fp16 copy for logits A */
    k_ln<<<NROWS, 256>>>(px, fn_g, fn_b, painH, out + OUT_X);

    {
        dim3 grid(VPAD / 128, NROWS / 128);
        k_hgemm<<<grid, 256, GEMM_SMEM>>>(painH, pembH, (const float*)0, (const float*)0,
                                          out + OUT_LOGITS, (__half*)0, NROWS, VOCAB, DMODEL, 0);
    }

    k_means<<<(NROWS * 4 + NROWS + 255) / 256, 256>>>(out);
}

// round 16
// speedup vs baseline: 1.0703x; 1.0246x over previous
#include <cuda_runtime.h>
#include <cuda_fp16.h>
#include <math.h>
#include <stdint.h>

#define NB      2
#define LSEQ    1024
#define DMODEL  1024
#define NHEAD   16
#define DHEAD   64
#define NLAY    6
#define VOCAB   30000
#define VPAD    30080
#define HIDB    512
#define FFDIM   4096
#define NROWS   2048   /* NB*LSEQ */

/* ---- output layout (flattened tuple, in reference return order) ---- */
static const size_t OUT_LOGITS = 0;
static const size_t OUT_X   = (size_t)NROWS * VOCAB;
static const size_t OUT_GSM = OUT_X   + (size_t)NROWS * DMODEL;
static const size_t OUT_SSM = OUT_GSM + (size_t)NROWS * 4;
static const size_t OUT_GS  = OUT_SSM + (size_t)NROWS;
static const size_t OUT_SS  = OUT_GS  + (size_t)NLAY * NROWS * 4;

/* ---- transposed fp16 weight scratch layout (elements) ---- */
#define W_QKV 0UL
#define W_OUT (W_QKV + (size_t)NLAY * DMODEL * 3 * DMODEL)
#define W_FF1 (W_OUT + (size_t)NLAY * DMODEL * DMODEL)
#define W_FF2 (W_FF1 + (size_t)NLAY * DMODEL * FFDIM)
#define W_BND (W_FF2 + (size_t)NLAY * FFDIM * DMODEL)
#define W_TOT (W_BND + (size_t)DMODEL * HIDB)

/* ---- scratch ---- */
__device__ float g_x  [NROWS * DMODEL];
__device__ float g_xm [NROWS * DMODEL];
__device__ float g_pv [NROWS * NHEAD];
__device__ float g_bndh[NROWS * HIDB];
__device__ __align__(16) __half g_ainH[NROWS * DMODEL];
__device__ __align__(16) __half g_aoH [NROWS * DMODEL];
__device__ __align__(16) __half g_ffhH[NROWS * FFDIM];
__device__ __align__(16) __half g_qkvH[NROWS * 3 * DMODEL];
__device__ __align__(16) __half g_wh  [W_TOT];
__device__ __align__(16) __half g_embH[(size_t)VPAD * DMODEL];

/* ================= low-level helpers (compute_103-safe) ================= */
__device__ __forceinline__ uint32_t smem_u32(const void* p) {
    uint32_t a;
    asm("{ .reg .u64 t; cvta.to.shared.u64 t, %1; cvt.u32.u64 %0, t; }" : "=r"(a) : "l"(p));
    return a;
}
__device__ __forceinline__ void cp16(void* s, const void* g) {
    asm volatile("cp.async.cg.shared.global [%0], [%1], 16;"
                 :: "r"(smem_u32(s)), "l"(g) : "memory");
}
#define CP_COMMIT() asm volatile("cp.async.commit_group;" ::: "memory")
#define CP_WAIT1()  asm volatile("cp.async.wait_group 1;" ::: "memory")
#define CP_WAIT0()  asm volatile("cp.async.wait_group 0;" ::: "memory")

#define LDSM4(r0, r1, r2, r3, addr) \
    asm volatile("ldmatrix.sync.aligned.m8n8.x4.shared.b16 {%0,%1,%2,%3}, [%4];" \
                 : "=r"(r0), "=r"(r1), "=r"(r2), "=r"(r3) : "r"(addr))

#define LDSM4T(r0, r1, r2, r3, addr) \
    asm volatile("ldmatrix.sync.aligned.m8n8.x4.trans.shared.b16 {%0,%1,%2,%3}, [%4];" \
                 : "=r"(r0), "=r"(r1), "=r"(r2), "=r"(r3) : "r"(addr))

__device__ __forceinline__ void mma_h(float* c, const uint32_t* a, const uint32_t* b) {
    asm volatile(
        "mma.sync.aligned.m16n8k16.row.col.f32.f16.f16.f32 "
        "{%0,%1,%2,%3}, {%4,%5,%6,%7}, {%8,%9}, {%0,%1,%2,%3};"
        : "+f"(c[0]), "+f"(c[1]), "+f"(c[2]), "+f"(c[3])
        : "r"(a[0]), "r"(a[1]), "r"(a[2]), "r"(a[3]), "r"(b[0]), "r"(b[1]));
}
/* fp16-accumulate variant (double rate); C = 2 regs of half2 */
__device__ __forceinline__ void mma_hh(uint32_t* c, const uint32_t* a, const uint32_t* b) {
    asm volatile(
        "mma.sync.aligned.m16n8k16.row.col.f16.f16.f16.f16 "
        "{%0,%1}, {%2,%3,%4,%5}, {%6,%7}, {%0,%1};"
        : "+r"(c[0]), "+r"(c[1])
        : "r"(a[0]), "r"(a[1]), "r"(a[2]), "r"(a[3]), "r"(b[0]), "r"(b[1]));
}
__device__ __forceinline__ uint32_t packh2(float a, float b) {
    __half2 h = __floats2half2_rn(a, b);
    return *(uint32_t*)&h;
}

/* ================= fp16 mma GEMM, templated M-tile =================
   MT=4: 128xN tile (verified); MT=2: 64xN tile (fills small grids).
   C[M,N](f32) / C2[M,N](fp16) = act(A[M,K] @ Bt[N,K]^T + bias) (+resid) */
template <int MT>
__global__ __launch_bounds__(256, 2)
void k_hgemm(const __half* __restrict__ A, const __half* __restrict__ Bm,
             const float* __restrict__ bias, const float* __restrict__ resid,
             float* __restrict__ C, __half* __restrict__ C2,
             int M, int N, int K, int act)
{
    extern __shared__ __half hs[];
    const int ASTG = MT * 2048;            /* halves per A stage */
    __half* As = hs;                       /* 2 stages */
    __half* Bs = hs + 2 * ASTG;

    const int tid  = threadIdx.x;
    const int wid  = tid >> 5;
    const int lane = tid & 31;
    const int m0 = blockIdx.y * (MT * 32);
    const int n0 = blockIdx.x * 128;
    const int wm = (wid & 1) * (MT * 16);
    const int wn = (wid >> 1) * 32;
    const int nch = K >> 6;

    const int st_row = tid >> 3;
    const uint32_t st_sw = (uint32_t)(((tid & 7) ^ (st_row & 7)) * 8);
    const __half* aglob = A + (size_t)(m0 + st_row) * K + (tid & 7) * 8;
    const __half* bglob = Bm + (size_t)(n0 + st_row) * K + (tid & 7) * 8;

#define HSTAGE(ch, s) do {                                                      \
    __half* as_ = As + (s) * ASTG;                                              \
    __half* bs_ = Bs + (s) * 8192;                                              \
    const __half* ap = aglob + (ch) * 64;                                       \
    const __half* bp = bglob + (ch) * 64;                                       \
    _Pragma("unroll")                                                           \
    for (int it = 0; it < MT; it++)                                             \
        cp16(as_ + (st_row + it * 32) * 64 + st_sw, ap + (size_t)(it * 32) * K);\
    _Pragma("unroll")                                                           \
    for (int it = 0; it < 4; it++)                                              \
        cp16(bs_ + (st_row + it * 32) * 64 + st_sw, bp + (size_t)(it * 32) * K);\
} while (0)

    const int lsw = lane & 7;
    const int rA  = (lane & 7) + (lane & 8);
    const int rB  = (lane & 7) + ((lane & 16) >> 1);
    const int cA  = (lane >> 4) & 1;
    const int cB  = (lane >> 3) & 1;

    float cf[MT][4][4];
    #pragma unroll
    for (int i = 0; i < MT; i++)
        #pragma unroll
        for (int j = 0; j < 4; j++)
            { cf[i][j][0] = 0.f; cf[i][j][1] = 0.f; cf[i][j][2] = 0.f; cf[i][j][3] = 0.f; }

    HSTAGE(0, 0);
    CP_COMMIT();

    for (int c = 0; c < nch; c++) {
        if (c + 1 < nch) { HSTAGE(c + 1, (c + 1) & 1); CP_COMMIT(); CP_WAIT1(); }
        else             { CP_WAIT0(); }
        __syncthreads();

        const uint32_t ab = smem_u32(As + (c & 1) * ASTG);
        const uint32_t bb = smem_u32(Bs + (c & 1) * 8192);

        #pragma unroll
        for (int kk = 0; kk < 4; kk++) {
            const uint32_t sA = (uint32_t)(((kk * 2 + cA) ^ lsw) * 16);
            const uint32_t sB = (uint32_t)(((kk * 2 + cB) ^ lsw) * 16);
            uint32_t af[MT][4], bf[2][4];
            #pragma unroll
            for (int mt = 0; mt < MT; mt++)
                LDSM4(af[mt][0], af[mt][1], af[mt][2], af[mt][3],
                      ab + (uint32_t)(wm + mt * 16 + rA) * 128u + sA);
            #pragma unroll
            for (int p = 0; p < 2; p++)
                LDSM4(bf[p][0], bf[p][1], bf[p][2], bf[p][3],
                      bb + (uint32_t)(wn + p * 16 + rB) * 128u + sB);
            #pragma unroll
            for (int mt = 0; mt < MT; mt++)
                #pragma unroll
                for (int nt = 0; nt < 4; nt++)
                    mma_h(cf[mt][nt], af[mt], &bf[nt >> 1][(nt & 1) * 2]);
        }
        __syncthreads();
    }
#undef HSTAGE

    #pragma unroll
    for (int mt = 0; mt < MT; mt++) {
        int row = m0 + wm + mt * 16 + (lane >> 2);
        #pragma unroll
        for (int nt = 0; nt < 4; nt++) {
            int col = n0 + wn + nt * 8 + (lane & 3) * 2;
            if (col < N) {
                #pragma unroll
                for (int hh = 0; hh < 2; hh++) {
                    int r = row + hh * 8;
                    float v0 = cf[mt][nt][hh * 2 + 0];
                    float v1 = cf[mt][nt][hh * 2 + 1];
                    if (bias) { v0 += bias[col]; v1 += bias[col + 1]; }
                    if (act == 1) {
                        v0 = 0.5f * v0 * (1.0f + erff(v0 * 0.70710678118654752f));
                        v1 = 0.5f * v1 * (1.0f + erff(v1 * 0.70710678118654752f));
                    } else if (act == 2) {
                        v0 = tanhf(v0); v1 = tanhf(v1);
                    }
                    if (resid) {
                        v0 += resid[(size_t)r * N + col];
                        v1 += resid[(size_t)r * N + col + 1];
                    }
                    if (C)  *(float2*)(C + (size_t)r * N + col) = make_float2(v0, v1);
                    if (C2) *(__half2*)(C2 + (size_t)r * N + col) = __floats2half2_rn(v0, v1);
                }
            }
        }
    }
}

/* == tensor-core fused attention; S fp16-acc; P register repack; O per-tile fp16-acc == */
__global__ __launch_bounds__(128)
void k_attn(const float* __restrict__ res_scale, int layer)
{
    const int b = blockIdx.z, h = blockIdx.y, q0 = blockIdx.x * 64;
    const int tid = threadIdx.x, wid = tid >> 5, lane = tid & 31;
    const float rs = res_scale[layer];

    __shared__ __half Qs[64 * 64];
    __shared__ __half Ks[2][64 * 64];
    __shared__ __half Vs[2][64 * 64];
    __shared__ float pvs[64];

    const int srow = tid >> 3;
    const int sc   = tid & 7;
    const uint32_t sdst = (uint32_t)((sc ^ (srow & 7)) * 8);

    {
        const __half* qg = g_qkvH + (size_t)(b * LSEQ + q0 + srow) * 3 * DMODEL + h * DHEAD + sc * 8;
        const __half* kg = g_qkvH + (size_t)(b * LSEQ + srow) * 3 * DMODEL + DMODEL + h * DHEAD + sc * 8;
        #pragma unroll
        for (int it = 0; it < 4; it++) {
            size_t off = (size_t)(it * 16) * 3 * DMODEL;
            cp16(Qs + (srow + it * 16) * 64 + sdst, qg + off);
            cp16(Ks[0] + (srow + it * 16) * 64 + sdst, kg + off);
            cp16(Vs[0] + (srow + it * 16) * 64 + sdst, kg + DMODEL + off);
        }
    }
    CP_COMMIT();

    const int lsw = lane & 7;
    const int rA  = (lane & 7) + (lane & 8);
    const int rB  = (lane & 7) + ((lane & 16) >> 1);
    const int cA  = (lane >> 4) & 1;
    const int cB  = (lane >> 3) & 1;
    const int wm  = wid * 16;
    const int g   = lane >> 2;
    const int tq  = lane & 3;

    const int gr1 = q0 + wm + g;
    const float pq1 = g_pv[(size_t)(b * LSEQ + gr1) * NHEAD + h];
    const float pq2 = g_pv[(size_t)(b * LSEQ + gr1 + 8) * NHEAD + h];

    float o[8][4];
    #pragma unroll
    for (int i = 0; i < 8; i++)
        { o[i][0] = 0.f; o[i][1] = 0.f; o[i][2] = 0.f; o[i][3] = 0.f; }
    float m1 = -1e30f, m2 = -1e30f, d1 = 0.f, d2 = 0.f;
    uint32_t qa[4][4];

    for (int j = 0; j < LSEQ / 64; j++) {
        const int buf = j & 1;
        if (j + 1 < LSEQ / 64) {
            const int nbuf = buf ^ 1;
            const int kv1 = (j + 1) * 64;
            const __half* kg = g_qkvH + (size_t)(b * LSEQ + kv1 + srow) * 3 * DMODEL
                               + DMODEL + h * DHEAD + sc * 8;
            #pragma unroll
            for (int it = 0; it < 4; it++) {
                size_t off = (size_t)(it * 16) * 3 * DMODEL;
                cp16(Ks[nbuf] + (srow + it * 16) * 64 + sdst, kg + off);
                cp16(Vs[nbuf] + (srow + it * 16) * 64 + sdst, kg + DMODEL + off);
            }
            CP_COMMIT();
            CP_WAIT1();
        } else {
            CP_WAIT0();
        }
        if (tid < 64)
            pvs[tid] = g_pv[(size_t)(b * LSEQ + j * 64 + tid) * NHEAD + h];
        __syncthreads();

        if (j == 0) {
            const uint32_t qb = smem_u32(Qs);
            #pragma unroll
            for (int ks = 0; ks < 4; ks++)
                LDSM4(qa[ks][0], qa[ks][1], qa[ks][2], qa[ks][3],
                      qb + (uint32_t)(wm + rA) * 128u + (uint32_t)(((ks * 2 + cA) ^ lsw) * 16));
        }

        /* S = Q K^T  (fp16 accumulate; fresh per tile) */
        uint32_t sh[8][2];
        #pragma unroll
        for (int i = 0; i < 8; i++) { sh[i][0] = 0u; sh[i][1] = 0u; }
        {
            const uint32_t kb = smem_u32(Ks[buf]);
            #pragma unroll
            for (int ks = 0; ks < 4; ks++) {
                const uint32_t sB = (uint32_t)(((ks * 2 + cB) ^ lsw) * 16);
                uint32_t bfm[4][4];
                #pragma unroll
                for (int nb2 = 0; nb2 < 4; nb2++)
                    LDSM4(bfm[nb2][0], bfm[nb2][1], bfm[nb2][2], bfm[nb2][3],
                          kb + (uint32_t)(nb2 * 16 + rB) * 128u + sB);
                #pragma unroll
                for (int nt = 0; nt < 8; nt++)
                    mma_hh(sh[nt], qa[ks], &bfm[nt >> 1][(nt & 1) * 2]);
            }
        }
        float s[8][4];
        #pragma unroll
        for (int nt = 0; nt < 8; nt++) {
            float2 v01 = __half22float2(*(__half2*)&sh[nt][0]);
            float2 v23 = __half22float2(*(__half2*)&sh[nt][1]);
            s[nt][0] = v01.x; s[nt][1] = v01.y;
            s[nt][2] = v23.x; s[nt][3] = v23.y;
        }

        /* exact phase penalty + online softmax */
        float tmax1 = -1e30f, tmax2 = -1e30f;
        #pragma unroll
        for (int nt = 0; nt < 8; nt++) {
            float k0 = pvs[nt * 8 + tq * 2];
            float k1 = pvs[nt * 8 + tq * 2 + 1];
            float u;
            u = pq1 - k0; s[nt][0] = s[nt][0] * 0.125f - rs * u * u;
            u = pq1 - k1; s[nt][1] = s[nt][1] * 0.125f - rs * u * u;
            u = pq2 - k0; s[nt][2] = s[nt][2] * 0.125f - rs * u * u;
            u = pq2 - k1; s[nt][3] = s[nt][3] * 0.125f - rs * u * u;
            tmax1 = fmaxf(tmax1, fmaxf(s[nt][0], s[nt][1]));
            tmax2 = fmaxf(tmax2, fmaxf(s[nt][2], s[nt][3]));
        }
        tmax1 = fmaxf(tmax1, __shfl_xor_sync(0xffffffffu, tmax1, 1));
        tmax1 = fmaxf(tmax1, __shfl_xor_sync(0xffffffffu, tmax1, 2));
        tmax2 = fmaxf(tmax2, __shfl_xor_sync(0xffffffffu, tmax2, 1));
        tmax2 = fmaxf(tmax2, __shfl_xor_sync(0xffffffffu, tmax2, 2));
        float mn1 = fmaxf(m1, tmax1), mn2 = fmaxf(m2, tmax2);
        float c1 = __expf(m1 - mn1), c2 = __expf(m2 - mn2);
        m1 = mn1; m2 = mn2;
        d1 *= c1; d2 *= c2;
        #pragma unroll
        for (int nt = 0; nt < 8; nt++) {
            o[nt][0] *= c1; o[nt][1] *= c1;
            o[nt][2] *= c2; o[nt][3] *= c2;
        }
        uint32_t pa[4][4];
        #pragma unroll
        for (int nt = 0; nt < 8; nt++) {
            float p0 = __expf(s[nt][0] - m1), p1 = __expf(s[nt][1] - m1);
            float p2 = __expf(s[nt][2] - m2), p3 = __expf(s[nt][3] - m2);
            d1 += p0 + p1; d2 += p2 + p3;
            pa[nt >> 1][(nt & 1) * 2 + 0] = packh2(p0, p1);
            pa[nt >> 1][(nt & 1) * 2 + 1] = packh2(p2, p3);
        }

        /* O-tile = P @ V in fp16 accum, promoted once per tile into fp32 o */
        uint32_t oh[8][2];
        #pragma unroll
        for (int i = 0; i < 8; i++) { oh[i][0] = 0u; oh[i][1] = 0u; }
        {
            const uint32_t vb = smem_u32(Vs[buf]);
            #pragma unroll
            for (int ks = 0; ks < 4; ks++) {
                uint32_t vf[4][4];
                #pragma unroll
                for (int nb2 = 0; nb2 < 4; nb2++)
                    LDSM4T(vf[nb2][0], vf[nb2][1], vf[nb2][2], vf[nb2][3],
                           vb + (uint32_t)(ks * 16 + rA) * 128u
                              + (uint32_t)(((nb2 * 2 + cA) ^ lsw) * 16));
                #pragma unroll
                for (int nt = 0; nt < 8; nt++)
                    mma_hh(oh[nt], pa[ks], &vf[nt >> 1][(nt & 1) * 2]);
            }
        }
        #pragma unroll
        for (int nt = 0; nt < 8; nt++) {
            float2 v01 = __half22float2(*(__half2*)&oh[nt][0]);
            float2 v23 = __half22float2(*(__half2*)&oh[nt][1]);
            o[nt][0] += v01.x; o[nt][1] += v01.y;
            o[nt][2] += v23.x; o[nt][3] += v23.y;
        }
        __syncthreads();
    }

    d1 += __shfl_xor_sync(0xffffffffu, d1, 1);
    d1 += __shfl_xor_sync(0xffffffffu, d1, 2);
    d2 += __shfl_xor_sync(0xffffffffu, d2, 1);
    d2 += __shfl_xor_sync(0xffffffffu, d2, 2);
    float i1 = 1.0f / d1, i2 = 1.0f / d2;
    __half* o1 = g_aoH + (size_t)(b * LSEQ + gr1) * DMODEL + h * DHEAD + tq * 2;
    __half* o2 = o1 + (size_t)8 * DMODEL;
    #pragma unroll
    for (int nt = 0; nt < 8; nt++) {
        *(__half2*)(o1 + nt * 8) = __floats2half2_rn(o[nt][0] * i1, o[nt][1] * i1);
        *(__half2*)(o2 + nt * 8) = __floats2half2_rn(o[nt][2] * i2, o[nt][3] * i2);
    }
}

/* ===== weight transpose + fp16 convert, 64x64 tiles, layer-batched (z) ===== */
__global__ void k_cvtT(const float* __restrict__ src, __half* __restrict__ dst,
                       int K, int N)
{
    __shared__ float t[64][65];
    size_t seg = (size_t)blockIdx.z * K * N;
    const float* s0 = src + seg;
    __half* d0 = dst + seg;
    int n0 = blockIdx.x * 64, k0 = blockIdx.y * 64;
    int tid = threadIdx.x;               /* 256 */
    {
        int kr = tid >> 2, c4 = tid & 3;
        const float* sp = s0 + (size_t)(k0 + kr) * N + n0;
        #pragma unroll
        for (int j = 0; j < 4; j++) {
            int col = (c4 + j * 4) * 4;
            float4 v = *(const float4*)(sp + col);
            t[kr][col + 0] = v.x; t[kr][col + 1] = v.y;
            t[kr][col + 2] = v.z; t[kr][col + 3] = v.w;
        }
    }
    __syncthreads();
    {
        int n = tid >> 2, kc = (tid & 3) * 16;
        __half2 h[8];
        #pragma unroll
        for (int j = 0; j < 8; j++)
            h[j] = __floats2half2_rn(t[kc + 2 * j][n], t[kc + 2 * j + 1][n]);
        __half* dp = d0 + (size_t)(n0 + n) * K + k0 + kc;
        *(uint4*)(dp + 0) = *(uint4*)&h[0];
        *(uint4*)(dp + 8) = *(uint4*)&h[4];
    }
}

/* ================= embed -> fp16 [VPAD][D] with zero pad ================= */
__global__ void k_cvtE(const float* __restrict__ src)
{
    size_t stride = (size_t)gridDim.x * blockDim.x;
    size_t tot8 = (size_t)VPAD * DMODEL / 8;
    for (size_t i = (size_t)blockIdx.x * blockDim.x + threadIdx.x; i < tot8; i += stride) {
        size_t e = i * 8;
        size_t row = e >> 10;
        __half2 h[4];
        if (row < VOCAB) {
            float4 v0 = *(const float4*)(src + e);
            float4 v1 = *(const float4*)(src + e + 4);
            h[0] = __floats2half2_rn(v0.x, v0.y);
            h[1] = __floats2half2_rn(v0.z, v0.w);
            h[2] = __floats2half2_rn(v1.x, v1.y);
            h[3] = __floats2half2_rn(v1.z, v1.w);
        } else {
            h[0] = h[1] = h[2] = h[3] = __float2half2_rn(0.f);
        }
        *(uint4*)(g_embH + e) = *(uint4*)h;
    }
}

/* ================= embedding + positional ================= */
__global__ void k_embed(const int* __restrict__ ids,
                        const float* __restrict__ emb,
                        const float* __restrict__ pos)
{
    int r = blockIdx.x;
    int l = r % LSEQ;
    int id = ids[r];
    const float4* e4 = (const float4*)(emb + (size_t)id * DMODEL);
    const float4* p4 = (const float4*)(pos + (size_t)l * DMODEL);
    float4* x4 = (float4*)(g_x + (size_t)r * DMODEL);
    for (int k = threadIdx.x; k < DMODEL / 4; k += blockDim.x) {
        float4 e = e4[k], p = p4[k];
        float4 o;
        o.x = e.x * 32.0f + p.x;
        o.y = e.y * 32.0f + p.y;
        o.z = e.z * 32.0f + p.z;
        o.w = e.w * 32.0f + p.w;
        x4[k] = o;
    }
}

/* ========== fused: R-grammar gate + xm + pre-norm1 + phase vector ========== */
__global__ void k_gate_ln_ph(const float* __restrict__ rg_w, const float* __restrict__ rg_b,
                             const float* __restrict__ n1g, const float* __restrict__ n1b,
                             const float* __restrict__ ph_w, const float* __restrict__ ph_b,
                             const float* __restrict__ ph_scale, int layer,
                             float* __restrict__ gs_out)
{
    int r = blockIdx.x, t = threadIdx.x;   /* 256 threads, 4 elems each */
    int w = t >> 5, lane = t & 31;
    __shared__ float gred[8][4];
    __shared__ float sred[8], qred[8];
    __shared__ float pred_[8][16];
    __shared__ float s_ms, s_mean, s_inv;

    float4 xv = ((const float4*)(g_x + (size_t)r * DMODEL))[t];

    const float4* w4 = (const float4*)(rg_w + (size_t)layer * DMODEL * 4);
    float4 wa = w4[t * 4 + 0], wb = w4[t * 4 + 1], wc = w4[t * 4 + 2], wd = w4[t * 4 + 3];
    float s0 = xv.x * wa.x + xv.y * wb.x + xv.z * wc.x + xv.w * wd.x;
    float s1 = xv.x * wa.y + xv.y * wb.y + xv.z * wc.y + xv.w * wd.y;
    float s2 = xv.x * wa.z + xv.y * wb.z + xv.z * wc.z + xv.w * wd.z;
    float s3 = xv.x * wa.w + xv.y * wb.w + xv.z * wc.w + xv.w * wd.w;
    #pragma unroll
    for (int o = 16; o > 0; o >>= 1) {
        s0 += __shfl_xor_sync(0xffffffffu, s0, o);
        s1 += __shfl_xor_sync(0xffffffffu, s1, o);
        s2 += __shfl_xor_sync(0xffffffffu, s2, o);
        s3 += __shfl_xor_sync(0xffffffffu, s3, o);
    }
    if (lane == 0) { gred[w][0] = s0; gred[w][1] = s1; gred[w][2] = s2; gred[w][3] = s3; }
    __syncthreads();
    if (t == 0) {
        float sum4 = 0.f;
        float* gsp = gs_out + ((size_t)layer * NROWS + r) * 4;
        #pragma unroll
        for (int n = 0; n < 4; n++) {
            float a = rg_b[layer * 4 + n];
            #pragma unroll
            for (int ww = 0; ww < 8; ww++) a += gred[ww][n];
            float sg = 1.0f / (1.0f + expf(-a));
            gsp[n] = sg;
            sum4 += sg;
        }
        s_ms = 1.0f + 0.1f * (sum4 * 0.25f);
    }
    __syncthreads();
    float ms = s_ms;
    float4 xm;
    xm.x = xv.x * ms; xm.y = xv.y * ms; xm.z = xv.z * ms; xm.w = xv.w * ms;
    ((float4*)(g_xm + (size_t)r * DMODEL))[t] = xm;

    float s = xm.x + xm.y + xm.z + xm.w;
    float q = xm.x * xm.x + xm.y * xm.y + xm.z * xm.z + xm.w * xm.w;
    #pragma unroll
    for (int o = 16; o > 0; o >>= 1) {
        s += __shfl_xor_sync(0xffffffffu, s, o);
        q += __shfl_xor_sync(0xffffffffu, q, o);
    }
    if (lane == 0) { sred[w] = s; qred[w] = q; }
    __syncthreads();
    if (t == 0) {
        float S = 0.f, Q = 0.f;
        #pragma unroll
        for (int i = 0; i < 8; i++) { S += sred[i]; Q += qred[i]; }
        float mean = S * (1.0f / DMODEL);
        float var = Q * (1.0f / DMODEL) - mean * mean;
        s_mean = mean;
        s_inv = rsqrtf(var + 1e-5f);
    }
    __syncthreads();
    float mean = s_mean, inv = s_inv;
    float4 gg = ((const float4*)n1g)[t];
    float4 bb = ((const float4*)n1b)[t];
    float a0 = (xm.x - mean) * inv * gg.x + bb.x;
    float a1 = (xm.y - mean) * inv * gg.y + bb.y;
    float a2 = (xm.z - mean) * inv * gg.z + bb.z;
    float a3 = (xm.w - mean) * inv * gg.w + bb.w;
    __half2* hp = (__half2*)(g_ainH + (size_t)r * DMODEL + t * 4);
    hp[0] = __floats2half2_rn(a0, a1);
    hp[1] = __floats2half2_rn(a2, a3);

    const float4* p4 = (const float4*)(ph_w + (size_t)layer * DMODEL * NHEAD);
    float acc[16];
    #pragma unroll
    for (int n = 0; n < 16; n++) acc[n] = 0.f;
    float av[4] = {a0, a1, a2, a3};
    #pragma unroll
    for (int e = 0; e < 4; e++) {
        float a = av[e];
        const float4* pr = p4 + (size_t)(t * 4 + e) * 4;
        float4 p0 = pr[0], p1 = pr[1], p2 = pr[2], p3 = pr[3];
        acc[0]  += a * p0.x; acc[1]  += a * p0.y; acc[2]  += a * p0.z; acc[3]  += a * p0.w;
        acc[4]  += a * p1.x; acc[5]  += a * p1.y; acc[6]  += a * p1.z; acc[7]  += a * p1.w;
        acc[8]  += a * p2.x; acc[9]  += a * p2.y; acc[10] += a * p2.z; acc[11] += a * p2.w;
        acc[12] += a * p3.x; acc[13] += a * p3.y; acc[14] += a * p3.z; acc[15] += a * p3.w;
    }
    #pragma unroll
    for (int n = 0; n < 16; n++) {
        #pragma unroll
        for (int o = 16; o > 0; o >>= 1)
            acc[n] += __shfl_xor_sync(0xffffffffu, acc[n], o);
    }
    if (lane == 0) {
        #pragma unroll
        for (int n = 0; n < 16; n++) pred_[w][n] = acc[n];
    }
    __syncthreads();
    if (t < 16) {
        float v = ph_b[layer * NHEAD + t];
        #pragma unroll
        for (int ww = 0; ww < 8; ww++) v += pred_[ww][t];
        g_pv[(size_t)r * NHEAD + t] = tanhf(ph_scale[layer] * v);
    }
}

/* ================= LayerNorm: fp16 main output + optional fp32 copy ======= */
__global__ void k_ln(const float* __restrict__ in,
                     const float* __restrict__ g,
                     const float* __restrict__ b,
                     __half* __restrict__ outh,
                     float* __restrict__ outf)
{
    int r = blockIdx.x, t = threadIdx.x;
    const float4* i4 = (const float4*)(in + (size_t)r * DMODEL);
    float4 v = i4[t];
    float s = v.x + v.y + v.z + v.w;
    float q = v.x * v.x + v.y * v.y + v.z * v.z + v.w * v.w;
    for (int o = 16; o > 0; o >>= 1) {
        s += __shfl_down_sync(0xffffffffu, s, o);
        q += __shfl_down_sync(0xffffffffu, q, o);
    }
    __shared__ float sr[8], qr[8];
    __shared__ float smean, sinv;
    if ((t & 31) == 0) { sr[t >> 5] = s; qr[t >> 5] = q; }
    __syncthreads();
    if (t == 0) {
        float S = 0.f, Q = 0.f;
        #pragma unroll
        for (int i = 0; i < 8; i++) { S += sr[i]; Q += qr[i]; }
        float mean = S * (1.0f / DMODEL);
        float var = Q * (1.0f / DMODEL) - mean * mean;
        smean = mean;
        sinv = rsqrtf(var + 1e-5f);
    }
    __syncthreads();
    float mean = smean, inv = sinv;
    float4 gg = ((const float4*)g)[t];
    float4 bb = ((const float4*)b)[t];
    float4 o;
    o.x = (v.x - mean) * inv * gg.x + bb.x;
    o.y = (v.y - mean) * inv * gg.y + bb.y;
    o.z = (v.z - mean) * inv * gg.z + bb.z;
    o.w = (v.w - mean) * inv * gg.w + bb.w;
    __half2* hp = (__half2*)(outh + (size_t)r * DMODEL + t * 4);
    hp[0] = __floats2half2_rn(o.x, o.y);
    hp[1] = __floats2half2_rn(o.z, o.w);
    if (outf)
        ((float4*)(outf + (size_t)r * DMODEL))[t] = o;
}

/* ================= boundary scalar ================= */
__global__ void k_bnd2(const float* __restrict__ w2,
                       const float* __restrict__ b2,
                       float* __restrict__ ss_out, int layer)
{
    int r = blockIdx.x, t = threadIdx.x;
    const float* hr = g_bndh + (size_t)r * HIDB;
    float s = 0.f;
    for (int k = t; k < HIDB; k += 128) s += hr[k] * w2[k];
    for (int o = 16; o > 0; o >>= 1) s += __shfl_down_sync(0xffffffffu, s, o);
    __shared__ float red[4];
    if ((t & 31) == 0) red[t >> 5] = s;
    __syncthreads();
    if (t == 0) {
        float v = red[0] + red[1] + red[2] + red[3] + b2[0];
        ss_out[(size_t)layer * NROWS + r] = 1.0f / (1.0f + expf(-v));
    }
}

/* ================= means over layers ================= */
__global__ void k_means(float* out)
{
    int idx = blockIdx.x * 256 + threadIdx.x;
    if (idx < NROWS * 4) {
        float s = 0.f;
        #pragma unroll
        for (int l = 0; l < NLAY; l++) s += out[OUT_GS + (size_t)l * NROWS * 4 + idx];
        out[OUT_GSM + idx] = s * (1.0f / NLAY);
    }
    int idx2 = idx - NROWS * 4;
    if (idx2 >= 0 && idx2 < NROWS) {
        float s = 0.f;
        #pragma unroll
        for (int l = 0; l < NLAY; l++) s += out[OUT_SS + (size_t)l * NROWS + idx2];
        out[OUT_SSM + idx2] = s * (1.0f / NLAY);
    }
}

/* ================= host ================= */
#define GEMM_SMEM4 65536
#define GEMM_SMEM2 49152

extern "C" void kernel_launch(void* const* d_in, const int* in_sizes, int n_in,
                              void* d_out, int out_size)
{
    const int*   ids      = (const int*)  d_in[0];
    const float* embed    = (const float*)d_in[1];
    const float* pos_enc  = (const float*)d_in[2];
    const float* rg_w     = (const float*)d_in[3];
    const float* rg_b     = (const float*)d_in[4];
    const float* qkv_w    = (const float*)d_in[5];
    const float* qkv_b    = (const float*)d_in[6];
    const float* out_w    = (const float*)d_in[7];
    const float* out_b    = (const float*)d_in[8];
    const float* ph_w     = (const float*)d_in[9];
    const float* ph_b     = (const float*)d_in[10];
    const float* resscale = (const float*)d_in[11];
    const float* ph_scale = (const float*)d_in[12];
    const float* ff1_w    = (const float*)d_in[13];
    const float* ff1_b    = (const float*)d_in[14];
    const float* ff2_w    = (const float*)d_in[15];
    const float* ff2_b    = (const float*)d_in[16];
    const float* n1_g     = (const float*)d_in[17];
    const float* n1_b     = (const float*)d_in[18];
    const float* n2_g     = (const float*)d_in[19];
    const float* n2_b     = (const float*)d_in[20];
    const float* bnd_w1   = (const float*)d_in[21];
    const float* bnd_b1   = (const float*)d_in[22];
    const float* bnd_w2   = (const float*)d_in[23];
    const float* bnd_b2   = (const float*)d_in[24];
    const float* fn_g     = (const float*)d_in[25];
    const float* fn_b     = (const float*)d_in[26];
    float* out = (float*)d_out;

    float *px, *pxm, *pbndh;
    __half *painH, *paoH, *pffhH, *pqkvH, *pwh, *pembH;
    cudaGetSymbolAddress((void**)&px,    g_x);
    cudaGetSymbolAddress((void**)&pxm,   g_xm);
    cudaGetSymbolAddress((void**)&pbndh, g_bndh);
    cudaGetSymbolAddress((void**)&painH, g_ainH);
    cudaGetSymbolAddress((void**)&paoH,  g_aoH);
    cudaGetSymbolAddress((void**)&pffhH, g_ffhH);
    cudaGetSymbolAddress((void**)&pqkvH, g_qkvH);
    cudaGetSymbolAddress((void**)&pwh,   g_wh);
    cudaGetSymbolAddress((void**)&pembH, g_embH);

    cudaFuncSetAttribute(k_hgemm<4>, cudaFuncAttributeMaxDynamicSharedMemorySize, GEMM_SMEM4);
    cudaFuncSetAttribute(k_hgemm<2>, cudaFuncAttributeMaxDynamicSharedMemorySize, GEMM_SMEM2);

    /* weight conversions, layer-batched over grid.z */
    dim3 tb(256);
    k_cvtT<<<dim3(3 * DMODEL / 64, DMODEL / 64, NLAY), tb>>>(qkv_w, pwh + W_QKV, DMODEL, 3 * DMODEL);
    k_cvtT<<<dim3(DMODEL / 64, DMODEL / 64, NLAY), tb>>>(out_w, pwh + W_OUT, DMODEL, DMODEL);
    k_cvtT<<<dim3(FFDIM / 64, DMODEL / 64, NLAY), tb>>>(ff1_w, pwh + W_FF1, DMODEL, FFDIM);
    k_cvtT<<<dim3(DMODEL / 64, FFDIM / 64, NLAY), tb>>>(ff2_w, pwh + W_FF2, FFDIM, DMODEL);
    k_cvtT<<<dim3(HIDB / 64, DMODEL / 64, 1), tb>>>(bnd_w1, pwh + W_BND, DMODEL, HIDB);
    k_cvtE<<<2048, 256>>>(embed);
    k_embed<<<NROWS, 256>>>(ids, embed, pos_enc);

    for (int i = 0; i < NLAY; i++) {
        k_gate_ln_ph<<<NROWS, 256>>>(rg_w, rg_b,
                                     n1_g + (size_t)i * DMODEL, n1_b + (size_t)i * DMODEL,
                                     ph_w, ph_b, ph_scale, i, out + OUT_GS);
        /* QKV projection -> fp16 qkv (M-tile 64: 768 CTAs) */
        {
            dim3 grid((3 * DMODEL) / 128, NROWS / 64);
            k_hgemm<2><<<grid, 256, GEMM_SMEM2>>>(painH, pwh + W_QKV + (size_t)i * 3 * DMODEL * DMODEL,
                                                  qkv_b + (size_t)i * 3 * DMODEL, (const float*)0,
                                                  (float*)0, pqkvH, NROWS, 3 * DMODEL, DMODEL, 0);
        }
        {
            dim3 grid(LSEQ / 64, NHEAD, NB);
            k_attn<<<grid, 128>>>(resscale, i);
        }
        /* out projection + residual (xm) -> px fp32 (M-tile 64: 256 CTAs) */
        {
            dim3 grid(DMODEL / 128, NROWS / 64);
            k_hgemm<2><<<grid, 256, GEMM_SMEM2>>>(paoH, pwh + W_OUT + (size_t)i * DMODEL * DMODEL,
                                                  out_b + (size_t)i * DMODEL, pxm,
                                                  px, (__half*)0, NROWS, DMODEL, DMODEL, 0);
        }
        k_ln<<<NROWS, 256>>>(px, n2_g + (size_t)i * DMODEL, n2_b + (size_t)i * DMODEL,
                             painH, (float*)0);
        /* FF1 + GELU -> fp16 hidden (M-tile 128: 512 CTAs) */
        {
            dim3 grid(FFDIM / 128, NROWS / 128);
            k_hgemm<4><<<grid, 256, GEMM_SMEM4>>>(painH, pwh + W_FF1 + (size_t)i * DMODEL * FFDIM,
                                                  ff1_b + (size_t)i * FFDIM, (const float*)0,
                                                  (float*)0, pffhH, NROWS, FFDIM, DMODEL, 1);
        }
        /* FF2 + residual -> px fp32 AND fp16 copy for boundary (M-tile 64: 256 CTAs) */
        {
            dim3 grid(DMODEL / 128, NROWS / 64);
            k_hgemm<2><<<grid, 256, GEMM_SMEM2>>>(pffhH, pwh + W_FF2 + (size_t)i * FFDIM * DMODEL,
                                                  ff2_b + (size_t)i * DMODEL, px,
                                                  px, painH, NROWS, DMODEL, FFDIM, 0);
        }
        /* boundary MLP layer 1 (tanh) -> fp32 hidden (M-tile 64: 128 CTAs) */
        {
            dim3 grid(HIDB / 128, NROWS / 64);
            k_hgemm<2><<<grid, 256, GEMM_SMEM2>>>(painH, pwh + W_BND, bnd_b1, (const float*)0,
                                                  pbndh, (__half*)0, NROWS, HIDB, DMODEL, 2);
        }
        k_bnd2<<<NROWS, 128>>>(bnd_w2, bnd_b2, out + OUT_SS, i);
    }

    /* final LN -> fp32 x output + fp16 copy for logits A */
    k_ln<<<NROWS, 256>>>(px, fn_g, fn_b, painH, out + OUT_X);

    {
        dim3 grid(VPAD / 128, NROWS / 128);
        k_hgemm<4><<<grid, 256, GEMM_SMEM4>>>(painH, pembH, (const float*)0, (const float*)0,
                                              out + OUT_LOGITS, (__half*)0, NROWS, VOCAB, DMODEL, 0);
    }

    k_means<<<(NROWS * 4 + NROWS + 255) / 256, 256>>>(out);
}